// round 10
// baseline (speedup 1.0000x reference)
#include <cuda_runtime.h>
#include <cuda_bf16.h>
#include <cstdint>
#include <cstddef>

#define BATCH 16384
#define NND   7
#define FEATD 512
#define HID   256
#define CTXD  256
#define MROWS (BATCH * NND)        // 114688
#define GB    8                    // batches per attn1 block
#define GB2   4                    // batches per attn2 block
#define CS    2052                 // padded combined stride (floats)

// ---- HMMA staging (rows 0..127 of tile), row stride 80B, conflict-free LDSM
#define STR     80
#define AH_OFF  0
#define AL_OFF  10240
#define BH_OFF  20480
#define BL_OFF  30720
#define STAGE   40960              // per buffer
// ---- SIMT ext staging (rows 128..223), cp.async double buffered
#define AE_OFF  (2 * STAGE)        // 81920: A-ext [96][36] floats (stride 144B)
#define AE_SZ   (96 * 144)         // 13824
#define BE_OFF  (AE_OFF + 2 * AE_SZ)  // 109568: B-ext [32][140] floats (560B)
#define BE_SZ   (32 * 560)         // 17920
#define G_SMEM  (BE_OFF + 2 * BE_SZ)  // 145408
#define TILE_M  224

// ---------------- scratch (no allocs allowed; __device__ globals) ----------
__device__ float g_h1[(size_t)MROWS * HID];
__device__ float g_x2[(size_t)MROWS * HID];
__device__ float g_h2[(size_t)MROWS * HID];
__device__ __nv_bfloat16 g_w1hi[HID * FEATD], g_w1lo[HID * FEATD];
__device__ __nv_bfloat16 g_w2hi[HID * HID],  g_w2lo[HID * HID];
__device__ float g_w1t[FEATD * HID];   // W1^T  [K=512][256]
__device__ float g_w2t[HID * HID];     // W2^T  [K=256][256]

// ---------------- helpers --------------------------------------------------
__device__ __forceinline__ uint32_t smem_u32(const void* p) {
    uint32_t a;
    asm("{ .reg .u64 t; cvta.to.shared.u64 t, %1; cvt.u32.u64 %0, t; }" : "=r"(a) : "l"(p));
    return a;
}
__device__ __forceinline__ void ldsm4(uint32_t* r, uint32_t addr) {
    asm volatile("ldmatrix.sync.aligned.m8n8.x4.shared.b16 {%0,%1,%2,%3}, [%4];"
                 : "=r"(r[0]), "=r"(r[1]), "=r"(r[2]), "=r"(r[3]) : "r"(addr));
}
__device__ __forceinline__ void mma_bf16(float* c, const uint32_t* a, const uint32_t* b) {
    asm volatile(
        "mma.sync.aligned.m16n8k16.row.col.f32.bf16.bf16.f32 "
        "{%0,%1,%2,%3}, {%4,%5,%6,%7}, {%8,%9}, {%0,%1,%2,%3};"
        : "+f"(c[0]), "+f"(c[1]), "+f"(c[2]), "+f"(c[3])
        : "r"(a[0]), "r"(a[1]), "r"(a[2]), "r"(a[3]), "r"(b[0]), "r"(b[1]));
}
__device__ __forceinline__ void cvt_hilo(float4 v, uint32_t& h0, uint32_t& h1,
                                         uint32_t& l0, uint32_t& l1) {
    __nv_bfloat162 ha = __float22bfloat162_rn(make_float2(v.x, v.y));
    __nv_bfloat162 hb = __float22bfloat162_rn(make_float2(v.z, v.w));
    float2 fa = __bfloat1622float2(ha);
    float2 fb = __bfloat1622float2(hb);
    __nv_bfloat162 la = __float22bfloat162_rn(make_float2(v.x - fa.x, v.y - fa.y));
    __nv_bfloat162 lb = __float22bfloat162_rn(make_float2(v.z - fb.x, v.w - fb.y));
    h0 = *(uint32_t*)&ha; h1 = *(uint32_t*)&hb;
    l0 = *(uint32_t*)&la; l1 = *(uint32_t*)&lb;
}
__device__ __forceinline__ void cpasync16(uint32_t saddr, const void* g) {
    asm volatile("cp.async.cg.shared.global [%0], [%1], 16;" :: "r"(saddr), "l"(g) : "memory");
}
__device__ __forceinline__ void cpasync_commit() {
    asm volatile("cp.async.commit_group;" ::: "memory");
}
__device__ __forceinline__ void cpasync_wait0() {
    asm volatile("cp.async.wait_group 0;" ::: "memory");
}

// ---------------------------------------------------------------------------
// Weight pre-split: fp32 -> bf16 hi + bf16 lo(residual)
// ---------------------------------------------------------------------------
__global__ void convw_kernel(const float* __restrict__ W, __nv_bfloat16* __restrict__ hi,
                             __nv_bfloat16* __restrict__ lo, int n) {
    int i = blockIdx.x * 256 + threadIdx.x;
    if (i < n) {
        float x = W[i];
        __nv_bfloat16 h = __float2bfloat16(x);
        hi[i] = h;
        lo[i] = __float2bfloat16(x - __bfloat162float(h));
    }
}
// Weight transpose: Wt[k][n] = W[n][k]   (N = 256 fixed)
__global__ void transw_kernel(const float* __restrict__ W, float* __restrict__ Wt, int K) {
    int i = blockIdx.x * 256 + threadIdx.x;
    if (i < 256 * K) {
        int n = i / K, k = i - n * K;
        Wt[k * 256 + n] = W[i];
    }
}

// ---------------------------------------------------------------------------
// Hybrid GEMM: C[m,n] = sum_k A[m,k]*W[n,k].  Tile 224x128, 384 threads.
//   warps 0-7  : rows m0..m0+127 via 3-term bf16 HMMA (tensor pipe)
//   warps 8-11 : rows m0+128..m0+223 via exact fp32 SIMT (fma pipe)
// HMMA tiles: reg-prefetch double buffer. SIMT tiles: cp.async double buffer.
// ---------------------------------------------------------------------------
__global__ void __launch_bounds__(384, 1)
gemm_hybrid(const float* __restrict__ A, const __nv_bfloat16* __restrict__ Bhi,
            const __nv_bfloat16* __restrict__ Blo, const float* __restrict__ Wt,
            float* __restrict__ C, int K) {
    extern __shared__ char smem[];
    const uint32_t sb = smem_u32(smem);
    const int tid  = threadIdx.x;
    const int lane = tid & 31;
    const int wid  = tid >> 5;
    const int m0   = blockIdx.x * TILE_M;
    const int n0   = blockIdx.y * 128;
    const int nk   = K >> 5;       // BK = 32

    // ======== HMMA-path per-thread state (tid < 256) ========
    const int wm = wid & 3, wn = (wid >> 2) & 1;
    const int ra = (tid & 255) >> 1;
    const int ca = (tid & 1) * 16;
    const float* Ag = A + (size_t)(m0 + ra) * K + ca;
    const int rb = (tid & 255) >> 1;
    const int cb = (tid & 1) * 2;
    const char* Bhg = (const char*)Bhi + (size_t)(n0 + rb) * K * 2;
    const char* Blg = (const char*)Blo + (size_t)(n0 + rb) * K * 2;
    const uint32_t a_off = AH_OFF + (uint32_t)(wm * 32 + (lane & 15)) * STR + ((lane >> 4) << 4);
    const uint32_t b_off = BH_OFF + (uint32_t)(wn * 64 + (lane & 7) + ((lane >> 4) << 3)) * STR
                         + ((lane & 8) << 1);
    float acc[2][8][4];
    float4 av[4];
    uint4  bhv[2], blv[2];

    // ======== SIMT-path per-thread state (tid >= 256) ========
    const int st  = tid - 256;         // 0..127
    const int sw  = wid - 8;           // 0..3
    const int wr  = sw >> 1;           // row half (48 rows)
    const int wc  = sw & 1;            // col half (64 cols)
    const int rb4 = lane >> 3;         // 0..3
    const int cg  = lane & 7;          // 0..7
    float sacc[12][8];

    if (tid < 256) {
#pragma unroll
        for (int i = 0; i < 2; ++i)
#pragma unroll
            for (int j = 0; j < 8; ++j)
#pragma unroll
                for (int q = 0; q < 4; ++q) acc[i][j][q] = 0.f;
    } else {
#pragma unroll
        for (int i = 0; i < 12; ++i)
#pragma unroll
            for (int j = 0; j < 8; ++j) sacc[i][j] = 0.f;
    }

    // ---- prologue: stage chunk 0 ----
    if (tid < 256) {
#pragma unroll
        for (int i = 0; i < 4; ++i) av[i] = *(const float4*)(Ag + i * 4);
#pragma unroll
        for (int j = 0; j < 2; ++j) {
            bhv[j] = *(const uint4*)(Bhg + (cb + j) * 16);
            blv[j] = *(const uint4*)(Blg + (cb + j) * 16);
        }
        char* sA  = smem + AH_OFF + ra * STR + ca * 2;
        char* sAl = smem + AL_OFF + ra * STR + ca * 2;
#pragma unroll
        for (int i = 0; i < 4; ++i) {
            uint32_t h0, h1, l0, l1;
            cvt_hilo(av[i], h0, h1, l0, l1);
            *(uint2*)(sA  + i * 8) = make_uint2(h0, h1);
            *(uint2*)(sAl + i * 8) = make_uint2(l0, l1);
        }
#pragma unroll
        for (int j = 0; j < 2; ++j) {
            *(uint4*)(smem + BH_OFF + rb * STR + (cb + j) * 16) = bhv[j];
            *(uint4*)(smem + BL_OFF + rb * STR + (cb + j) * 16) = blv[j];
        }
    } else {
        // A-ext: 96 rows x 8 chunks(16B); B-ext: 32 rows x 32 chunks
#pragma unroll
        for (int q = 0; q < 6; ++q) {
            const int idx = st * 6 + q, row = idx >> 3, ch = idx & 7;
            cpasync16(sb + AE_OFF + row * 144 + ch * 16,
                      A + (size_t)(m0 + 128 + row) * K + ch * 4);
        }
#pragma unroll
        for (int q = 0; q < 8; ++q) {
            const int idx = st * 8 + q, row = idx >> 5, ch = idx & 31;
            cpasync16(sb + BE_OFF + row * 560 + ch * 16,
                      Wt + (size_t)row * 256 + n0 + ch * 4);
        }
        cpasync_commit();
    }
    cpasync_wait0();
    __syncthreads();

    for (int kt = 0; kt < nk; ++kt) {
        const int buf = kt & 1;
        const bool more = (kt + 1 < nk);

        if (tid < 256) {
            if (more) {
#pragma unroll
                for (int i = 0; i < 4; ++i) av[i] = *(const float4*)(Ag + (kt + 1) * 32 + i * 4);
#pragma unroll
                for (int j = 0; j < 2; ++j) {
                    bhv[j] = *(const uint4*)(Bhg + (kt + 1) * 64 + (cb + j) * 16);
                    blv[j] = *(const uint4*)(Blg + (kt + 1) * 64 + (cb + j) * 16);
                }
            }
            // ---- HMMA compute (per-p grouping, R4-proven) ----
            const uint32_t bufo = buf * STAGE;
#pragma unroll
            for (int ks = 0; ks < 2; ++ks) {
                const uint32_t ab = sb + bufo + a_off + ks * 32;
                const uint32_t bb = sb + bufo + b_off + ks * 32;
                uint32_t ah[2][4], al[2][4];
                ldsm4(ah[0], ab);
                ldsm4(ah[1], ab + 16 * STR);
                ldsm4(al[0], ab + (AL_OFF - AH_OFF));
                ldsm4(al[1], ab + (AL_OFF - AH_OFF) + 16 * STR);
#pragma unroll
                for (int p = 0; p < 4; ++p) {
                    uint32_t bh[4], bl[4];
                    ldsm4(bh, bb + p * (16 * STR));
                    ldsm4(bl, bb + p * (16 * STR) + (BL_OFF - BH_OFF));
#pragma unroll
                    for (int mi = 0; mi < 2; ++mi) {
                        mma_bf16(acc[mi][2 * p],     ah[mi], bh);
                        mma_bf16(acc[mi][2 * p],     al[mi], bh);
                        mma_bf16(acc[mi][2 * p],     ah[mi], bl);
                        mma_bf16(acc[mi][2 * p + 1], ah[mi], bh + 2);
                        mma_bf16(acc[mi][2 * p + 1], al[mi], bh + 2);
                        mma_bf16(acc[mi][2 * p + 1], ah[mi], bl + 2);
                    }
                }
            }
            if (more) {
                char* dA = smem + (buf ^ 1) * STAGE;
#pragma unroll
                for (int i = 0; i < 4; ++i) {
                    uint32_t h0, h1, l0, l1;
                    cvt_hilo(av[i], h0, h1, l0, l1);
                    *(uint2*)(dA + AH_OFF + ra * STR + ca * 2 + i * 8) = make_uint2(h0, h1);
                    *(uint2*)(dA + AL_OFF + ra * STR + ca * 2 + i * 8) = make_uint2(l0, l1);
                }
#pragma unroll
                for (int j = 0; j < 2; ++j) {
                    *(uint4*)(dA + BH_OFF + rb * STR + (cb + j) * 16) = bhv[j];
                    *(uint4*)(dA + BL_OFF + rb * STR + (cb + j) * 16) = blv[j];
                }
            }
        } else {
            if (more) {
                const uint32_t ae = sb + AE_OFF + (buf ^ 1) * AE_SZ;
                const uint32_t be = sb + BE_OFF + (buf ^ 1) * BE_SZ;
#pragma unroll
                for (int q = 0; q < 6; ++q) {
                    const int idx = st * 6 + q, row = idx >> 3, ch = idx & 7;
                    cpasync16(ae + row * 144 + ch * 16,
                              A + (size_t)(m0 + 128 + row) * K + (kt + 1) * 32 + ch * 4);
                }
#pragma unroll
                for (int q = 0; q < 8; ++q) {
                    const int idx = st * 8 + q, row = idx >> 5, ch = idx & 31;
                    cpasync16(be + row * 560 + ch * 16,
                              Wt + (size_t)((kt + 1) * 32 + row) * 256 + n0 + ch * 4);
                }
                cpasync_commit();
            }
            // ---- SIMT fp32 compute ----
            const float* Ae = (const float*)(smem + AE_OFF + buf * AE_SZ);
            const float* Be = (const float*)(smem + BE_OFF + buf * BE_SZ);
#pragma unroll 4
            for (int k = 0; k < 32; ++k) {
                float bf[8];
                const float* bp = Be + k * 140 + wc * 64 + cg * 8;
                *(float4*)&bf[0] = *(const float4*)bp;
                *(float4*)&bf[4] = *(const float4*)(bp + 4);
                float af[12];
#pragma unroll
                for (int i = 0; i < 12; ++i)
                    af[i] = Ae[(wr * 48 + rb4 + 4 * i) * 36 + k];
#pragma unroll
                for (int i = 0; i < 12; ++i)
#pragma unroll
                    for (int j = 0; j < 8; ++j)
                        sacc[i][j] = fmaf(af[i], bf[j], sacc[i][j]);
            }
        }

        if (more) {
            cpasync_wait0();
            __syncthreads();
        }
    }

    // ---- epilogues ----
    if (tid < 256) {
        const int g  = lane >> 2;
        const int cq = (lane & 3) * 2;
#pragma unroll
        for (int mi = 0; mi < 2; ++mi) {
            const int row0 = m0 + wm * 32 + mi * 16 + g;
            float* C0 = C + (size_t)row0 * 256 + n0 + wn * 64;
            float* C1 = C0 + (size_t)8 * 256;
#pragma unroll
            for (int ni = 0; ni < 8; ++ni) {
                *(float2*)(C0 + ni * 8 + cq) = make_float2(acc[mi][ni][0], acc[mi][ni][1]);
                *(float2*)(C1 + ni * 8 + cq) = make_float2(acc[mi][ni][2], acc[mi][ni][3]);
            }
        }
    } else {
#pragma unroll
        for (int i = 0; i < 12; ++i) {
            const int row = m0 + 128 + wr * 48 + rb4 + 4 * i;
            float* Cr = C + (size_t)row * 256 + n0 + wc * 64 + cg * 8;
            *(float4*)Cr       = make_float4(sacc[i][0], sacc[i][1], sacc[i][2], sacc[i][3]);
            *(float4*)(Cr + 4) = make_float4(sacc[i][4], sacc[i][5], sacc[i][6], sacc[i][7]);
        }
    }
}

// ---------------------------------------------------------------------------
// GAT attention layer 1: x2 = relu(alpha1 @ h1). 8 batches / block.
// ---------------------------------------------------------------------------
__global__ void __launch_bounds__(256)
attn1_kernel(const float* __restrict__ h1, const float* __restrict__ adj,
             const float* __restrict__ a1, float* __restrict__ x2) {
    extern __shared__ float sm[];
    float* hs   = sm;           // 14336
    float* av   = sm + 14336;   // 512
    float* sadj = sm + 14848;   // 49
    float* ssi  = sm + 14897;   // 56
    float* ssj  = sm + 14953;   // 56
    float* sal  = sm + 15009;   // 392
    const int tid = threadIdx.x;
    const int w = tid >> 5, lane = tid & 31;
    const size_t base = (size_t)blockIdx.x * (GB * NND * HID);

    {
        const float4* src = (const float4*)(h1 + base);
        float4* dst = (float4*)hs;
        for (int i = tid; i < GB * NND * HID / 4; i += 256) dst[i] = src[i];
        if (tid < 128) ((float4*)av)[tid] = ((const float4*)a1)[tid];
        if (tid < 49) sadj[tid] = adj[tid];
    }
    __syncthreads();

    {
#pragma unroll
        for (int ri = 0; ri < 7; ++ri) {
            const int r = w * 7 + ri;
            const float* hr = hs + r * HID;
            float si = 0.f, sj = 0.f;
#pragma unroll
            for (int k = lane; k < HID; k += 32) {
                const float hv = hr[k];
                si = fmaf(hv, av[k], si);
                sj = fmaf(hv, av[HID + k], sj);
            }
#pragma unroll
            for (int off = 16; off > 0; off >>= 1) {
                si += __shfl_xor_sync(0xffffffffu, si, off);
                sj += __shfl_xor_sync(0xffffffffu, sj, off);
            }
            if (lane == 0) { ssi[r] = si; ssj[r] = sj; }
        }
    }
    __syncthreads();

    if (tid < GB * NND) {
        const int b = tid / 7, i = tid - b * 7;
        float e[7]; float mx = -3.0e38f;
#pragma unroll
        for (int j = 0; j < 7; ++j) {
            float v = ssi[b * 7 + i] + ssj[b * 7 + j];
            v = (v > 0.f) ? v : 0.2f * v;
            if (sadj[i * 7 + j] == 0.f) v = -3.0e38f;
            e[j] = v; mx = fmaxf(mx, v);
        }
        float s = 0.f;
#pragma unroll
        for (int j = 0; j < 7; ++j) {
            const float ex = (e[j] < -1.0e38f) ? 0.f : __expf(e[j] - mx);
            e[j] = ex; s += ex;
        }
        const float inv = 1.f / s;
#pragma unroll
        for (int j = 0; j < 7; ++j) sal[tid * 7 + j] = e[j] * inv;
    }
    __syncthreads();

    {
        const float* hb = hs + w * 7 * HID;
#pragma unroll
        for (int ri = 0; ri < 7; ++ri) {
            const int r = w * 7 + ri;
            const float* alr = sal + r * 7;
            float a0 = alr[0], a1v = alr[1], a2v = alr[2], a3 = alr[3],
                  a4 = alr[4], a5 = alr[5], a6 = alr[6];
#pragma unroll
            for (int d4 = lane; d4 < 64; d4 += 32) {
                const float4* p0 = (const float4*)(hb) + d4;
                float4 h0 = p0[0],  h1v = p0[64],  h2 = p0[128], h3 = p0[192],
                       h4 = p0[256], h5 = p0[320], h6 = p0[384];
                float4 o;
                o.x = a0*h0.x + a1v*h1v.x + a2v*h2.x + a3*h3.x + a4*h4.x + a5*h5.x + a6*h6.x;
                o.y = a0*h0.y + a1v*h1v.y + a2v*h2.y + a3*h3.y + a4*h4.y + a5*h5.y + a6*h6.y;
                o.z = a0*h0.z + a1v*h1v.z + a2v*h2.z + a3*h3.z + a4*h4.z + a5*h5.z + a6*h6.z;
                o.w = a0*h0.w + a1v*h1v.w + a2v*h2.w + a3*h3.w + a4*h4.w + a5*h5.w + a6*h6.w;
                o.x = fmaxf(o.x, 0.f); o.y = fmaxf(o.y, 0.f);
                o.z = fmaxf(o.z, 0.f); o.w = fmaxf(o.w, 0.f);
                *(float4*)(x2 + base + r * HID + d4 * 4) = o;
            }
        }
    }
}

// ---------------------------------------------------------------------------
// GAT layer 2 attention + MLP heads, fused. GB2=4 batches/block.
// out = [pred(B) | weights(B*5) | attn2(B*49)]
// ---------------------------------------------------------------------------
__global__ void __launch_bounds__(256)
attn2_heads_kernel(const float* __restrict__ h2, const float* __restrict__ adj,
                   const float* __restrict__ a2, const float* __restrict__ context,
                   const float* __restrict__ base_preds,
                   const float* __restrict__ wh1_w, const float* __restrict__ wh1_b,
                   const float* __restrict__ wh2_w, const float* __restrict__ wh2_b,
                   const float* __restrict__ wh3_w, const float* __restrict__ wh3_b,
                   const float* __restrict__ rh1_w, const float* __restrict__ rh1_b,
                   const float* __restrict__ rh2_w, const float* __restrict__ rh2_b,
                   float* __restrict__ out) {
    extern __shared__ float sm[];
    float* hs   = sm;            // 7168
    float* comb = sm + 7168;     // 4*2052 = 8208
    float* av   = sm + 15376;    // 512
    float* sadj = sm + 15888;    // 49
    float* ssi  = sm + 15937;    // 28
    float* ssj  = sm + 15965;    // 28
    float* sal  = sm + 15993;    // 196
    float* t1s  = sm + 16189;    // 128
    float* rrs  = sm + 16317;    // 64
    const int tid = threadIdx.x;
    const int w = tid >> 5, lane = tid & 31;
    const int b0 = blockIdx.x * GB2;
    const size_t base = (size_t)blockIdx.x * (GB2 * NND * HID);

    {
        const float4* src = (const float4*)(h2 + base);
        float4* dst = (float4*)hs;
        for (int i = tid; i < GB2 * NND * HID / 4; i += 256) dst[i] = src[i];
        if (tid < 128) ((float4*)av)[tid] = ((const float4*)a2)[tid];
        if (tid < 49) sadj[tid] = adj[tid];
    }
    __syncthreads();

    {
        for (int r = w; r < GB2 * NND; r += 8) {
            const float* hr = hs + r * HID;
            float si = 0.f, sj = 0.f;
#pragma unroll
            for (int k = lane; k < HID; k += 32) {
                const float hv = hr[k];
                si = fmaf(hv, av[k], si);
                sj = fmaf(hv, av[HID + k], sj);
            }
#pragma unroll
            for (int off = 16; off > 0; off >>= 1) {
                si += __shfl_xor_sync(0xffffffffu, si, off);
                sj += __shfl_xor_sync(0xffffffffu, sj, off);
            }
            if (lane == 0) { ssi[r] = si; ssj[r] = sj; }
        }
    }
    __syncthreads();

    if (tid < GB2 * NND) {
        const int b = tid / 7, i = tid - b * 7;
        float e[7]; float mx = -3.0e38f;
#pragma unroll
        for (int j = 0; j < 7; ++j) {
            float v = ssi[b * 7 + i] + ssj[b * 7 + j];
            v = (v > 0.f) ? v : 0.2f * v;
            if (sadj[i * 7 + j] == 0.f) v = -3.0e38f;
            e[j] = v; mx = fmaxf(mx, v);
        }
        float s = 0.f;
#pragma unroll
        for (int j = 0; j < 7; ++j) {
            const float ex = (e[j] < -1.0e38f) ? 0.f : __expf(e[j] - mx);
            e[j] = ex; s += ex;
        }
        const float inv = 1.f / s;
        float* oa = out + (size_t)6 * BATCH + (size_t)(b0 + b) * 49 + i * 7;
#pragma unroll
        for (int j = 0; j < 7; ++j) {
            const float al = e[j] * inv;
            sal[tid * 7 + j] = al;
            oa[j] = al;
        }
    }
    __syncthreads();

    for (int r = w; r < GB2 * NND; r += 8) {
        const int b = r / 7;
        const float* hb = hs + b * 7 * HID;
        const float* alr = sal + r * 7;
        float a0 = alr[0], a1v = alr[1], a2v = alr[2], a3 = alr[3],
              a4 = alr[4], a5 = alr[5], a6 = alr[6];
        const int rem = r - b * 7;
#pragma unroll
        for (int d4 = lane; d4 < 64; d4 += 32) {
            const float4* p0 = (const float4*)(hb) + d4;
            float4 h0 = p0[0],  h1v = p0[64],  h2 = p0[128], h3 = p0[192],
                   h4 = p0[256], h5 = p0[320], h6 = p0[384];
            float4 o;
            o.x = a0*h0.x + a1v*h1v.x + a2v*h2.x + a3*h3.x + a4*h4.x + a5*h5.x + a6*h6.x;
            o.y = a0*h0.y + a1v*h1v.y + a2v*h2.y + a3*h3.y + a4*h4.y + a5*h5.y + a6*h6.y;
            o.z = a0*h0.z + a1v*h1v.z + a2v*h2.z + a3*h3.z + a4*h4.z + a5*h5.z + a6*h6.z;
            o.w = a0*h0.w + a1v*h1v.w + a2v*h2.w + a3*h3.w + a4*h4.w + a5*h5.w + a6*h6.w;
            o.x = fmaxf(o.x, 0.f); o.y = fmaxf(o.y, 0.f);
            o.z = fmaxf(o.z, 0.f); o.w = fmaxf(o.w, 0.f);
            *(float4*)(comb + b * CS + rem * HID + d4 * 4) = o;
        }
    }
    for (int idx = tid; idx < GB2 * CTXD; idx += 256) {
        const int b = idx >> 8, c = idx & 255;
        comb[b * CS + NND * HID + c] = context[(size_t)(b0 + b) * CTXD + c];
    }
    __syncthreads();

    if (tid < 128) {
        const int row = tid >> 2, b = tid & 3;
        const float4* wv = (const float4*)wh1_w + row * 512;
        const float4* cv = (const float4*)(comb + b * CS);
        float4 a4 = make_float4(0.f, 0.f, 0.f, 0.f);
        for (int k = 0; k < 512; ++k) {
            const float4 w4 = wv[k], c4 = cv[k];
            a4.x = fmaf(w4.x, c4.x, a4.x);
            a4.y = fmaf(w4.y, c4.y, a4.y);
            a4.z = fmaf(w4.z, c4.z, a4.z);
            a4.w = fmaf(w4.w, c4.w, a4.w);
        }
        t1s[b * 32 + row] = fmaxf(a4.x + a4.y + a4.z + a4.w + wh1_b[row], 0.f);
    } else if (tid < 192) {
        const int t = tid - 128;
        const int row = t >> 2, b = t & 3;
        const float4* wv = (const float4*)rh1_w + row * 512;
        const float4* cv = (const float4*)(comb + b * CS);
        float4 a4 = make_float4(0.f, 0.f, 0.f, 0.f);
        for (int k = 0; k < 512; ++k) {
            const float4 w4 = wv[k], c4 = cv[k];
            a4.x = fmaf(w4.x, c4.x, a4.x);
            a4.y = fmaf(w4.y, c4.y, a4.y);
            a4.z = fmaf(w4.z, c4.z, a4.z);
            a4.w = fmaf(w4.w, c4.w, a4.w);
        }
        rrs[b * 16 + row] = tanhf(a4.x + a4.y + a4.z + a4.w + rh1_b[row]);
    }
    __syncthreads();

    if (tid < GB2) {
        const int b = tid;
        float t2[16];
#pragma unroll
        for (int o = 0; o < 16; ++o) {
            float s = wh2_b[o];
#pragma unroll
            for (int k = 0; k < 32; ++k) s = fmaf(t1s[b * 32 + k], wh2_w[o * 32 + k], s);
            t2[o] = fmaxf(s, 0.f);
        }
        float raw[5]; float mx = -3.0e38f;
#pragma unroll
        for (int o = 0; o < 5; ++o) {
            float s = wh3_b[o];
#pragma unroll
            for (int k = 0; k < 16; ++k) s = fmaf(t2[k], wh3_w[o * 16 + k], s);
            raw[o] = s; mx = fmaxf(mx, s);
        }
        float se = 0.f;
#pragma unroll
        for (int o = 0; o < 5; ++o) { raw[o] = __expf(raw[o] - mx); se += raw[o]; }
        const float inv = 1.f / se;
        float wp = 0.f;
#pragma unroll
        for (int o = 0; o < 5; ++o) {
            const float wt = raw[o] * inv;
            out[BATCH + (size_t)(b0 + b) * 5 + o] = wt;
            wp = fmaf(wt, base_preds[(size_t)(b0 + b) * 5 + o], wp);
        }
        float rr = rh2_b[0];
#pragma unroll
        for (int k = 0; k < 16; ++k) rr = fmaf(rrs[b * 16 + k], rh2_w[k], rr);
        out[b0 + b] = fmaxf(wp + rr * 0.05f, 0.05f);
    }
}

// ---------------------------------------------------------------------------
extern "C" void kernel_launch(void* const* d_in, const int* in_sizes, int n_in,
                              void* d_out, int out_size) {
    const float* node_feats = (const float*)d_in[0];
    const float* adj        = (const float*)d_in[1];
    const float* context    = (const float*)d_in[2];
    const float* base_preds = (const float*)d_in[3];
    const float* W1    = (const float*)d_in[4];
    const float* a1    = (const float*)d_in[5];
    const float* W2    = (const float*)d_in[6];
    const float* a2    = (const float*)d_in[7];
    const float* wh1_w = (const float*)d_in[8];
    const float* wh1_b = (const float*)d_in[9];
    const float* wh2_w = (const float*)d_in[10];
    const float* wh2_b = (const float*)d_in[11];
    const float* wh3_w = (const float*)d_in[12];
    const float* wh3_b = (const float*)d_in[13];
    const float* rh1_w = (const float*)d_in[14];
    const float* rh1_b = (const float*)d_in[15];
    const float* rh2_w = (const float*)d_in[16];
    const float* rh2_b = (const float*)d_in[17];
    float* out = (float*)d_out;

    float *h1p, *x2p, *h2p, *w1t, *w2t;
    __nv_bfloat16 *w1h, *w1l, *w2h, *w2l;
    cudaGetSymbolAddress((void**)&h1p, g_h1);
    cudaGetSymbolAddress((void**)&x2p, g_x2);
    cudaGetSymbolAddress((void**)&h2p, g_h2);
    cudaGetSymbolAddress((void**)&w1h, g_w1hi);
    cudaGetSymbolAddress((void**)&w1l, g_w1lo);
    cudaGetSymbolAddress((void**)&w2h, g_w2hi);
    cudaGetSymbolAddress((void**)&w2l, g_w2lo);
    cudaGetSymbolAddress((void**)&w1t, g_w1t);
    cudaGetSymbolAddress((void**)&w2t, g_w2t);

    const int smem1 = 15401 * 4;
    const int smem2 = 16381 * 4;
    cudaFuncSetAttribute(gemm_hybrid, cudaFuncAttributeMaxDynamicSharedMemorySize, G_SMEM);
    cudaFuncSetAttribute(attn1_kernel, cudaFuncAttributeMaxDynamicSharedMemorySize, smem1);
    cudaFuncSetAttribute(attn2_heads_kernel, cudaFuncAttributeMaxDynamicSharedMemorySize, smem2);

    // pre-split + pre-transpose weights
    convw_kernel<<<(HID * FEATD + 255) / 256, 256>>>(W1, w1h, w1l, HID * FEATD);
    convw_kernel<<<(HID * HID + 255) / 256, 256>>>(W2, w2h, w2l, HID * HID);
    transw_kernel<<<(HID * FEATD + 255) / 256, 256>>>(W1, w1t, FEATD);
    transw_kernel<<<(HID * HID + 255) / 256, 256>>>(W2, w2t, HID);

    // h1 = node_feats @ W1^T  (hybrid tensor+fma)
    gemm_hybrid<<<dim3(MROWS / TILE_M, 2), 384, G_SMEM>>>(node_feats, w1h, w1l, w1t, h1p, FEATD);
    // x2 = relu(alpha1 @ h1)
    attn1_kernel<<<BATCH / GB, 256, smem1>>>(h1p, adj, a1, x2p);
    // h2 = x2 @ W2^T
    gemm_hybrid<<<dim3(MROWS / TILE_M, 2), 384, G_SMEM>>>(x2p, w2h, w2l, w2t, h2p, HID);
    // layer-2 attention + heads + outputs
    attn2_heads_kernel<<<BATCH / GB2, 256, smem2>>>(h2p, adj, a2, context, base_preds,
                                                    wh1_w, wh1_b, wh2_w, wh2_b,
                                                    wh3_w, wh3_b, rh1_w, rh1_b,
                                                    rh2_w, rh2_b, out);
}

// round 11
// speedup vs baseline: 1.5586x; 1.5586x over previous
#include <cuda_runtime.h>
#include <cuda_fp16.h>
#include <cstdint>
#include <cstddef>

#define BATCH 16384
#define NND   7
#define FEATD 512
#define HID   256
#define CTXD  256
#define MROWS (BATCH * NND)        // 114688
#define GB    8                    // batches per attn1 block
#define GB2   4                    // batches per attn2 block
#define CS    2052                 // padded combined stride (floats)

// smem staging layout (bytes); row stride 80 = 5x16B -> LDSM row fetches for
// 8 consecutive rows land on 8 distinct 16B chunks (mod 128): conflict-free.
#define STR     80
#define AH_OFF  0
#define AL_OFF  10240
#define BH_OFF  20480
#define STAGE   30720
#define G_SMEM  (2 * STAGE)

// ---------------- scratch (no allocs allowed; __device__ globals) ----------
__device__ float g_h1[(size_t)MROWS * HID];
__device__ float g_x2[(size_t)MROWS * HID];
__device__ float g_h2[(size_t)MROWS * HID];
__device__ __half g_w1h[HID * FEATD];
__device__ __half g_w2h[HID * HID];

// ---------------- helpers --------------------------------------------------
__device__ __forceinline__ uint32_t smem_u32(const void* p) {
    uint32_t a;
    asm("{ .reg .u64 t; cvta.to.shared.u64 t, %1; cvt.u32.u64 %0, t; }" : "=r"(a) : "l"(p));
    return a;
}
__device__ __forceinline__ void ldsm4(uint32_t* r, uint32_t addr) {
    asm volatile("ldmatrix.sync.aligned.m8n8.x4.shared.b16 {%0,%1,%2,%3}, [%4];"
                 : "=r"(r[0]), "=r"(r[1]), "=r"(r[2]), "=r"(r[3]) : "r"(addr));
}
__device__ __forceinline__ void mma_f16(float* c, const uint32_t* a, const uint32_t* b) {
    asm volatile(
        "mma.sync.aligned.m16n8k16.row.col.f32.f16.f16.f32 "
        "{%0,%1,%2,%3}, {%4,%5,%6,%7}, {%8,%9}, {%0,%1,%2,%3};"
        : "+f"(c[0]), "+f"(c[1]), "+f"(c[2]), "+f"(c[3])
        : "r"(a[0]), "r"(a[1]), "r"(a[2]), "r"(a[3]), "r"(b[0]), "r"(b[1]));
}
// fp32 -> fp16 hi + fp16 residual (2 packed pairs)
__device__ __forceinline__ void cvt_hilo(float4 v, uint32_t& h0, uint32_t& h1,
                                         uint32_t& l0, uint32_t& l1) {
    __half2 ha = __floats2half2_rn(v.x, v.y);
    __half2 hb = __floats2half2_rn(v.z, v.w);
    float2 fa = __half22float2(ha);
    float2 fb = __half22float2(hb);
    __half2 la = __floats2half2_rn(v.x - fa.x, v.y - fa.y);
    __half2 lb = __floats2half2_rn(v.z - fb.x, v.w - fb.y);
    h0 = *(uint32_t*)&ha; h1 = *(uint32_t*)&hb;
    l0 = *(uint32_t*)&la; l1 = *(uint32_t*)&lb;
}

// ---------------------------------------------------------------------------
// Weight convert: fp32 -> fp16 (single precision level; A carries the split)
// ---------------------------------------------------------------------------
__global__ void convw_kernel(const float* __restrict__ W, __half* __restrict__ H, int n) {
    int i = blockIdx.x * 256 + threadIdx.x;
    if (i < n) H[i] = __float2half_rn(W[i]);
}

// ---------------------------------------------------------------------------
// HMMA GEMM: C[m,n] = sum_k A[m,k]*W[n,k].  A fp32 (M x K) split in-kernel to
// fp16 hi/lo; W pre-converted fp16 (256 x K). 2-term: Ah*Bh + Al*Bh.
// Block 128x128, BK=32, 256 threads = 8 warps (4m x 2n), warp tile 32x64.
// ---------------------------------------------------------------------------
__global__ void __launch_bounds__(256)
gemm_mma(const float* __restrict__ A, const __half* __restrict__ Bh16,
         float* __restrict__ C, int K) {
    extern __shared__ char smem[];
    const uint32_t sb = smem_u32(smem);
    const int tid  = threadIdx.x;
    const int lane = tid & 31;
    const int wid  = tid >> 5;
    const int wm   = wid & 3;      // warp row block (32 rows)
    const int wn   = wid >> 2;     // warp col block (64 cols)
    const int m0   = blockIdx.x * 128;
    const int n0   = blockIdx.y * 128;
    const int nk   = K >> 5;       // BK = 32

    // --- staging maps ---
    const int ra = tid >> 1;                 // A row 0..127
    const int ca = (tid & 1) * 16;           // A col base (fp32 within 32-chunk)
    const float* Ag = A + (size_t)(m0 + ra) * K + ca;
    const int rb = tid >> 1;                 // B row 0..127
    const int cb = (tid & 1) * 2;            // B 16B chunk base (0 or 2)
    const char* Bhg = (const char*)Bh16 + (size_t)(n0 + rb) * K * 2;
    char* sA  = smem + AH_OFF + ra * STR + ca * 2;
    char* sAl = smem + AL_OFF + ra * STR + ca * 2;
    char* sBh = smem + BH_OFF + rb * STR + cb * 16;

    // --- LDSM address bases (per warp lane) ---
    const uint32_t a_off = AH_OFF + (uint32_t)(wm * 32 + (lane & 15)) * STR + ((lane >> 4) << 4);
    const uint32_t b_off = BH_OFF + (uint32_t)(wn * 64 + (lane & 7) + ((lane >> 4) << 3)) * STR
                         + ((lane & 8) << 1);

    float acc[2][8][4];
#pragma unroll
    for (int i = 0; i < 2; ++i)
#pragma unroll
        for (int j = 0; j < 8; ++j)
#pragma unroll
            for (int q = 0; q < 4; ++q) acc[i][j][q] = 0.f;

    float4 av[4];
    uint4  bhv[2];

    // prologue: load + stage chunk 0
#pragma unroll
    for (int i = 0; i < 4; ++i) av[i] = *(const float4*)(Ag + i * 4);
#pragma unroll
    for (int j = 0; j < 2; ++j) bhv[j] = *(const uint4*)(Bhg + (cb + j) * 16);
#pragma unroll
    for (int i = 0; i < 4; ++i) {
        uint32_t h0, h1, l0, l1;
        cvt_hilo(av[i], h0, h1, l0, l1);
        *(uint2*)(sA  + i * 8) = make_uint2(h0, h1);
        *(uint2*)(sAl + i * 8) = make_uint2(l0, l1);
    }
#pragma unroll
    for (int j = 0; j < 2; ++j) *(uint4*)(sBh + j * 16) = bhv[j];
    __syncthreads();

    for (int kt = 0; kt < nk; ++kt) {
        const uint32_t bufo = (kt & 1) * STAGE;
        const bool more = (kt + 1 < nk);
        if (more) {
#pragma unroll
            for (int i = 0; i < 4; ++i) av[i] = *(const float4*)(Ag + (kt + 1) * 32 + i * 4);
#pragma unroll
            for (int j = 0; j < 2; ++j)
                bhv[j] = *(const uint4*)(Bhg + (kt + 1) * 64 + (cb + j) * 16);
        }

        // ---- compute BK=32 from buffer bufo, term-major ----
#pragma unroll
        for (int ks = 0; ks < 2; ++ks) {
            const uint32_t ab = sb + bufo + a_off + ks * 32;
            const uint32_t bb = sb + bufo + b_off + ks * 32;
            uint32_t ah[2][4], al[2][4], bh[4][4];
            ldsm4(ah[0], ab);
            ldsm4(ah[1], ab + 16 * STR);
            ldsm4(al[0], ab + (AL_OFF - AH_OFF));
            ldsm4(al[1], ab + (AL_OFF - AH_OFF) + 16 * STR);
#pragma unroll
            for (int p = 0; p < 4; ++p) ldsm4(bh[p], bb + p * (16 * STR));
            // term 1: Ah * Bh   (16 independent MMAs)
#pragma unroll
            for (int p = 0; p < 4; ++p)
#pragma unroll
                for (int mi = 0; mi < 2; ++mi) {
                    mma_f16(acc[mi][2 * p],     ah[mi], bh[p]);
                    mma_f16(acc[mi][2 * p + 1], ah[mi], bh[p] + 2);
                }
            // term 2: Al * Bh
#pragma unroll
            for (int p = 0; p < 4; ++p)
#pragma unroll
                for (int mi = 0; mi < 2; ++mi) {
                    mma_f16(acc[mi][2 * p],     al[mi], bh[p]);
                    mma_f16(acc[mi][2 * p + 1], al[mi], bh[p] + 2);
                }
        }

        if (more) {
            char* dA = smem + ((kt + 1) & 1) * STAGE;
#pragma unroll
            for (int i = 0; i < 4; ++i) {
                uint32_t h0, h1, l0, l1;
                cvt_hilo(av[i], h0, h1, l0, l1);
                *(uint2*)(dA + AH_OFF + ra * STR + ca * 2 + i * 8) = make_uint2(h0, h1);
                *(uint2*)(dA + AL_OFF + ra * STR + ca * 2 + i * 8) = make_uint2(l0, l1);
            }
#pragma unroll
            for (int j = 0; j < 2; ++j)
                *(uint4*)(dA + BH_OFF + rb * STR + (cb + j) * 16) = bhv[j];
            __syncthreads();
        }
    }

    // ---- epilogue ----
    const int g  = lane >> 2;
    const int cq = (lane & 3) * 2;
#pragma unroll
    for (int mi = 0; mi < 2; ++mi) {
        const int row0 = m0 + wm * 32 + mi * 16 + g;
        float* C0 = C + (size_t)row0 * 256 + n0 + wn * 64;
        float* C1 = C0 + (size_t)8 * 256;
#pragma unroll
        for (int ni = 0; ni < 8; ++ni) {
            *(float2*)(C0 + ni * 8 + cq) = make_float2(acc[mi][ni][0], acc[mi][ni][1]);
            *(float2*)(C1 + ni * 8 + cq) = make_float2(acc[mi][ni][2], acc[mi][ni][3]);
        }
    }
}

// ---------------------------------------------------------------------------
// GAT attention layer 1: x2 = relu(alpha1 @ h1). 8 batches / block.
// ---------------------------------------------------------------------------
__global__ void __launch_bounds__(256)
attn1_kernel(const float* __restrict__ h1, const float* __restrict__ adj,
             const float* __restrict__ a1, float* __restrict__ x2) {
    extern __shared__ float sm[];
    float* hs   = sm;           // 14336
    float* av   = sm + 14336;   // 512
    float* sadj = sm + 14848;   // 49
    float* ssi  = sm + 14897;   // 56
    float* ssj  = sm + 14953;   // 56
    float* sal  = sm + 15009;   // 392
    const int tid = threadIdx.x;
    const int w = tid >> 5, lane = tid & 31;
    const size_t base = (size_t)blockIdx.x * (GB * NND * HID);

    {
        const float4* src = (const float4*)(h1 + base);
        float4* dst = (float4*)hs;
        for (int i = tid; i < GB * NND * HID / 4; i += 256) dst[i] = src[i];
        if (tid < 128) ((float4*)av)[tid] = ((const float4*)a1)[tid];
        if (tid < 49) sadj[tid] = adj[tid];
    }
    __syncthreads();

    {
#pragma unroll
        for (int ri = 0; ri < 7; ++ri) {
            const int r = w * 7 + ri;
            const float* hr = hs + r * HID;
            float si = 0.f, sj = 0.f;
#pragma unroll
            for (int k = lane; k < HID; k += 32) {
                const float hv = hr[k];
                si = fmaf(hv, av[k], si);
                sj = fmaf(hv, av[HID + k], sj);
            }
#pragma unroll
            for (int off = 16; off > 0; off >>= 1) {
                si += __shfl_xor_sync(0xffffffffu, si, off);
                sj += __shfl_xor_sync(0xffffffffu, sj, off);
            }
            if (lane == 0) { ssi[r] = si; ssj[r] = sj; }
        }
    }
    __syncthreads();

    if (tid < GB * NND) {
        const int b = tid / 7, i = tid - b * 7;
        float e[7]; float mx = -3.0e38f;
#pragma unroll
        for (int j = 0; j < 7; ++j) {
            float v = ssi[b * 7 + i] + ssj[b * 7 + j];
            v = (v > 0.f) ? v : 0.2f * v;
            if (sadj[i * 7 + j] == 0.f) v = -3.0e38f;
            e[j] = v; mx = fmaxf(mx, v);
        }
        float s = 0.f;
#pragma unroll
        for (int j = 0; j < 7; ++j) {
            const float ex = (e[j] < -1.0e38f) ? 0.f : __expf(e[j] - mx);
            e[j] = ex; s += ex;
        }
        const float inv = 1.f / s;
#pragma unroll
        for (int j = 0; j < 7; ++j) sal[tid * 7 + j] = e[j] * inv;
    }
    __syncthreads();

    // aggregation: warp w -> graph w, rows w*7..w*7+6, float4 over HID
    {
        const float* hb = hs + w * 7 * HID;
#pragma unroll
        for (int ri = 0; ri < 7; ++ri) {
            const int r = w * 7 + ri;
            const float* alr = sal + r * 7;
            float a0 = alr[0], a1v = alr[1], a2v = alr[2], a3 = alr[3],
                  a4 = alr[4], a5 = alr[5], a6 = alr[6];
#pragma unroll
            for (int d4 = lane; d4 < 64; d4 += 32) {
                const float4* p0 = (const float4*)(hb) + d4;
                float4 h0 = p0[0],  h1v = p0[64],  h2 = p0[128], h3 = p0[192],
                       h4 = p0[256], h5 = p0[320], h6 = p0[384];
                float4 o;
                o.x = a0*h0.x + a1v*h1v.x + a2v*h2.x + a3*h3.x + a4*h4.x + a5*h5.x + a6*h6.x;
                o.y = a0*h0.y + a1v*h1v.y + a2v*h2.y + a3*h3.y + a4*h4.y + a5*h5.y + a6*h6.y;
                o.z = a0*h0.z + a1v*h1v.z + a2v*h2.z + a3*h3.z + a4*h4.z + a5*h5.z + a6*h6.z;
                o.w = a0*h0.w + a1v*h1v.w + a2v*h2.w + a3*h3.w + a4*h4.w + a5*h5.w + a6*h6.w;
                o.x = fmaxf(o.x, 0.f); o.y = fmaxf(o.y, 0.f);
                o.z = fmaxf(o.z, 0.f); o.w = fmaxf(o.w, 0.f);
                *(float4*)(x2 + base + r * HID + d4 * 4) = o;
            }
        }
    }
}

// ---------------------------------------------------------------------------
// GAT layer 2 attention + MLP heads, fused. GB2=4 batches/block.
// out = [pred(B) | weights(B*5) | attn2(B*49)]
// ---------------------------------------------------------------------------
__global__ void __launch_bounds__(256)
attn2_heads_kernel(const float* __restrict__ h2, const float* __restrict__ adj,
                   const float* __restrict__ a2, const float* __restrict__ context,
                   const float* __restrict__ base_preds,
                   const float* __restrict__ wh1_w, const float* __restrict__ wh1_b,
                   const float* __restrict__ wh2_w, const float* __restrict__ wh2_b,
                   const float* __restrict__ wh3_w, const float* __restrict__ wh3_b,
                   const float* __restrict__ rh1_w, const float* __restrict__ rh1_b,
                   const float* __restrict__ rh2_w, const float* __restrict__ rh2_b,
                   float* __restrict__ out) {
    extern __shared__ float sm[];
    float* hs   = sm;            // 7168
    float* comb = sm + 7168;     // 4*2052 = 8208
    float* av   = sm + 15376;    // 512
    float* sadj = sm + 15888;    // 49
    float* ssi  = sm + 15937;    // 28
    float* ssj  = sm + 15965;    // 28
    float* sal  = sm + 15993;    // 196
    float* t1s  = sm + 16189;    // 128
    float* rrs  = sm + 16317;    // 64   (total 16381 floats)
    const int tid = threadIdx.x;
    const int w = tid >> 5, lane = tid & 31;
    const int b0 = blockIdx.x * GB2;
    const size_t base = (size_t)blockIdx.x * (GB2 * NND * HID);

    {
        const float4* src = (const float4*)(h2 + base);
        float4* dst = (float4*)hs;
        for (int i = tid; i < GB2 * NND * HID / 4; i += 256) dst[i] = src[i];
        if (tid < 128) ((float4*)av)[tid] = ((const float4*)a2)[tid];
        if (tid < 49) sadj[tid] = adj[tid];
    }
    __syncthreads();

    {
        for (int r = w; r < GB2 * NND; r += 8) {
            const float* hr = hs + r * HID;
            float si = 0.f, sj = 0.f;
#pragma unroll
            for (int k = lane; k < HID; k += 32) {
                const float hv = hr[k];
                si = fmaf(hv, av[k], si);
                sj = fmaf(hv, av[HID + k], sj);
            }
#pragma unroll
            for (int off = 16; off > 0; off >>= 1) {
                si += __shfl_xor_sync(0xffffffffu, si, off);
                sj += __shfl_xor_sync(0xffffffffu, sj, off);
            }
            if (lane == 0) { ssi[r] = si; ssj[r] = sj; }
        }
    }
    __syncthreads();

    if (tid < GB2 * NND) {
        const int b = tid / 7, i = tid - b * 7;
        float e[7]; float mx = -3.0e38f;
#pragma unroll
        for (int j = 0; j < 7; ++j) {
            float v = ssi[b * 7 + i] + ssj[b * 7 + j];
            v = (v > 0.f) ? v : 0.2f * v;
            if (sadj[i * 7 + j] == 0.f) v = -3.0e38f;
            e[j] = v; mx = fmaxf(mx, v);
        }
        float s = 0.f;
#pragma unroll
        for (int j = 0; j < 7; ++j) {
            const float ex = (e[j] < -1.0e38f) ? 0.f : __expf(e[j] - mx);
            e[j] = ex; s += ex;
        }
        const float inv = 1.f / s;
        float* oa = out + (size_t)6 * BATCH + (size_t)(b0 + b) * 49 + i * 7;
#pragma unroll
        for (int j = 0; j < 7; ++j) {
            const float al = e[j] * inv;
            sal[tid * 7 + j] = al;
            oa[j] = al;
        }
    }
    __syncthreads();

    // aggregation: warp handles rows r = w, w+8, ... (28 rows over 8 warps)
    for (int r = w; r < GB2 * NND; r += 8) {
        const int b = r / 7;
        const float* hb = hs + b * 7 * HID;
        const float* alr = sal + r * 7;
        float a0 = alr[0], a1v = alr[1], a2v = alr[2], a3 = alr[3],
              a4 = alr[4], a5 = alr[5], a6 = alr[6];
        const int rem = r - b * 7;
#pragma unroll
        for (int d4 = lane; d4 < 64; d4 += 32) {
            const float4* p0 = (const float4*)(hb) + d4;
            float4 h0 = p0[0],  h1v = p0[64],  h2 = p0[128], h3 = p0[192],
                   h4 = p0[256], h5 = p0[320], h6 = p0[384];
            float4 o;
            o.x = a0*h0.x + a1v*h1v.x + a2v*h2.x + a3*h3.x + a4*h4.x + a5*h5.x + a6*h6.x;
            o.y = a0*h0.y + a1v*h1v.y + a2v*h2.y + a3*h3.y + a4*h4.y + a5*h5.y + a6*h6.y;
            o.z = a0*h0.z + a1v*h1v.z + a2v*h2.z + a3*h3.z + a4*h4.z + a5*h5.z + a6*h6.z;
            o.w = a0*h0.w + a1v*h1v.w + a2v*h2.w + a3*h3.w + a4*h4.w + a5*h5.w + a6*h6.w;
            o.x = fmaxf(o.x, 0.f); o.y = fmaxf(o.y, 0.f);
            o.z = fmaxf(o.z, 0.f); o.w = fmaxf(o.w, 0.f);
            *(float4*)(comb + b * CS + rem * HID + d4 * 4) = o;
        }
    }
    for (int idx = tid; idx < GB2 * CTXD; idx += 256) {
        const int b = idx >> 8, c = idx & 255;
        comb[b * CS + NND * HID + c] = context[(size_t)(b0 + b) * CTXD + c];
    }
    __syncthreads();

    if (tid < 128) {            // weight head L1: 32 rows x 4 batches
        const int row = tid >> 2, b = tid & 3;
        const float4* wv = (const float4*)wh1_w + row * 512;
        const float4* cv = (const float4*)(comb + b * CS);
        float4 a4 = make_float4(0.f, 0.f, 0.f, 0.f);
        for (int k = 0; k < 512; ++k) {
            const float4 w4 = wv[k], c4 = cv[k];
            a4.x = fmaf(w4.x, c4.x, a4.x);
            a4.y = fmaf(w4.y, c4.y, a4.y);
            a4.z = fmaf(w4.z, c4.z, a4.z);
            a4.w = fmaf(w4.w, c4.w, a4.w);
        }
        t1s[b * 32 + row] = fmaxf(a4.x + a4.y + a4.z + a4.w + wh1_b[row], 0.f);
    } else if (tid < 192) {     // residual head L1: 16 rows x 4 batches
        const int t = tid - 128;
        const int row = t >> 2, b = t & 3;
        const float4* wv = (const float4*)rh1_w + row * 512;
        const float4* cv = (const float4*)(comb + b * CS);
        float4 a4 = make_float4(0.f, 0.f, 0.f, 0.f);
        for (int k = 0; k < 512; ++k) {
            const float4 w4 = wv[k], c4 = cv[k];
            a4.x = fmaf(w4.x, c4.x, a4.x);
            a4.y = fmaf(w4.y, c4.y, a4.y);
            a4.z = fmaf(w4.z, c4.z, a4.z);
            a4.w = fmaf(w4.w, c4.w, a4.w);
        }
        rrs[b * 16 + row] = tanhf(a4.x + a4.y + a4.z + a4.w + rh1_b[row]);
    }
    __syncthreads();

    if (tid < GB2) {
        const int b = tid;
        float t2[16];
#pragma unroll
        for (int o = 0; o < 16; ++o) {
            float s = wh2_b[o];
#pragma unroll
            for (int k = 0; k < 32; ++k) s = fmaf(t1s[b * 32 + k], wh2_w[o * 32 + k], s);
            t2[o] = fmaxf(s, 0.f);
        }
        float raw[5]; float mx = -3.0e38f;
#pragma unroll
        for (int o = 0; o < 5; ++o) {
            float s = wh3_b[o];
#pragma unroll
            for (int k = 0; k < 16; ++k) s = fmaf(t2[k], wh3_w[o * 16 + k], s);
            raw[o] = s; mx = fmaxf(mx, s);
        }
        float se = 0.f;
#pragma unroll
        for (int o = 0; o < 5; ++o) { raw[o] = __expf(raw[o] - mx); se += raw[o]; }
        const float inv = 1.f / se;
        float wp = 0.f;
#pragma unroll
        for (int o = 0; o < 5; ++o) {
            const float wt = raw[o] * inv;
            out[BATCH + (size_t)(b0 + b) * 5 + o] = wt;
            wp = fmaf(wt, base_preds[(size_t)(b0 + b) * 5 + o], wp);
        }
        float rr = rh2_b[0];
#pragma unroll
        for (int k = 0; k < 16; ++k) rr = fmaf(rrs[b * 16 + k], rh2_w[k], rr);
        out[b0 + b] = fmaxf(wp + rr * 0.05f, 0.05f);
    }
}

// ---------------------------------------------------------------------------
extern "C" void kernel_launch(void* const* d_in, const int* in_sizes, int n_in,
                              void* d_out, int out_size) {
    const float* node_feats = (const float*)d_in[0];
    const float* adj        = (const float*)d_in[1];
    const float* context    = (const float*)d_in[2];
    const float* base_preds = (const float*)d_in[3];
    const float* W1    = (const float*)d_in[4];
    const float* a1    = (const float*)d_in[5];
    const float* W2    = (const float*)d_in[6];
    const float* a2    = (const float*)d_in[7];
    const float* wh1_w = (const float*)d_in[8];
    const float* wh1_b = (const float*)d_in[9];
    const float* wh2_w = (const float*)d_in[10];
    const float* wh2_b = (const float*)d_in[11];
    const float* wh3_w = (const float*)d_in[12];
    const float* wh3_b = (const float*)d_in[13];
    const float* rh1_w = (const float*)d_in[14];
    const float* rh1_b = (const float*)d_in[15];
    const float* rh2_w = (const float*)d_in[16];
    const float* rh2_b = (const float*)d_in[17];
    float* out = (float*)d_out;

    float *h1p, *x2p, *h2p;
    __half *w1h, *w2h;
    cudaGetSymbolAddress((void**)&h1p, g_h1);
    cudaGetSymbolAddress((void**)&x2p, g_x2);
    cudaGetSymbolAddress((void**)&h2p, g_h2);
    cudaGetSymbolAddress((void**)&w1h, g_w1h);
    cudaGetSymbolAddress((void**)&w2h, g_w2h);

    const int smem1 = 15401 * 4;
    const int smem2 = 16381 * 4;
    cudaFuncSetAttribute(gemm_mma, cudaFuncAttributeMaxDynamicSharedMemorySize, G_SMEM);
    cudaFuncSetAttribute(attn1_kernel, cudaFuncAttributeMaxDynamicSharedMemorySize, smem1);
    cudaFuncSetAttribute(attn2_heads_kernel, cudaFuncAttributeMaxDynamicSharedMemorySize, smem2);

    // pre-convert weights to fp16
    convw_kernel<<<(HID * FEATD + 255) / 256, 256>>>(W1, w1h, HID * FEATD);
    convw_kernel<<<(HID * HID + 255) / 256, 256>>>(W2, w2h, HID * HID);

    // h1 = node_feats @ W1^T      (HMMA fp16, 2-term A-split)
    gemm_mma<<<dim3(MROWS / 128, 2), 256, G_SMEM>>>(node_feats, w1h, h1p, FEATD);
    // x2 = relu(alpha1 @ h1)
    attn1_kernel<<<BATCH / GB, 256, smem1>>>(h1p, adj, a1, x2p);
    // h2 = x2 @ W2^T
    gemm_mma<<<dim3(MROWS / 128, 2), 256, G_SMEM>>>(x2p, w2h, h2p, HID);
    // layer-2 attention + heads + outputs
    attn2_heads_kernel<<<BATCH / GB2, 256, smem2>>>(h2p, adj, a2, context, base_preds,
                                                    wh1_w, wh1_b, wh2_w, wh2_b,
                                                    wh3_w, wh3_b, rh1_w, rh1_b,
                                                    rh2_w, rh2_b, out);
}

// round 12
// speedup vs baseline: 1.7758x; 1.1393x over previous
#include <cuda_runtime.h>
#include <cuda_fp16.h>
#include <cstdint>
#include <cstddef>

#define BATCH 16384
#define NND   7
#define FEATD 512
#define HID   256
#define CTXD  256
#define MROWS (BATCH * NND)        // 114688
#define GB    8
#define GB2   4
#define CS    2052

// fp16 GEMM smem staging: all rows stride 80B (5x16B) -> conflict-free LDSM
#define AH2_OFF 0                  // A-hi 128 x 80
#define AL2_OFF 10240              // A-lo 128 x 80
#define B2_OFF  20480              // B    256 x 80
#define STAGE2  40960
#define G2_SMEM (2 * STAGE2)

// ---------------- scratch ---------------------------------------------------
__device__ float  g_h1[(size_t)MROWS * HID];
__device__ float  g_h2[(size_t)MROWS * HID];
__device__ __half g_a1hi[(size_t)MROWS * FEATD];
__device__ __half g_a1lo[(size_t)MROWS * FEATD];
__device__ __half g_x2hi[(size_t)MROWS * HID];
__device__ __half g_x2lo[(size_t)MROWS * HID];
__device__ __half g_w1h[HID * FEATD];
__device__ __half g_w2h[HID * HID];

// ---------------- helpers ---------------------------------------------------
__device__ __forceinline__ uint32_t smem_u32(const void* p) {
    uint32_t a;
    asm("{ .reg .u64 t; cvta.to.shared.u64 t, %1; cvt.u32.u64 %0, t; }" : "=r"(a) : "l"(p));
    return a;
}
__device__ __forceinline__ void ldsm4(uint32_t* r, uint32_t addr) {
    asm volatile("ldmatrix.sync.aligned.m8n8.x4.shared.b16 {%0,%1,%2,%3}, [%4];"
                 : "=r"(r[0]), "=r"(r[1]), "=r"(r[2]), "=r"(r[3]) : "r"(addr));
}
__device__ __forceinline__ void mma_f16(float* c, const uint32_t* a, const uint32_t* b) {
    asm volatile(
        "mma.sync.aligned.m16n8k16.row.col.f32.f16.f16.f32 "
        "{%0,%1,%2,%3}, {%4,%5,%6,%7}, {%8,%9}, {%0,%1,%2,%3};"
        : "+f"(c[0]), "+f"(c[1]), "+f"(c[2]), "+f"(c[3])
        : "r"(a[0]), "r"(a[1]), "r"(a[2]), "r"(a[3]), "r"(b[0]), "r"(b[1]));
}
__device__ __forceinline__ void cvt_hilo(float4 v, uint32_t& h0, uint32_t& h1,
                                         uint32_t& l0, uint32_t& l1) {
    __half2 ha = __floats2half2_rn(v.x, v.y);
    __half2 hb = __floats2half2_rn(v.z, v.w);
    float2 fa = __half22float2(ha);
    float2 fb = __half22float2(hb);
    __half2 la = __floats2half2_rn(v.x - fa.x, v.y - fa.y);
    __half2 lb = __floats2half2_rn(v.z - fb.x, v.w - fb.y);
    h0 = *(uint32_t*)&ha; h1 = *(uint32_t*)&hb;
    l0 = *(uint32_t*)&la; l1 = *(uint32_t*)&lb;
}
__device__ __forceinline__ void cpasync16(uint32_t saddr, const void* g) {
    asm volatile("cp.async.cg.shared.global [%0], [%1], 16;" :: "r"(saddr), "l"(g) : "memory");
}
__device__ __forceinline__ void cpasync_commit() {
    asm volatile("cp.async.commit_group;" ::: "memory");
}
__device__ __forceinline__ void cpasync_wait0() {
    asm volatile("cp.async.wait_group 0;" ::: "memory");
}

// ---------------------------------------------------------------------------
// convw: fp32 -> fp16 ; convA: fp32 -> fp16 hi + fp16 lo (vectorized)
// ---------------------------------------------------------------------------
__global__ void convw_kernel(const float* __restrict__ W, __half* __restrict__ H, int n) {
    int i = blockIdx.x * 256 + threadIdx.x;
    if (i < n) H[i] = __float2half_rn(W[i]);
}
__global__ void convA_kernel(const float* __restrict__ A, __half* __restrict__ Hi,
                             __half* __restrict__ Lo, int n4) {
    int i = blockIdx.x * 256 + threadIdx.x;
    if (i < n4) {
        float4 v = ((const float4*)A)[i];
        uint32_t h0, h1, l0, l1;
        cvt_hilo(v, h0, h1, l0, l1);
        ((uint2*)Hi)[i] = make_uint2(h0, h1);
        ((uint2*)Lo)[i] = make_uint2(l0, l1);
    }
}

// ---------------------------------------------------------------------------
// Pure-fp16 HMMA GEMM: C[m,n] = sum_k (Ahi+Alo)[m,k]*B[n,k], 2-term.
// CTA tile 128x256 (full N), BK=32, 256 threads = 8 warps (4m x 2n),
// warp tile 32x128. cp.async double-buffered staging, zero in-kernel convert.
// ---------------------------------------------------------------------------
__global__ void __launch_bounds__(256, 1)
gemm_f16(const __half* __restrict__ Ahi, const __half* __restrict__ Alo,
         const __half* __restrict__ Bh, float* __restrict__ C, int K) {
    extern __shared__ char smem[];
    const uint32_t sb = smem_u32(smem);
    const int tid  = threadIdx.x;
    const int lane = tid & 31;
    const int wid  = tid >> 5;
    const int wm   = wid & 3;          // 32-row block
    const int wn   = wid >> 2;         // 128-col block
    const int m0   = blockIdx.x * 128;
    const int nk   = K >> 5;

    // cp.async staging maps (16B units)
    const int ar0 = tid >> 1;          // A: 2 units/thread -> unit = tid*2+q
    const int ac0 = (tid & 1) * 2;     //   row = unit>>2, ch = unit&3
    const int br0 = tid;               // B: 4 units/thread -> row = tid? no:
    // B: 1024 units, thread covers units tid*4..tid*4+3 -> row=tid, ch=q
    const __half* AhiG = Ahi + (size_t)(m0 + ar0) * K + ac0 * 8;
    const __half* AloG = Alo + (size_t)(m0 + ar0) * K + ac0 * 8;
    const __half* BG   = Bh  + (size_t)br0 * K;
    const uint32_t sAh = sb + AH2_OFF + ar0 * 80 + ac0 * 16;
    const uint32_t sAl = sb + AL2_OFF + ar0 * 80 + ac0 * 16;
    const uint32_t sB  = sb + B2_OFF  + br0 * 80;

    // LDSM bases
    const uint32_t a_off = AH2_OFF + (uint32_t)(wm * 32 + (lane & 15)) * 80 + ((lane >> 4) << 4);
    const uint32_t b_off = B2_OFF + (uint32_t)(wn * 128 + (lane & 7) + ((lane >> 4) << 3)) * 80
                         + ((lane & 8) << 1);

    float acc[2][16][4];
#pragma unroll
    for (int i = 0; i < 2; ++i)
#pragma unroll
        for (int j = 0; j < 16; ++j)
#pragma unroll
            for (int q = 0; q < 4; ++q) acc[i][j][q] = 0.f;

    // prologue: stage chunk 0
    {
#pragma unroll
        for (int q = 0; q < 2; ++q) {
            cpasync16(sAh + q * 16, AhiG + q * 8);
            cpasync16(sAl + q * 16, AloG + q * 8);
        }
#pragma unroll
        for (int q = 0; q < 4; ++q)
            cpasync16(sB + q * 16, BG + q * 8);
        cpasync_commit();
        cpasync_wait0();
    }
    __syncthreads();

    for (int kt = 0; kt < nk; ++kt) {
        const uint32_t bufo = (kt & 1) * STAGE2;
        const bool more = (kt + 1 < nk);
        if (more) {
            const uint32_t nb = ((kt + 1) & 1) * STAGE2;
#pragma unroll
            for (int q = 0; q < 2; ++q) {
                cpasync16(sAh + nb + q * 16, AhiG + (kt + 1) * 32 + q * 8);
                cpasync16(sAl + nb + q * 16, AloG + (kt + 1) * 32 + q * 8);
            }
#pragma unroll
            for (int q = 0; q < 4; ++q)
                cpasync16(sB + nb + q * 16, BG + (kt + 1) * 32 + q * 8);
            cpasync_commit();
        }

        // compute BK=32 from current buffer
#pragma unroll
        for (int ks = 0; ks < 2; ++ks) {
            const uint32_t ab = sb + bufo + a_off + ks * 32;
            const uint32_t bb = sb + bufo + b_off + ks * 32;
            uint32_t ah[2][4], al[2][4], bh[8][4];
            ldsm4(ah[0], ab);
            ldsm4(ah[1], ab + 16 * 80);
            ldsm4(al[0], ab + (AL2_OFF - AH2_OFF));
            ldsm4(al[1], ab + (AL2_OFF - AH2_OFF) + 16 * 80);
#pragma unroll
            for (int p = 0; p < 8; ++p) ldsm4(bh[p], bb + p * (16 * 80));
            // term 1: Ah * B
#pragma unroll
            for (int p = 0; p < 8; ++p)
#pragma unroll
                for (int mi = 0; mi < 2; ++mi) {
                    mma_f16(acc[mi][2 * p],     ah[mi], bh[p]);
                    mma_f16(acc[mi][2 * p + 1], ah[mi], bh[p] + 2);
                }
            // term 2: Al * B
#pragma unroll
            for (int p = 0; p < 8; ++p)
#pragma unroll
                for (int mi = 0; mi < 2; ++mi) {
                    mma_f16(acc[mi][2 * p],     al[mi], bh[p]);
                    mma_f16(acc[mi][2 * p + 1], al[mi], bh[p] + 2);
                }
        }

        if (more) {
            cpasync_wait0();
            __syncthreads();
        }
    }

    // epilogue
    const int g  = lane >> 2;
    const int cq = (lane & 3) * 2;
#pragma unroll
    for (int mi = 0; mi < 2; ++mi) {
        const int row0 = m0 + wm * 32 + mi * 16 + g;
        float* C0 = C + (size_t)row0 * 256 + wn * 128;
        float* C1 = C0 + (size_t)8 * 256;
#pragma unroll
        for (int ni = 0; ni < 16; ++ni) {
            *(float2*)(C0 + ni * 8 + cq) = make_float2(acc[mi][ni][0], acc[mi][ni][1]);
            *(float2*)(C1 + ni * 8 + cq) = make_float2(acc[mi][ni][2], acc[mi][ni][3]);
        }
    }
}

// ---------------------------------------------------------------------------
// attn1: x2 = relu(alpha1 @ h1), emitted directly as fp16 hi/lo.
// ---------------------------------------------------------------------------
__global__ void __launch_bounds__(256)
attn1_kernel(const float* __restrict__ h1, const float* __restrict__ adj,
             const float* __restrict__ a1, __half* __restrict__ x2hi,
             __half* __restrict__ x2lo) {
    extern __shared__ float sm[];
    float* hs   = sm;           // 14336
    float* av   = sm + 14336;   // 512
    float* sadj = sm + 14848;   // 49
    float* ssi  = sm + 14897;   // 56
    float* ssj  = sm + 14953;   // 56
    float* sal  = sm + 15009;   // 392
    const int tid = threadIdx.x;
    const int w = tid >> 5, lane = tid & 31;
    const size_t base = (size_t)blockIdx.x * (GB * NND * HID);

    {
        const float4* src = (const float4*)(h1 + base);
        float4* dst = (float4*)hs;
        for (int i = tid; i < GB * NND * HID / 4; i += 256) dst[i] = src[i];
        if (tid < 128) ((float4*)av)[tid] = ((const float4*)a1)[tid];
        if (tid < 49) sadj[tid] = adj[tid];
    }
    __syncthreads();

    {
#pragma unroll
        for (int ri = 0; ri < 7; ++ri) {
            const int r = w * 7 + ri;
            const float* hr = hs + r * HID;
            float si = 0.f, sj = 0.f;
#pragma unroll
            for (int k = lane; k < HID; k += 32) {
                const float hv = hr[k];
                si = fmaf(hv, av[k], si);
                sj = fmaf(hv, av[HID + k], sj);
            }
#pragma unroll
            for (int off = 16; off > 0; off >>= 1) {
                si += __shfl_xor_sync(0xffffffffu, si, off);
                sj += __shfl_xor_sync(0xffffffffu, sj, off);
            }
            if (lane == 0) { ssi[r] = si; ssj[r] = sj; }
        }
    }
    __syncthreads();

    if (tid < GB * NND) {
        const int b = tid / 7, i = tid - b * 7;
        float e[7]; float mx = -3.0e38f;
#pragma unroll
        for (int j = 0; j < 7; ++j) {
            float v = ssi[b * 7 + i] + ssj[b * 7 + j];
            v = (v > 0.f) ? v : 0.2f * v;
            if (sadj[i * 7 + j] == 0.f) v = -3.0e38f;
            e[j] = v; mx = fmaxf(mx, v);
        }
        float s = 0.f;
#pragma unroll
        for (int j = 0; j < 7; ++j) {
            const float ex = (e[j] < -1.0e38f) ? 0.f : __expf(e[j] - mx);
            e[j] = ex; s += ex;
        }
        const float inv = 1.f / s;
#pragma unroll
        for (int j = 0; j < 7; ++j) sal[tid * 7 + j] = e[j] * inv;
    }
    __syncthreads();

    {
        const float* hb = hs + w * 7 * HID;
#pragma unroll
        for (int ri = 0; ri < 7; ++ri) {
            const int r = w * 7 + ri;
            const float* alr = sal + r * 7;
            float a0 = alr[0], a1v = alr[1], a2v = alr[2], a3 = alr[3],
                  a4 = alr[4], a5 = alr[5], a6 = alr[6];
#pragma unroll
            for (int d4 = lane; d4 < 64; d4 += 32) {
                const float4* p0 = (const float4*)(hb) + d4;
                float4 h0 = p0[0],  h1v = p0[64],  h2 = p0[128], h3 = p0[192],
                       h4 = p0[256], h5 = p0[320], h6 = p0[384];
                float4 o;
                o.x = a0*h0.x + a1v*h1v.x + a2v*h2.x + a3*h3.x + a4*h4.x + a5*h5.x + a6*h6.x;
                o.y = a0*h0.y + a1v*h1v.y + a2v*h2.y + a3*h3.y + a4*h4.y + a5*h5.y + a6*h6.y;
                o.z = a0*h0.z + a1v*h1v.z + a2v*h2.z + a3*h3.z + a4*h4.z + a5*h5.z + a6*h6.z;
                o.w = a0*h0.w + a1v*h1v.w + a2v*h2.w + a3*h3.w + a4*h4.w + a5*h5.w + a6*h6.w;
                o.x = fmaxf(o.x, 0.f); o.y = fmaxf(o.y, 0.f);
                o.z = fmaxf(o.z, 0.f); o.w = fmaxf(o.w, 0.f);
                uint32_t h0p, h1p, l0p, l1p;
                cvt_hilo(o, h0p, h1p, l0p, l1p);
                const size_t off = base + r * HID + d4 * 4;
                *(uint2*)(x2hi + off) = make_uint2(h0p, h1p);
                *(uint2*)(x2lo + off) = make_uint2(l0p, l1p);
            }
        }
    }
}

// ---------------------------------------------------------------------------
// attn2 + heads (unchanged from R8 best).
// out = [pred(B) | weights(B*5) | attn2(B*49)]
// ---------------------------------------------------------------------------
__global__ void __launch_bounds__(256)
attn2_heads_kernel(const float* __restrict__ h2, const float* __restrict__ adj,
                   const float* __restrict__ a2, const float* __restrict__ context,
                   const float* __restrict__ base_preds,
                   const float* __restrict__ wh1_w, const float* __restrict__ wh1_b,
                   const float* __restrict__ wh2_w, const float* __restrict__ wh2_b,
                   const float* __restrict__ wh3_w, const float* __restrict__ wh3_b,
                   const float* __restrict__ rh1_w, const float* __restrict__ rh1_b,
                   const float* __restrict__ rh2_w, const float* __restrict__ rh2_b,
                   float* __restrict__ out) {
    extern __shared__ float sm[];
    float* hs   = sm;            // 7168
    float* comb = sm + 7168;     // 8208
    float* av   = sm + 15376;    // 512
    float* sadj = sm + 15888;    // 49
    float* ssi  = sm + 15937;    // 28
    float* ssj  = sm + 15965;    // 28
    float* sal  = sm + 15993;    // 196
    float* t1s  = sm + 16189;    // 128
    float* rrs  = sm + 16317;    // 64
    const int tid = threadIdx.x;
    const int w = tid >> 5, lane = tid & 31;
    const int b0 = blockIdx.x * GB2;
    const size_t base = (size_t)blockIdx.x * (GB2 * NND * HID);

    {
        const float4* src = (const float4*)(h2 + base);
        float4* dst = (float4*)hs;
        for (int i = tid; i < GB2 * NND * HID / 4; i += 256) dst[i] = src[i];
        if (tid < 128) ((float4*)av)[tid] = ((const float4*)a2)[tid];
        if (tid < 49) sadj[tid] = adj[tid];
    }
    __syncthreads();

    {
        for (int r = w; r < GB2 * NND; r += 8) {
            const float* hr = hs + r * HID;
            float si = 0.f, sj = 0.f;
#pragma unroll
            for (int k = lane; k < HID; k += 32) {
                const float hv = hr[k];
                si = fmaf(hv, av[k], si);
                sj = fmaf(hv, av[HID + k], sj);
            }
#pragma unroll
            for (int off = 16; off > 0; off >>= 1) {
                si += __shfl_xor_sync(0xffffffffu, si, off);
                sj += __shfl_xor_sync(0xffffffffu, sj, off);
            }
            if (lane == 0) { ssi[r] = si; ssj[r] = sj; }
        }
    }
    __syncthreads();

    if (tid < GB2 * NND) {
        const int b = tid / 7, i = tid - b * 7;
        float e[7]; float mx = -3.0e38f;
#pragma unroll
        for (int j = 0; j < 7; ++j) {
            float v = ssi[b * 7 + i] + ssj[b * 7 + j];
            v = (v > 0.f) ? v : 0.2f * v;
            if (sadj[i * 7 + j] == 0.f) v = -3.0e38f;
            e[j] = v; mx = fmaxf(mx, v);
        }
        float s = 0.f;
#pragma unroll
        for (int j = 0; j < 7; ++j) {
            const float ex = (e[j] < -1.0e38f) ? 0.f : __expf(e[j] - mx);
            e[j] = ex; s += ex;
        }
        const float inv = 1.f / s;
        float* oa = out + (size_t)6 * BATCH + (size_t)(b0 + b) * 49 + i * 7;
#pragma unroll
        for (int j = 0; j < 7; ++j) {
            const float al = e[j] * inv;
            sal[tid * 7 + j] = al;
            oa[j] = al;
        }
    }
    __syncthreads();

    for (int r = w; r < GB2 * NND; r += 8) {
        const int b = r / 7;
        const float* hb = hs + b * 7 * HID;
        const float* alr = sal + r * 7;
        float a0 = alr[0], a1v = alr[1], a2v = alr[2], a3 = alr[3],
              a4 = alr[4], a5 = alr[5], a6 = alr[6];
        const int rem = r - b * 7;
#pragma unroll
        for (int d4 = lane; d4 < 64; d4 += 32) {
            const float4* p0 = (const float4*)(hb) + d4;
            float4 h0 = p0[0],  h1v = p0[64],  h2 = p0[128], h3 = p0[192],
                   h4 = p0[256], h5 = p0[320], h6 = p0[384];
            float4 o;
            o.x = a0*h0.x + a1v*h1v.x + a2v*h2.x + a3*h3.x + a4*h4.x + a5*h5.x + a6*h6.x;
            o.y = a0*h0.y + a1v*h1v.y + a2v*h2.y + a3*h3.y + a4*h4.y + a5*h5.y + a6*h6.y;
            o.z = a0*h0.z + a1v*h1v.z + a2v*h2.z + a3*h3.z + a4*h4.z + a5*h5.z + a6*h6.z;
            o.w = a0*h0.w + a1v*h1v.w + a2v*h2.w + a3*h3.w + a4*h4.w + a5*h5.w + a6*h6.w;
            o.x = fmaxf(o.x, 0.f); o.y = fmaxf(o.y, 0.f);
            o.z = fmaxf(o.z, 0.f); o.w = fmaxf(o.w, 0.f);
            *(float4*)(comb + b * CS + rem * HID + d4 * 4) = o;
        }
    }
    for (int idx = tid; idx < GB2 * CTXD; idx += 256) {
        const int b = idx >> 8, c = idx & 255;
        comb[b * CS + NND * HID + c] = context[(size_t)(b0 + b) * CTXD + c];
    }
    __syncthreads();

    if (tid < 128) {
        const int row = tid >> 2, b = tid & 3;
        const float4* wv = (const float4*)wh1_w + row * 512;
        const float4* cv = (const float4*)(comb + b * CS);
        float4 a4 = make_float4(0.f, 0.f, 0.f, 0.f);
        for (int k = 0; k < 512; ++k) {
            const float4 w4 = wv[k], c4 = cv[k];
            a4.x = fmaf(w4.x, c4.x, a4.x);
            a4.y = fmaf(w4.y, c4.y, a4.y);
            a4.z = fmaf(w4.z, c4.z, a4.z);
            a4.w = fmaf(w4.w, c4.w, a4.w);
        }
        t1s[b * 32 + row] = fmaxf(a4.x + a4.y + a4.z + a4.w + wh1_b[row], 0.f);
    } else if (tid < 192) {
        const int t = tid - 128;
        const int row = t >> 2, b = t & 3;
        const float4* wv = (const float4*)rh1_w + row * 512;
        const float4* cv = (const float4*)(comb + b * CS);
        float4 a4 = make_float4(0.f, 0.f, 0.f, 0.f);
        for (int k = 0; k < 512; ++k) {
            const float4 w4 = wv[k], c4 = cv[k];
            a4.x = fmaf(w4.x, c4.x, a4.x);
            a4.y = fmaf(w4.y, c4.y, a4.y);
            a4.z = fmaf(w4.z, c4.z, a4.z);
            a4.w = fmaf(w4.w, c4.w, a4.w);
        }
        rrs[b * 16 + row] = tanhf(a4.x + a4.y + a4.z + a4.w + rh1_b[row]);
    }
    __syncthreads();

    if (tid < GB2) {
        const int b = tid;
        float t2[16];
#pragma unroll
        for (int o = 0; o < 16; ++o) {
            float s = wh2_b[o];
#pragma unroll
            for (int k = 0; k < 32; ++k) s = fmaf(t1s[b * 32 + k], wh2_w[o * 32 + k], s);
            t2[o] = fmaxf(s, 0.f);
        }
        float raw[5]; float mx = -3.0e38f;
#pragma unroll
        for (int o = 0; o < 5; ++o) {
            float s = wh3_b[o];
#pragma unroll
            for (int k = 0; k < 16; ++k) s = fmaf(t2[k], wh3_w[o * 16 + k], s);
            raw[o] = s; mx = fmaxf(mx, s);
        }
        float se = 0.f;
#pragma unroll
        for (int o = 0; o < 5; ++o) { raw[o] = __expf(raw[o] - mx); se += raw[o]; }
        const float inv = 1.f / se;
        float wp = 0.f;
#pragma unroll
        for (int o = 0; o < 5; ++o) {
            const float wt = raw[o] * inv;
            out[BATCH + (size_t)(b0 + b) * 5 + o] = wt;
            wp = fmaf(wt, base_preds[(size_t)(b0 + b) * 5 + o], wp);
        }
        float rr = rh2_b[0];
#pragma unroll
        for (int k = 0; k < 16; ++k) rr = fmaf(rrs[b * 16 + k], rh2_w[k], rr);
        out[b0 + b] = fmaxf(wp + rr * 0.05f, 0.05f);
    }
}

// ---------------------------------------------------------------------------
extern "C" void kernel_launch(void* const* d_in, const int* in_sizes, int n_in,
                              void* d_out, int out_size) {
    const float* node_feats = (const float*)d_in[0];
    const float* adj        = (const float*)d_in[1];
    const float* context    = (const float*)d_in[2];
    const float* base_preds = (const float*)d_in[3];
    const float* W1    = (const float*)d_in[4];
    const float* a1    = (const float*)d_in[5];
    const float* W2    = (const float*)d_in[6];
    const float* a2    = (const float*)d_in[7];
    const float* wh1_w = (const float*)d_in[8];
    const float* wh1_b = (const float*)d_in[9];
    const float* wh2_w = (const float*)d_in[10];
    const float* wh2_b = (const float*)d_in[11];
    const float* wh3_w = (const float*)d_in[12];
    const float* wh3_b = (const float*)d_in[13];
    const float* rh1_w = (const float*)d_in[14];
    const float* rh1_b = (const float*)d_in[15];
    const float* rh2_w = (const float*)d_in[16];
    const float* rh2_b = (const float*)d_in[17];
    float* out = (float*)d_out;

    float *h1p, *h2p;
    __half *a1h, *a1l, *x2h, *x2l, *w1h, *w2h;
    cudaGetSymbolAddress((void**)&h1p, g_h1);
    cudaGetSymbolAddress((void**)&h2p, g_h2);
    cudaGetSymbolAddress((void**)&a1h, g_a1hi);
    cudaGetSymbolAddress((void**)&a1l, g_a1lo);
    cudaGetSymbolAddress((void**)&x2h, g_x2hi);
    cudaGetSymbolAddress((void**)&x2l, g_x2lo);
    cudaGetSymbolAddress((void**)&w1h, g_w1h);
    cudaGetSymbolAddress((void**)&w2h, g_w2h);

    const int smem1 = 15401 * 4;
    const int smem2 = 16381 * 4;
    cudaFuncSetAttribute(gemm_f16, cudaFuncAttributeMaxDynamicSharedMemorySize, G2_SMEM);
    cudaFuncSetAttribute(attn1_kernel, cudaFuncAttributeMaxDynamicSharedMemorySize, smem1);
    cudaFuncSetAttribute(attn2_heads_kernel, cudaFuncAttributeMaxDynamicSharedMemorySize, smem2);

    // pre-convert weights (fp16) and A (fp16 hi/lo)
    convw_kernel<<<(HID * FEATD + 255) / 256, 256>>>(W1, w1h, HID * FEATD);
    convw_kernel<<<(HID * HID + 255) / 256, 256>>>(W2, w2h, HID * HID);
    convA_kernel<<<(MROWS * FEATD / 4 + 255) / 256, 256>>>(node_feats, a1h, a1l,
                                                           MROWS * FEATD / 4);

    // h1 = (a1hi + a1lo) @ W1^T   (pure fp16 HMMA, cp.async)
    gemm_f16<<<MROWS / 128, 256, G2_SMEM>>>(a1h, a1l, w1h, h1p, FEATD);
    // x2 (fp16 hi/lo) = relu(alpha1 @ h1)
    attn1_kernel<<<BATCH / GB, 256, smem1>>>(h1p, adj, a1, x2h, x2l);
    // h2 = (x2hi + x2lo) @ W2^T
    gemm_f16<<<MROWS / 128, 256, G2_SMEM>>>(x2h, x2l, w2h, h2p, HID);
    // layer-2 attention + heads + outputs
    attn2_heads_kernel<<<BATCH / GB2, 256, smem2>>>(h2p, adj, a2, context, base_preds,
                                                    wh1_w, wh1_b, wh2_w, wh2_b,
                                                    wh3_w, wh3_b, rh1_w, rh1_b,
                                                    rh2_w, rh2_b, out);
}

// round 13
// speedup vs baseline: 3.0405x; 1.7122x over previous
#include <cuda_runtime.h>
#include <cuda_fp16.h>
#include <cstdint>
#include <cstddef>

#define BATCH 16384
#define NND   7
#define FEATD 512
#define HID   256
#define CTXD  256
#define COMB  2048
#define MROWS (BATCH * NND)        // 114688
#define GB    8

// fp16 GEMM smem staging: all rows stride 80B (5x16B) -> conflict-free LDSM
#define AH2_OFF 0                  // A-hi 128 x 80
#define AL2_OFF 10240              // A-lo 128 x 80
#define B2_OFF  20480              // B    256 x 80
#define STAGE2  40960
#define G2_SMEM (2 * STAGE2)
// heads GEMM staging: B only 64 rows
#define HB_OFF  20480
#define STAGE3  25600
#define G3_SMEM (2 * STAGE3)

// ---------------- scratch ---------------------------------------------------
__device__ float  g_h1[(size_t)MROWS * HID];
__device__ float  g_h2[(size_t)MROWS * HID];
__device__ __half g_a1hi[(size_t)MROWS * FEATD];
__device__ __half g_a1lo[(size_t)MROWS * FEATD];
__device__ __half g_x2hi[(size_t)MROWS * HID];
__device__ __half g_x2lo[(size_t)MROWS * HID];
__device__ __half g_combhi[(size_t)BATCH * COMB];
__device__ __half g_comblo[(size_t)BATCH * COMB];
__device__ float  g_ht[(size_t)BATCH * 64];
__device__ __half g_w1h[HID * FEATD];
__device__ __half g_w2h[HID * HID];
__device__ __half g_hw[64 * COMB];

// ---------------- helpers ---------------------------------------------------
__device__ __forceinline__ uint32_t smem_u32(const void* p) {
    uint32_t a;
    asm("{ .reg .u64 t; cvta.to.shared.u64 t, %1; cvt.u32.u64 %0, t; }" : "=r"(a) : "l"(p));
    return a;
}
__device__ __forceinline__ void ldsm4(uint32_t* r, uint32_t addr) {
    asm volatile("ldmatrix.sync.aligned.m8n8.x4.shared.b16 {%0,%1,%2,%3}, [%4];"
                 : "=r"(r[0]), "=r"(r[1]), "=r"(r[2]), "=r"(r[3]) : "r"(addr));
}
__device__ __forceinline__ void mma_f16(float* c, const uint32_t* a, const uint32_t* b) {
    asm volatile(
        "mma.sync.aligned.m16n8k16.row.col.f32.f16.f16.f32 "
        "{%0,%1,%2,%3}, {%4,%5,%6,%7}, {%8,%9}, {%0,%1,%2,%3};"
        : "+f"(c[0]), "+f"(c[1]), "+f"(c[2]), "+f"(c[3])
        : "r"(a[0]), "r"(a[1]), "r"(a[2]), "r"(a[3]), "r"(b[0]), "r"(b[1]));
}
__device__ __forceinline__ void cvt_hilo(float4 v, uint32_t& h0, uint32_t& h1,
                                         uint32_t& l0, uint32_t& l1) {
    __half2 ha = __floats2half2_rn(v.x, v.y);
    __half2 hb = __floats2half2_rn(v.z, v.w);
    float2 fa = __half22float2(ha);
    float2 fb = __half22float2(hb);
    __half2 la = __floats2half2_rn(v.x - fa.x, v.y - fa.y);
    __half2 lb = __floats2half2_rn(v.z - fb.x, v.w - fb.y);
    h0 = *(uint32_t*)&ha; h1 = *(uint32_t*)&hb;
    l0 = *(uint32_t*)&la; l1 = *(uint32_t*)&lb;
}
__device__ __forceinline__ void cpasync16(uint32_t saddr, const void* g) {
    asm volatile("cp.async.cg.shared.global [%0], [%1], 16;" :: "r"(saddr), "l"(g) : "memory");
}
__device__ __forceinline__ void cpasync_commit() {
    asm volatile("cp.async.commit_group;" ::: "memory");
}
__device__ __forceinline__ void cpasync_wait0() {
    asm volatile("cp.async.wait_group 0;" ::: "memory");
}

// ---------------------------------------------------------------------------
// converters
// ---------------------------------------------------------------------------
__global__ void convw_kernel(const float* __restrict__ W, __half* __restrict__ H, int n) {
    int i = blockIdx.x * 256 + threadIdx.x;
    if (i < n) H[i] = __float2half_rn(W[i]);
}
__global__ void convhw_kernel(const float* __restrict__ wh1_w, const float* __restrict__ rh1_w,
                              __half* __restrict__ HW) {
    int i = blockIdx.x * 256 + threadIdx.x;
    if (i < 64 * COMB) {
        int row = i >> 11, k = i & (COMB - 1);
        float v = 0.f;
        if (row < 32) v = wh1_w[row * COMB + k];
        else if (row < 48) v = rh1_w[(row - 32) * COMB + k];
        HW[i] = __float2half_rn(v);
    }
}
__global__ void convA_kernel(const float* __restrict__ A, __half* __restrict__ Hi,
                             __half* __restrict__ Lo, int n4) {
    int i = blockIdx.x * 256 + threadIdx.x;
    if (i < n4) {
        float4 v = ((const float4*)A)[i];
        uint32_t h0, h1, l0, l1;
        cvt_hilo(v, h0, h1, l0, l1);
        ((uint2*)Hi)[i] = make_uint2(h0, h1);
        ((uint2*)Lo)[i] = make_uint2(l0, l1);
    }
}

// ---------------------------------------------------------------------------
// Pure-fp16 HMMA GEMM (N=256): C[m,n] = sum_k (Ahi+Alo)[m,k]*B[n,k], 2-term.
// CTA 128x256, BK=32, 256 threads = 8 warps (4m x 2n), warp tile 32x128.
// ---------------------------------------------------------------------------
__global__ void __launch_bounds__(256, 1)
gemm_f16(const __half* __restrict__ Ahi, const __half* __restrict__ Alo,
         const __half* __restrict__ Bh, float* __restrict__ C, int K) {
    extern __shared__ char smem[];
    const uint32_t sb = smem_u32(smem);
    const int tid  = threadIdx.x;
    const int lane = tid & 31;
    const int wid  = tid >> 5;
    const int wm   = wid & 3;
    const int wn   = wid >> 2;
    const int m0   = blockIdx.x * 128;
    const int nk   = K >> 5;

    const int ar0 = tid >> 1;
    const int ac0 = (tid & 1) * 2;
    const __half* AhiG = Ahi + (size_t)(m0 + ar0) * K + ac0 * 8;
    const __half* AloG = Alo + (size_t)(m0 + ar0) * K + ac0 * 8;
    const __half* BG   = Bh  + (size_t)tid * K;
    const uint32_t sAh = sb + AH2_OFF + ar0 * 80 + ac0 * 16;
    const uint32_t sAl = sb + AL2_OFF + ar0 * 80 + ac0 * 16;
    const uint32_t sB  = sb + B2_OFF  + tid * 80;

    const uint32_t a_off = AH2_OFF + (uint32_t)(wm * 32 + (lane & 15)) * 80 + ((lane >> 4) << 4);
    const uint32_t b_off = B2_OFF + (uint32_t)(wn * 128 + (lane & 7) + ((lane >> 4) << 3)) * 80
                         + ((lane & 8) << 1);

    float acc[2][16][4];
#pragma unroll
    for (int i = 0; i < 2; ++i)
#pragma unroll
        for (int j = 0; j < 16; ++j)
#pragma unroll
            for (int q = 0; q < 4; ++q) acc[i][j][q] = 0.f;

    {
#pragma unroll
        for (int q = 0; q < 2; ++q) {
            cpasync16(sAh + q * 16, AhiG + q * 8);
            cpasync16(sAl + q * 16, AloG + q * 8);
        }
#pragma unroll
        for (int q = 0; q < 4; ++q) cpasync16(sB + q * 16, BG + q * 8);
        cpasync_commit();
        cpasync_wait0();
    }
    __syncthreads();

    for (int kt = 0; kt < nk; ++kt) {
        const uint32_t bufo = (kt & 1) * STAGE2;
        const bool more = (kt + 1 < nk);
        if (more) {
            const uint32_t nb = ((kt + 1) & 1) * STAGE2;
#pragma unroll
            for (int q = 0; q < 2; ++q) {
                cpasync16(sAh + nb + q * 16, AhiG + (kt + 1) * 32 + q * 8);
                cpasync16(sAl + nb + q * 16, AloG + (kt + 1) * 32 + q * 8);
            }
#pragma unroll
            for (int q = 0; q < 4; ++q)
                cpasync16(sB + nb + q * 16, BG + (kt + 1) * 32 + q * 8);
            cpasync_commit();
        }

#pragma unroll
        for (int ks = 0; ks < 2; ++ks) {
            const uint32_t ab = sb + bufo + a_off + ks * 32;
            const uint32_t bb = sb + bufo + b_off + ks * 32;
            uint32_t ah[2][4], al[2][4], bh[8][4];
            ldsm4(ah[0], ab);
            ldsm4(ah[1], ab + 16 * 80);
            ldsm4(al[0], ab + (AL2_OFF - AH2_OFF));
            ldsm4(al[1], ab + (AL2_OFF - AH2_OFF) + 16 * 80);
#pragma unroll
            for (int p = 0; p < 8; ++p) ldsm4(bh[p], bb + p * (16 * 80));
#pragma unroll
            for (int p = 0; p < 8; ++p)
#pragma unroll
                for (int mi = 0; mi < 2; ++mi) {
                    mma_f16(acc[mi][2 * p],     ah[mi], bh[p]);
                    mma_f16(acc[mi][2 * p + 1], ah[mi], bh[p] + 2);
                }
#pragma unroll
            for (int p = 0; p < 8; ++p)
#pragma unroll
                for (int mi = 0; mi < 2; ++mi) {
                    mma_f16(acc[mi][2 * p],     al[mi], bh[p]);
                    mma_f16(acc[mi][2 * p + 1], al[mi], bh[p] + 2);
                }
        }

        if (more) {
            cpasync_wait0();
            __syncthreads();
        }
    }

    const int g  = lane >> 2;
    const int cq = (lane & 3) * 2;
#pragma unroll
    for (int mi = 0; mi < 2; ++mi) {
        const int row0 = m0 + wm * 32 + mi * 16 + g;
        float* C0 = C + (size_t)row0 * 256 + wn * 128;
        float* C1 = C0 + (size_t)8 * 256;
#pragma unroll
        for (int ni = 0; ni < 16; ++ni) {
            *(float2*)(C0 + ni * 8 + cq) = make_float2(acc[mi][ni][0], acc[mi][ni][1]);
            *(float2*)(C1 + ni * 8 + cq) = make_float2(acc[mi][ni][2], acc[mi][ni][3]);
        }
    }
}

// ---------------------------------------------------------------------------
// Heads GEMM (N=64): ht[b, n] = sum_k (Chi+Clo)[b,k] * HW[n,k], K=2048.
// CTA 128x64, 8 warps (4m x 2n), warp tile 32x32.
// ---------------------------------------------------------------------------
__global__ void __launch_bounds__(256, 1)
gemm_heads(const __half* __restrict__ Ahi, const __half* __restrict__ Alo,
           const __half* __restrict__ Bh, float* __restrict__ C) {
    extern __shared__ char smem[];
    const uint32_t sb = smem_u32(smem);
    const int tid  = threadIdx.x;
    const int lane = tid & 31;
    const int wid  = tid >> 5;
    const int wm   = wid & 3;
    const int wn   = wid >> 2;
    const int m0   = blockIdx.x * 128;
    const int nk   = COMB >> 5;   // 64

    const int ar0 = tid >> 1;
    const int ac0 = (tid & 1) * 2;
    const __half* AhiG = Ahi + (size_t)(m0 + ar0) * COMB + ac0 * 8;
    const __half* AloG = Alo + (size_t)(m0 + ar0) * COMB + ac0 * 8;
    const int brow = tid >> 2, bch = tid & 3;
    const __half* BG = Bh + (size_t)brow * COMB + bch * 8;
    const uint32_t sAh = sb + AH2_OFF + ar0 * 80 + ac0 * 16;
    const uint32_t sAl = sb + AL2_OFF + ar0 * 80 + ac0 * 16;
    const uint32_t sB  = sb + HB_OFF + brow * 80 + bch * 16;

    const uint32_t a_off = AH2_OFF + (uint32_t)(wm * 32 + (lane & 15)) * 80 + ((lane >> 4) << 4);
    const uint32_t b_off = HB_OFF + (uint32_t)(wn * 32 + (lane & 7) + ((lane >> 4) << 3)) * 80
                         + ((lane & 8) << 1);

    float acc[2][4][4];
#pragma unroll
    for (int i = 0; i < 2; ++i)
#pragma unroll
        for (int j = 0; j < 4; ++j)
#pragma unroll
            for (int q = 0; q < 4; ++q) acc[i][j][q] = 0.f;

    {
#pragma unroll
        for (int q = 0; q < 2; ++q) {
            cpasync16(sAh + q * 16, AhiG + q * 8);
            cpasync16(sAl + q * 16, AloG + q * 8);
        }
        cpasync16(sB, BG);
        cpasync_commit();
        cpasync_wait0();
    }
    __syncthreads();

    for (int kt = 0; kt < nk; ++kt) {
        const uint32_t bufo = (kt & 1) * STAGE3;
        const bool more = (kt + 1 < nk);
        if (more) {
            const uint32_t nb = ((kt + 1) & 1) * STAGE3;
#pragma unroll
            for (int q = 0; q < 2; ++q) {
                cpasync16(sAh + nb + q * 16, AhiG + (kt + 1) * 32 + q * 8);
                cpasync16(sAl + nb + q * 16, AloG + (kt + 1) * 32 + q * 8);
            }
            cpasync16(sB + nb, BG + (kt + 1) * 32);
            cpasync_commit();
        }

#pragma unroll
        for (int ks = 0; ks < 2; ++ks) {
            const uint32_t ab = sb + bufo + a_off + ks * 32;
            const uint32_t bb = sb + bufo + b_off + ks * 32;
            uint32_t ah[2][4], al[2][4], bh[2][4];
            ldsm4(ah[0], ab);
            ldsm4(ah[1], ab + 16 * 80);
            ldsm4(al[0], ab + (AL2_OFF - AH2_OFF));
            ldsm4(al[1], ab + (AL2_OFF - AH2_OFF) + 16 * 80);
#pragma unroll
            for (int p = 0; p < 2; ++p) ldsm4(bh[p], bb + p * (16 * 80));
#pragma unroll
            for (int p = 0; p < 2; ++p)
#pragma unroll
                for (int mi = 0; mi < 2; ++mi) {
                    mma_f16(acc[mi][2 * p],     ah[mi], bh[p]);
                    mma_f16(acc[mi][2 * p + 1], ah[mi], bh[p] + 2);
                    mma_f16(acc[mi][2 * p],     al[mi], bh[p]);
                    mma_f16(acc[mi][2 * p + 1], al[mi], bh[p] + 2);
                }
        }

        if (more) {
            cpasync_wait0();
            __syncthreads();
        }
    }

    const int g  = lane >> 2;
    const int cq = (lane & 3) * 2;
#pragma unroll
    for (int mi = 0; mi < 2; ++mi) {
        const int row0 = m0 + wm * 32 + mi * 16 + g;
        float* C0 = C + (size_t)row0 * 64 + wn * 32;
        float* C1 = C0 + (size_t)8 * 64;
#pragma unroll
        for (int ni = 0; ni < 4; ++ni) {
            *(float2*)(C0 + ni * 8 + cq) = make_float2(acc[mi][ni][0], acc[mi][ni][1]);
            *(float2*)(C1 + ni * 8 + cq) = make_float2(acc[mi][ni][2], acc[mi][ni][3]);
        }
    }
}

// ---------------------------------------------------------------------------
// attn1: x2 = relu(alpha1 @ h1), emitted as fp16 hi/lo.
// ---------------------------------------------------------------------------
__global__ void __launch_bounds__(256)
attn1_kernel(const float* __restrict__ h1, const float* __restrict__ adj,
             const float* __restrict__ a1, __half* __restrict__ x2hi,
             __half* __restrict__ x2lo) {
    extern __shared__ float sm[];
    float* hs   = sm;           // 14336
    float* av   = sm + 14336;   // 512
    float* sadj = sm + 14848;   // 49
    float* ssi  = sm + 14897;   // 56
    float* ssj  = sm + 14953;   // 56
    float* sal  = sm + 15009;   // 392
    const int tid = threadIdx.x;
    const int w = tid >> 5, lane = tid & 31;
    const size_t base = (size_t)blockIdx.x * (GB * NND * HID);

    {
        const float4* src = (const float4*)(h1 + base);
        float4* dst = (float4*)hs;
        for (int i = tid; i < GB * NND * HID / 4; i += 256) dst[i] = src[i];
        if (tid < 128) ((float4*)av)[tid] = ((const float4*)a1)[tid];
        if (tid < 49) sadj[tid] = adj[tid];
    }
    __syncthreads();

    {
#pragma unroll
        for (int ri = 0; ri < 7; ++ri) {
            const int r = w * 7 + ri;
            const float* hr = hs + r * HID;
            float si = 0.f, sj = 0.f;
#pragma unroll
            for (int k = lane; k < HID; k += 32) {
                const float hv = hr[k];
                si = fmaf(hv, av[k], si);
                sj = fmaf(hv, av[HID + k], sj);
            }
#pragma unroll
            for (int off = 16; off > 0; off >>= 1) {
                si += __shfl_xor_sync(0xffffffffu, si, off);
                sj += __shfl_xor_sync(0xffffffffu, sj, off);
            }
            if (lane == 0) { ssi[r] = si; ssj[r] = sj; }
        }
    }
    __syncthreads();

    if (tid < GB * NND) {
        const int b = tid / 7, i = tid - b * 7;
        float e[7]; float mx = -3.0e38f;
#pragma unroll
        for (int j = 0; j < 7; ++j) {
            float v = ssi[b * 7 + i] + ssj[b * 7 + j];
            v = (v > 0.f) ? v : 0.2f * v;
            if (sadj[i * 7 + j] == 0.f) v = -3.0e38f;
            e[j] = v; mx = fmaxf(mx, v);
        }
        float s = 0.f;
#pragma unroll
        for (int j = 0; j < 7; ++j) {
            const float ex = (e[j] < -1.0e38f) ? 0.f : __expf(e[j] - mx);
            e[j] = ex; s += ex;
        }
        const float inv = 1.f / s;
#pragma unroll
        for (int j = 0; j < 7; ++j) sal[tid * 7 + j] = e[j] * inv;
    }
    __syncthreads();

    {
        const float* hb = hs + w * 7 * HID;
#pragma unroll
        for (int ri = 0; ri < 7; ++ri) {
            const int r = w * 7 + ri;
            const float* alr = sal + r * 7;
            float a0 = alr[0], a1v = alr[1], a2v = alr[2], a3 = alr[3],
                  a4 = alr[4], a5 = alr[5], a6 = alr[6];
#pragma unroll
            for (int d4 = lane; d4 < 64; d4 += 32) {
                const float4* p0 = (const float4*)(hb) + d4;
                float4 h0 = p0[0],  h1v = p0[64],  h2 = p0[128], h3 = p0[192],
                       h4 = p0[256], h5 = p0[320], h6 = p0[384];
                float4 o;
                o.x = a0*h0.x + a1v*h1v.x + a2v*h2.x + a3*h3.x + a4*h4.x + a5*h5.x + a6*h6.x;
                o.y = a0*h0.y + a1v*h1v.y + a2v*h2.y + a3*h3.y + a4*h4.y + a5*h5.y + a6*h6.y;
                o.z = a0*h0.z + a1v*h1v.z + a2v*h2.z + a3*h3.z + a4*h4.z + a5*h5.z + a6*h6.z;
                o.w = a0*h0.w + a1v*h1v.w + a2v*h2.w + a3*h3.w + a4*h4.w + a5*h5.w + a6*h6.w;
                o.x = fmaxf(o.x, 0.f); o.y = fmaxf(o.y, 0.f);
                o.z = fmaxf(o.z, 0.f); o.w = fmaxf(o.w, 0.f);
                uint32_t h0p, h1p, l0p, l1p;
                cvt_hilo(o, h0p, h1p, l0p, l1p);
                const size_t off = base + r * HID + d4 * 4;
                *(uint2*)(x2hi + off) = make_uint2(h0p, h1p);
                *(uint2*)(x2lo + off) = make_uint2(l0p, l1p);
            }
        }
    }
}

// ---------------------------------------------------------------------------
// attn2: softmax (writes attn2 output) + aggregation -> combined (fp16 hi/lo)
// + context append. NO heads here. 8 batches / block.
// ---------------------------------------------------------------------------
__global__ void __launch_bounds__(256)
attn2_kernel(const float* __restrict__ h2, const float* __restrict__ adj,
             const float* __restrict__ a2, const float* __restrict__ context,
             __half* __restrict__ chi, __half* __restrict__ clo,
             float* __restrict__ out) {
    extern __shared__ float sm[];
    float* hs   = sm;           // 14336
    float* av   = sm + 14336;   // 512
    float* sadj = sm + 14848;   // 49
    float* ssi  = sm + 14897;   // 56
    float* ssj  = sm + 14953;   // 56
    float* sal  = sm + 15009;   // 392
    const int tid = threadIdx.x;
    const int w = tid >> 5, lane = tid & 31;
    const int b0 = blockIdx.x * GB;
    const size_t base = (size_t)blockIdx.x * (GB * NND * HID);

    {
        const float4* src = (const float4*)(h2 + base);
        float4* dst = (float4*)hs;
        for (int i = tid; i < GB * NND * HID / 4; i += 256) dst[i] = src[i];
        if (tid < 128) ((float4*)av)[tid] = ((const float4*)a2)[tid];
        if (tid < 49) sadj[tid] = adj[tid];
    }
    __syncthreads();

    {
#pragma unroll
        for (int ri = 0; ri < 7; ++ri) {
            const int r = w * 7 + ri;
            const float* hr = hs + r * HID;
            float si = 0.f, sj = 0.f;
#pragma unroll
            for (int k = lane; k < HID; k += 32) {
                const float hv = hr[k];
                si = fmaf(hv, av[k], si);
                sj = fmaf(hv, av[HID + k], sj);
            }
#pragma unroll
            for (int off = 16; off > 0; off >>= 1) {
                si += __shfl_xor_sync(0xffffffffu, si, off);
                sj += __shfl_xor_sync(0xffffffffu, sj, off);
            }
            if (lane == 0) { ssi[r] = si; ssj[r] = sj; }
        }
    }
    __syncthreads();

    if (tid < GB * NND) {
        const int b = tid / 7, i = tid - b * 7;
        float e[7]; float mx = -3.0e38f;
#pragma unroll
        for (int j = 0; j < 7; ++j) {
            float v = ssi[b * 7 + i] + ssj[b * 7 + j];
            v = (v > 0.f) ? v : 0.2f * v;
            if (sadj[i * 7 + j] == 0.f) v = -3.0e38f;
            e[j] = v; mx = fmaxf(mx, v);
        }
        float s = 0.f;
#pragma unroll
        for (int j = 0; j < 7; ++j) {
            const float ex = (e[j] < -1.0e38f) ? 0.f : __expf(e[j] - mx);
            e[j] = ex; s += ex;
        }
        const float inv = 1.f / s;
        float* oa = out + (size_t)6 * BATCH + (size_t)(b0 + b) * 49 + i * 7;
#pragma unroll
        for (int j = 0; j < 7; ++j) {
            const float al = e[j] * inv;
            sal[tid * 7 + j] = al;
            oa[j] = al;
        }
    }
    __syncthreads();

    // aggregation -> combined[b][r*256 + d] as fp16 hi/lo
    {
        const float* hb = hs + w * 7 * HID;
        const size_t cb = (size_t)(b0 + w) * COMB;
#pragma unroll
        for (int ri = 0; ri < 7; ++ri) {
            const float* alr = sal + (w * 7 + ri) * 7;
            float a0 = alr[0], a1v = alr[1], a2v = alr[2], a3 = alr[3],
                  a4 = alr[4], a5 = alr[5], a6 = alr[6];
#pragma unroll
            for (int d4 = lane; d4 < 64; d4 += 32) {
                const float4* p0 = (const float4*)(hb) + d4;
                float4 h0 = p0[0],  h1v = p0[64],  h2 = p0[128], h3 = p0[192],
                       h4 = p0[256], h5 = p0[320], h6 = p0[384];
                float4 o;
                o.x = a0*h0.x + a1v*h1v.x + a2v*h2.x + a3*h3.x + a4*h4.x + a5*h5.x + a6*h6.x;
                o.y = a0*h0.y + a1v*h1v.y + a2v*h2.y + a3*h3.y + a4*h4.y + a5*h5.y + a6*h6.y;
                o.z = a0*h0.z + a1v*h1v.z + a2v*h2.z + a3*h3.z + a4*h4.z + a5*h5.z + a6*h6.z;
                o.w = a0*h0.w + a1v*h1v.w + a2v*h2.w + a3*h3.w + a4*h4.w + a5*h5.w + a6*h6.w;
                o.x = fmaxf(o.x, 0.f); o.y = fmaxf(o.y, 0.f);
                o.z = fmaxf(o.z, 0.f); o.w = fmaxf(o.w, 0.f);
                uint32_t h0p, h1p, l0p, l1p;
                cvt_hilo(o, h0p, h1p, l0p, l1p);
                const size_t off = cb + ri * HID + d4 * 4;
                *(uint2*)(chi + off) = make_uint2(h0p, h1p);
                *(uint2*)(clo + off) = make_uint2(l0p, l1p);
            }
        }
    }
    // context tail (float4 per thread-iter)
    for (int idx = tid; idx < GB * CTXD / 4; idx += 256) {
        const int b = idx >> 6, c4 = idx & 63;
        float4 v = ((const float4*)context)[(size_t)(b0 + b) * 64 + c4];
        uint32_t h0p, h1p, l0p, l1p;
        cvt_hilo(v, h0p, h1p, l0p, l1p);
        const size_t off = (size_t)(b0 + b) * COMB + NND * HID + c4 * 4;
        *(uint2*)(chi + off) = make_uint2(h0p, h1p);
        *(uint2*)(clo + off) = make_uint2(l0p, l1p);
    }
}

// ---------------------------------------------------------------------------
// final heads: biases + relu/tanh + wh2/wh3 + softmax + pred. 1 thread/batch.
// out = [pred(B) | weights(B*5) | attn2(B*49)]
// ---------------------------------------------------------------------------
__global__ void __launch_bounds__(256)
final_kernel(const float* __restrict__ ht, const float* __restrict__ base_preds,
             const float* __restrict__ wh1_b,
             const float* __restrict__ wh2_w, const float* __restrict__ wh2_b,
             const float* __restrict__ wh3_w, const float* __restrict__ wh3_b,
             const float* __restrict__ rh1_b,
             const float* __restrict__ rh2_w, const float* __restrict__ rh2_b,
             float* __restrict__ out) {
    const int b = blockIdx.x * 256 + threadIdx.x;
    if (b >= BATCH) return;
    const float* h = ht + (size_t)b * 64;

    float t1[32];
#pragma unroll
    for (int k = 0; k < 32; ++k) t1[k] = fmaxf(h[k] + wh1_b[k], 0.f);
    float t2[16];
#pragma unroll
    for (int o = 0; o < 16; ++o) {
        float s = wh2_b[o];
#pragma unroll
        for (int k = 0; k < 32; ++k) s = fmaf(t1[k], wh2_w[o * 32 + k], s);
        t2[o] = fmaxf(s, 0.f);
    }
    float raw[5]; float mx = -3.0e38f;
#pragma unroll
    for (int o = 0; o < 5; ++o) {
        float s = wh3_b[o];
#pragma unroll
        for (int k = 0; k < 16; ++k) s = fmaf(t2[k], wh3_w[o * 16 + k], s);
        raw[o] = s; mx = fmaxf(mx, s);
    }
    float se = 0.f;
#pragma unroll
    for (int o = 0; o < 5; ++o) { raw[o] = __expf(raw[o] - mx); se += raw[o]; }
    const float inv = 1.f / se;
    float wp = 0.f;
#pragma unroll
    for (int o = 0; o < 5; ++o) {
        const float wt = raw[o] * inv;
        out[BATCH + (size_t)b * 5 + o] = wt;
        wp = fmaf(wt, base_preds[(size_t)b * 5 + o], wp);
    }
    float rr = rh2_b[0];
#pragma unroll
    for (int k = 0; k < 16; ++k)
        rr = fmaf(tanhf(h[32 + k] + rh1_b[k]), rh2_w[k], rr);
    out[b] = fmaxf(wp + rr * 0.05f, 0.05f);
}

// ---------------------------------------------------------------------------
extern "C" void kernel_launch(void* const* d_in, const int* in_sizes, int n_in,
                              void* d_out, int out_size) {
    const float* node_feats = (const float*)d_in[0];
    const float* adj        = (const float*)d_in[1];
    const float* context    = (const float*)d_in[2];
    const float* base_preds = (const float*)d_in[3];
    const float* W1    = (const float*)d_in[4];
    const float* a1    = (const float*)d_in[5];
    const float* W2    = (const float*)d_in[6];
    const float* a2    = (const float*)d_in[7];
    const float* wh1_w = (const float*)d_in[8];
    const float* wh1_b = (const float*)d_in[9];
    const float* wh2_w = (const float*)d_in[10];
    const float* wh2_b = (const float*)d_in[11];
    const float* wh3_w = (const float*)d_in[12];
    const float* wh3_b = (const float*)d_in[13];
    const float* rh1_w = (const float*)d_in[14];
    const float* rh1_b = (const float*)d_in[15];
    const float* rh2_w = (const float*)d_in[16];
    const float* rh2_b = (const float*)d_in[17];
    float* out = (float*)d_out;

    float *h1p, *h2p, *htp;
    __half *a1h, *a1l, *x2h, *x2l, *w1h, *w2h, *hwp, *cbh, *cbl;
    cudaGetSymbolAddress((void**)&h1p, g_h1);
    cudaGetSymbolAddress((void**)&h2p, g_h2);
    cudaGetSymbolAddress((void**)&htp, g_ht);
    cudaGetSymbolAddress((void**)&a1h, g_a1hi);
    cudaGetSymbolAddress((void**)&a1l, g_a1lo);
    cudaGetSymbolAddress((void**)&x2h, g_x2hi);
    cudaGetSymbolAddress((void**)&x2l, g_x2lo);
    cudaGetSymbolAddress((void**)&w1h, g_w1h);
    cudaGetSymbolAddress((void**)&w2h, g_w2h);
    cudaGetSymbolAddress((void**)&hwp, g_hw);
    cudaGetSymbolAddress((void**)&cbh, g_combhi);
    cudaGetSymbolAddress((void**)&cbl, g_comblo);

    const int smem1 = 15401 * 4;
    cudaFuncSetAttribute(gemm_f16, cudaFuncAttributeMaxDynamicSharedMemorySize, G2_SMEM);
    cudaFuncSetAttribute(gemm_heads, cudaFuncAttributeMaxDynamicSharedMemorySize, G3_SMEM);
    cudaFuncSetAttribute(attn1_kernel, cudaFuncAttributeMaxDynamicSharedMemorySize, smem1);
    cudaFuncSetAttribute(attn2_kernel, cudaFuncAttributeMaxDynamicSharedMemorySize, smem1);

    convw_kernel<<<(HID * FEATD + 255) / 256, 256>>>(W1, w1h, HID * FEATD);
    convw_kernel<<<(HID * HID + 255) / 256, 256>>>(W2, w2h, HID * HID);
    convhw_kernel<<<(64 * COMB + 255) / 256, 256>>>(wh1_w, rh1_w, hwp);
    convA_kernel<<<(MROWS * FEATD / 4 + 255) / 256, 256>>>(node_feats, a1h, a1l,
                                                           MROWS * FEATD / 4);

    // h1 = (a1hi+a1lo) @ W1^T
    gemm_f16<<<MROWS / 128, 256, G2_SMEM>>>(a1h, a1l, w1h, h1p, FEATD);
    // x2 (fp16 hi/lo) = relu(alpha1 @ h1)
    attn1_kernel<<<BATCH / GB, 256, smem1>>>(h1p, adj, a1, x2h, x2l);
    // h2 = (x2hi+x2lo) @ W2^T
    gemm_f16<<<MROWS / 128, 256, G2_SMEM>>>(x2h, x2l, w2h, h2p, HID);
    // attn2: softmax out + combined (fp16 hi/lo)
    attn2_kernel<<<BATCH / GB, 256, smem1>>>(h2p, adj, a2, context, cbh, cbl, out);
    // ht = combined @ HW^T  (N=64 heads GEMM)
    gemm_heads<<<BATCH / 128, 256, G3_SMEM>>>(cbh, cbl, hwp, htp);
    // tiny tail
    final_kernel<<<BATCH / 256, 256>>>(htp, base_preds, wh1_b, wh2_w, wh2_b,
                                       wh3_w, wh3_b, rh1_b, rh2_w, rh2_b, out);
}

// round 14
// speedup vs baseline: 3.3606x; 1.1053x over previous
#include <cuda_runtime.h>
#include <cuda_fp16.h>
#include <cstdint>
#include <cstddef>

#define BATCH 16384
#define NND   7
#define FEATD 512
#define HID   256
#define CTXD  256
#define COMB  2048
#define MROWS (BATCH * NND)        // 114688
#define GB    8

// main GEMM buffer (tile 128x128), XOR-swizzled 64B rows
#define XA_HI  0
#define XA_LO  8192
#define XB     16384
#define XSTAGE 24576
#define GX_SMEM (2 * XSTAGE)       // 49152 -> 2 CTAs/SM

// heads GEMM staging (unchanged, 80B-padded rows)
#define AH2_OFF 0
#define AL2_OFF 10240
#define HB_OFF  20480
#define STAGE3  25600
#define G3_SMEM (2 * STAGE3)

// ---------------- scratch ---------------------------------------------------
__device__ float  g_h1[(size_t)MROWS * HID];
__device__ float  g_h2[(size_t)MROWS * HID];
__device__ __half g_a1hi[(size_t)MROWS * FEATD];
__device__ __half g_a1lo[(size_t)MROWS * FEATD];
__device__ __half g_x2hi[(size_t)MROWS * HID];
__device__ __half g_x2lo[(size_t)MROWS * HID];
__device__ __half g_combhi[(size_t)BATCH * COMB];
__device__ __half g_comblo[(size_t)BATCH * COMB];
__device__ float  g_ht[(size_t)BATCH * 64];
__device__ __half g_w1h[HID * FEATD];
__device__ __half g_w2h[HID * HID];
__device__ __half g_hw[64 * COMB];

// ---------------- helpers ---------------------------------------------------
__device__ __forceinline__ uint32_t smem_u32(const void* p) {
    uint32_t a;
    asm("{ .reg .u64 t; cvta.to.shared.u64 t, %1; cvt.u32.u64 %0, t; }" : "=r"(a) : "l"(p));
    return a;
}
__device__ __forceinline__ void ldsm4(uint32_t* r, uint32_t addr) {
    asm volatile("ldmatrix.sync.aligned.m8n8.x4.shared.b16 {%0,%1,%2,%3}, [%4];"
                 : "=r"(r[0]), "=r"(r[1]), "=r"(r[2]), "=r"(r[3]) : "r"(addr));
}
__device__ __forceinline__ void mma_f16(float* c, const uint32_t* a, const uint32_t* b) {
    asm volatile(
        "mma.sync.aligned.m16n8k16.row.col.f32.f16.f16.f32 "
        "{%0,%1,%2,%3}, {%4,%5,%6,%7}, {%8,%9}, {%0,%1,%2,%3};"
        : "+f"(c[0]), "+f"(c[1]), "+f"(c[2]), "+f"(c[3])
        : "r"(a[0]), "r"(a[1]), "r"(a[2]), "r"(a[3]), "r"(b[0]), "r"(b[1]));
}
__device__ __forceinline__ void cvt_hilo(float4 v, uint32_t& h0, uint32_t& h1,
                                         uint32_t& l0, uint32_t& l1) {
    __half2 ha = __floats2half2_rn(v.x, v.y);
    __half2 hb = __floats2half2_rn(v.z, v.w);
    float2 fa = __half22float2(ha);
    float2 fb = __half22float2(hb);
    __half2 la = __floats2half2_rn(v.x - fa.x, v.y - fa.y);
    __half2 lb = __floats2half2_rn(v.z - fb.x, v.w - fb.y);
    h0 = *(uint32_t*)&ha; h1 = *(uint32_t*)&hb;
    l0 = *(uint32_t*)&la; l1 = *(uint32_t*)&lb;
}
__device__ __forceinline__ void cpasync16(uint32_t saddr, const void* g) {
    asm volatile("cp.async.cg.shared.global [%0], [%1], 16;" :: "r"(saddr), "l"(g) : "memory");
}
__device__ __forceinline__ void cpasync_commit() {
    asm volatile("cp.async.commit_group;" ::: "memory");
}
__device__ __forceinline__ void cpasync_wait0() {
    asm volatile("cp.async.wait_group 0;" ::: "memory");
}
// XOR swizzle for 64B rows: 16B chunk index c at row r -> c ^ ((r>>1)&3)
__device__ __forceinline__ uint32_t xsw(int row, int ch) {
    return (uint32_t)(row * 64 + ((ch ^ ((row >> 1) & 3)) << 4));
}

// ---------------------------------------------------------------------------
// converters
// ---------------------------------------------------------------------------
__global__ void convw_kernel(const float* __restrict__ W, __half* __restrict__ H, int n) {
    int i = blockIdx.x * 256 + threadIdx.x;
    if (i < n) H[i] = __float2half_rn(W[i]);
}
__global__ void convhw_kernel(const float* __restrict__ wh1_w, const float* __restrict__ rh1_w,
                              __half* __restrict__ HW) {
    int i = blockIdx.x * 256 + threadIdx.x;
    if (i < 64 * COMB) {
        int row = i >> 11, k = i & (COMB - 1);
        float v = 0.f;
        if (row < 32) v = wh1_w[row * COMB + k];
        else if (row < 48) v = rh1_w[(row - 32) * COMB + k];
        HW[i] = __float2half_rn(v);
    }
}
__global__ void convA_kernel(const float* __restrict__ A, __half* __restrict__ Hi,
                             __half* __restrict__ Lo, int n4) {
    int i = blockIdx.x * 256 + threadIdx.x;
    if (i < n4) {
        float4 v = ((const float4*)A)[i];
        uint32_t h0, h1, l0, l1;
        cvt_hilo(v, h0, h1, l0, l1);
        ((uint2*)Hi)[i] = make_uint2(h0, h1);
        ((uint2*)Lo)[i] = make_uint2(l0, l1);
    }
}

// ---------------------------------------------------------------------------
// fp16 HMMA GEMM, tile 128x128, 2 CTAs/SM. C[m,n] = sum_k (Ahi+Alo)*B, 2-term.
// 256 threads = 8 warps (4m x 2n), warp tile 32x64. XOR-swizzled 64B rows.
// ---------------------------------------------------------------------------
__global__ void __launch_bounds__(256, 2)
gemm_f16(const __half* __restrict__ Ahi, const __half* __restrict__ Alo,
         const __half* __restrict__ Bh, float* __restrict__ C, int K) {
    extern __shared__ char smem[];
    const uint32_t sb = smem_u32(smem);
    const int tid  = threadIdx.x;
    const int lane = tid & 31;
    const int wid  = tid >> 5;
    const int wm   = wid & 3;
    const int wn   = wid >> 2;
    const int m0   = blockIdx.x * 128;
    const int n0   = blockIdx.y * 128;
    const int nk   = K >> 5;

    // staging map: thread t -> row t>>1, chunks (t&1)*2 + {0,1}
    const int srow = tid >> 1;
    const int sch  = (tid & 1) * 2;
    const __half* AhiG = Ahi + (size_t)(m0 + srow) * K + sch * 8;
    const __half* AloG = Alo + (size_t)(m0 + srow) * K + sch * 8;
    const __half* BG   = Bh  + (size_t)(n0 + srow) * K + sch * 8;
    const uint32_t sAh0 = sb + XA_HI + xsw(srow, sch);
    const uint32_t sAh1 = sb + XA_HI + xsw(srow, sch + 1);
    const uint32_t sAl0 = sb + XA_LO + xsw(srow, sch);
    const uint32_t sAl1 = sb + XA_LO + xsw(srow, sch + 1);
    const uint32_t sB0  = sb + XB + xsw(srow, sch);
    const uint32_t sB1  = sb + XB + xsw(srow, sch + 1);

    // LDSM per-lane constants
    const int arow0 = wm * 32 + (lane & 15);
    const int asel  = lane >> 4;
    const uint32_t abase0 = sb + XA_HI + arow0 * 64;
    const uint32_t abase1 = sb + XA_HI + (arow0 + 16) * 64;
    const int ars0 = (arow0 >> 1) & 3;
    const int ars1 = ((arow0 + 16) >> 1) & 3;
    const int brow0 = wn * 64 + (lane & 7) + ((lane >> 4) << 3);
    const int bsel  = (lane >> 3) & 1;
    uint32_t bbase[4]; int brs[4];
#pragma unroll
    for (int p = 0; p < 4; ++p) {
        bbase[p] = sb + XB + (brow0 + 16 * p) * 64;
        brs[p]   = ((brow0 + 16 * p) >> 1) & 3;
    }

    float acc[2][8][4];
#pragma unroll
    for (int i = 0; i < 2; ++i)
#pragma unroll
        for (int j = 0; j < 8; ++j)
#pragma unroll
            for (int q = 0; q < 4; ++q) acc[i][j][q] = 0.f;

    // prologue
    {
        cpasync16(sAh0, AhiG);
        cpasync16(sAh1, AhiG + 8);
        cpasync16(sAl0, AloG);
        cpasync16(sAl1, AloG + 8);
        cpasync16(sB0, BG);
        cpasync16(sB1, BG + 8);
        cpasync_commit();
        cpasync_wait0();
    }
    __syncthreads();

    for (int kt = 0; kt < nk; ++kt) {
        const uint32_t bufo = (kt & 1) * XSTAGE;
        const bool more = (kt + 1 < nk);
        if (more) {
            const uint32_t nb = ((kt + 1) & 1) * XSTAGE;
            const int go = (kt + 1) * 32;
            cpasync16(sAh0 + nb, AhiG + go);
            cpasync16(sAh1 + nb, AhiG + go + 8);
            cpasync16(sAl0 + nb, AloG + go);
            cpasync16(sAl1 + nb, AloG + go + 8);
            cpasync16(sB0 + nb, BG + go);
            cpasync16(sB1 + nb, BG + go + 8);
            cpasync_commit();
        }

#pragma unroll
        for (int ks = 0; ks < 2; ++ks) {
            const int ca = ks * 2 + asel;
            const int cbsel = ks * 2 + bsel;
            uint32_t ah[2][4], al[2][4], bh[4][4];
            ldsm4(ah[0], bufo + abase0 + ((ca ^ ars0) << 4));
            ldsm4(ah[1], bufo + abase1 + ((ca ^ ars1) << 4));
            ldsm4(al[0], bufo + abase0 + (XA_LO - XA_HI) + ((ca ^ ars0) << 4));
            ldsm4(al[1], bufo + abase1 + (XA_LO - XA_HI) + ((ca ^ ars1) << 4));
#pragma unroll
            for (int p = 0; p < 4; ++p)
                ldsm4(bh[p], bufo + bbase[p] + ((cbsel ^ brs[p]) << 4));
            // term 1: Ah * B
#pragma unroll
            for (int p = 0; p < 4; ++p)
#pragma unroll
                for (int mi = 0; mi < 2; ++mi) {
                    mma_f16(acc[mi][2 * p],     ah[mi], bh[p]);
                    mma_f16(acc[mi][2 * p + 1], ah[mi], bh[p] + 2);
                }
            // term 2: Al * B
#pragma unroll
            for (int p = 0; p < 4; ++p)
#pragma unroll
                for (int mi = 0; mi < 2; ++mi) {
                    mma_f16(acc[mi][2 * p],     al[mi], bh[p]);
                    mma_f16(acc[mi][2 * p + 1], al[mi], bh[p] + 2);
                }
        }

        if (more) {
            cpasync_wait0();
            __syncthreads();
        }
    }

    // epilogue
    const int g  = lane >> 2;
    const int cq = (lane & 3) * 2;
#pragma unroll
    for (int mi = 0; mi < 2; ++mi) {
        const int row0 = m0 + wm * 32 + mi * 16 + g;
        float* C0 = C + (size_t)row0 * 256 + n0 + wn * 64;
        float* C1 = C0 + (size_t)8 * 256;
#pragma unroll
        for (int ni = 0; ni < 8; ++ni) {
            *(float2*)(C0 + ni * 8 + cq) = make_float2(acc[mi][ni][0], acc[mi][ni][1]);
            *(float2*)(C1 + ni * 8 + cq) = make_float2(acc[mi][ni][2], acc[mi][ni][3]);
        }
    }
}

// ---------------------------------------------------------------------------
// Heads GEMM (N=64): ht[b,n] = sum_k (Chi+Clo)[b,k]*HW[n,k], K=2048.
// CTA 128x64, 8 warps (4m x 2n), warp tile 32x32. (unchanged from R13)
// ---------------------------------------------------------------------------
__global__ void __launch_bounds__(256, 1)
gemm_heads(const __half* __restrict__ Ahi, const __half* __restrict__ Alo,
           const __half* __restrict__ Bh, float* __restrict__ C) {
    extern __shared__ char smem[];
    const uint32_t sb = smem_u32(smem);
    const int tid  = threadIdx.x;
    const int lane = tid & 31;
    const int wid  = tid >> 5;
    const int wm   = wid & 3;
    const int wn   = wid >> 2;
    const int m0   = blockIdx.x * 128;
    const int nk   = COMB >> 5;   // 64

    const int ar0 = tid >> 1;
    const int ac0 = (tid & 1) * 2;
    const __half* AhiG = Ahi + (size_t)(m0 + ar0) * COMB + ac0 * 8;
    const __half* AloG = Alo + (size_t)(m0 + ar0) * COMB + ac0 * 8;
    const int brow = tid >> 2, bch = tid & 3;
    const __half* BG = Bh + (size_t)brow * COMB + bch * 8;
    const uint32_t sAh = sb + AH2_OFF + ar0 * 80 + ac0 * 16;
    const uint32_t sAl = sb + AL2_OFF + ar0 * 80 + ac0 * 16;
    const uint32_t sB  = sb + HB_OFF + brow * 80 + bch * 16;

    const uint32_t a_off = AH2_OFF + (uint32_t)(wm * 32 + (lane & 15)) * 80 + ((lane >> 4) << 4);
    const uint32_t b_off = HB_OFF + (uint32_t)(wn * 32 + (lane & 7) + ((lane >> 4) << 3)) * 80
                         + ((lane & 8) << 1);

    float acc[2][4][4];
#pragma unroll
    for (int i = 0; i < 2; ++i)
#pragma unroll
        for (int j = 0; j < 4; ++j)
#pragma unroll
            for (int q = 0; q < 4; ++q) acc[i][j][q] = 0.f;

    {
#pragma unroll
        for (int q = 0; q < 2; ++q) {
            cpasync16(sAh + q * 16, AhiG + q * 8);
            cpasync16(sAl + q * 16, AloG + q * 8);
        }
        cpasync16(sB, BG);
        cpasync_commit();
        cpasync_wait0();
    }
    __syncthreads();

    for (int kt = 0; kt < nk; ++kt) {
        const uint32_t bufo = (kt & 1) * STAGE3;
        const bool more = (kt + 1 < nk);
        if (more) {
            const uint32_t nb = ((kt + 1) & 1) * STAGE3;
#pragma unroll
            for (int q = 0; q < 2; ++q) {
                cpasync16(sAh + nb + q * 16, AhiG + (kt + 1) * 32 + q * 8);
                cpasync16(sAl + nb + q * 16, AloG + (kt + 1) * 32 + q * 8);
            }
            cpasync16(sB + nb, BG + (kt + 1) * 32);
            cpasync_commit();
        }

#pragma unroll
        for (int ks = 0; ks < 2; ++ks) {
            const uint32_t ab = sb + bufo + a_off + ks * 32;
            const uint32_t bb = sb + bufo + b_off + ks * 32;
            uint32_t ah[2][4], al[2][4], bh[2][4];
            ldsm4(ah[0], ab);
            ldsm4(ah[1], ab + 16 * 80);
            ldsm4(al[0], ab + (AL2_OFF - AH2_OFF));
            ldsm4(al[1], ab + (AL2_OFF - AH2_OFF) + 16 * 80);
#pragma unroll
            for (int p = 0; p < 2; ++p) ldsm4(bh[p], bb + p * (16 * 80));
#pragma unroll
            for (int p = 0; p < 2; ++p)
#pragma unroll
                for (int mi = 0; mi < 2; ++mi) {
                    mma_f16(acc[mi][2 * p],     ah[mi], bh[p]);
                    mma_f16(acc[mi][2 * p + 1], ah[mi], bh[p] + 2);
                    mma_f16(acc[mi][2 * p],     al[mi], bh[p]);
                    mma_f16(acc[mi][2 * p + 1], al[mi], bh[p] + 2);
                }
        }

        if (more) {
            cpasync_wait0();
            __syncthreads();
        }
    }

    const int g  = lane >> 2;
    const int cq = (lane & 3) * 2;
#pragma unroll
    for (int mi = 0; mi < 2; ++mi) {
        const int row0 = m0 + wm * 32 + mi * 16 + g;
        float* C0 = C + (size_t)row0 * 64 + wn * 32;
        float* C1 = C0 + (size_t)8 * 64;
#pragma unroll
        for (int ni = 0; ni < 4; ++ni) {
            *(float2*)(C0 + ni * 8 + cq) = make_float2(acc[mi][ni][0], acc[mi][ni][1]);
            *(float2*)(C1 + ni * 8 + cq) = make_float2(acc[mi][ni][2], acc[mi][ni][3]);
        }
    }
}

// ---------------------------------------------------------------------------
// attn1: x2 = relu(alpha1 @ h1), emitted as fp16 hi/lo.
// ---------------------------------------------------------------------------
__global__ void __launch_bounds__(256)
attn1_kernel(const float* __restrict__ h1, const float* __restrict__ adj,
             const float* __restrict__ a1, __half* __restrict__ x2hi,
             __half* __restrict__ x2lo) {
    extern __shared__ float sm[];
    float* hs   = sm;           // 14336
    float* av   = sm + 14336;   // 512
    float* sadj = sm + 14848;   // 49
    float* ssi  = sm + 14897;   // 56
    float* ssj  = sm + 14953;   // 56
    float* sal  = sm + 15009;   // 392
    const int tid = threadIdx.x;
    const int w = tid >> 5, lane = tid & 31;
    const size_t base = (size_t)blockIdx.x * (GB * NND * HID);

    {
        const float4* src = (const float4*)(h1 + base);
        float4* dst = (float4*)hs;
        for (int i = tid; i < GB * NND * HID / 4; i += 256) dst[i] = src[i];
        if (tid < 128) ((float4*)av)[tid] = ((const float4*)a1)[tid];
        if (tid < 49) sadj[tid] = adj[tid];
    }
    __syncthreads();

    {
#pragma unroll
        for (int ri = 0; ri < 7; ++ri) {
            const int r = w * 7 + ri;
            const float* hr = hs + r * HID;
            float si = 0.f, sj = 0.f;
#pragma unroll
            for (int k = lane; k < HID; k += 32) {
                const float hv = hr[k];
                si = fmaf(hv, av[k], si);
                sj = fmaf(hv, av[HID + k], sj);
            }
#pragma unroll
            for (int off = 16; off > 0; off >>= 1) {
                si += __shfl_xor_sync(0xffffffffu, si, off);
                sj += __shfl_xor_sync(0xffffffffu, sj, off);
            }
            if (lane == 0) { ssi[r] = si; ssj[r] = sj; }
        }
    }
    __syncthreads();

    if (tid < GB * NND) {
        const int b = tid / 7, i = tid - b * 7;
        float e[7]; float mx = -3.0e38f;
#pragma unroll
        for (int j = 0; j < 7; ++j) {
            float v = ssi[b * 7 + i] + ssj[b * 7 + j];
            v = (v > 0.f) ? v : 0.2f * v;
            if (sadj[i * 7 + j] == 0.f) v = -3.0e38f;
            e[j] = v; mx = fmaxf(mx, v);
        }
        float s = 0.f;
#pragma unroll
        for (int j = 0; j < 7; ++j) {
            const float ex = (e[j] < -1.0e38f) ? 0.f : __expf(e[j] - mx);
            e[j] = ex; s += ex;
        }
        const float inv = 1.f / s;
#pragma unroll
        for (int j = 0; j < 7; ++j) sal[tid * 7 + j] = e[j] * inv;
    }
    __syncthreads();

    {
        const float* hb = hs + w * 7 * HID;
#pragma unroll
        for (int ri = 0; ri < 7; ++ri) {
            const int r = w * 7 + ri;
            const float* alr = sal + r * 7;
            float a0 = alr[0], a1v = alr[1], a2v = alr[2], a3 = alr[3],
                  a4 = alr[4], a5 = alr[5], a6 = alr[6];
#pragma unroll
            for (int d4 = lane; d4 < 64; d4 += 32) {
                const float4* p0 = (const float4*)(hb) + d4;
                float4 h0 = p0[0],  h1v = p0[64],  h2 = p0[128], h3 = p0[192],
                       h4 = p0[256], h5 = p0[320], h6 = p0[384];
                float4 o;
                o.x = a0*h0.x + a1v*h1v.x + a2v*h2.x + a3*h3.x + a4*h4.x + a5*h5.x + a6*h6.x;
                o.y = a0*h0.y + a1v*h1v.y + a2v*h2.y + a3*h3.y + a4*h4.y + a5*h5.y + a6*h6.y;
                o.z = a0*h0.z + a1v*h1v.z + a2v*h2.z + a3*h3.z + a4*h4.z + a5*h5.z + a6*h6.z;
                o.w = a0*h0.w + a1v*h1v.w + a2v*h2.w + a3*h3.w + a4*h4.w + a5*h5.w + a6*h6.w;
                o.x = fmaxf(o.x, 0.f); o.y = fmaxf(o.y, 0.f);
                o.z = fmaxf(o.z, 0.f); o.w = fmaxf(o.w, 0.f);
                uint32_t h0p, h1p, l0p, l1p;
                cvt_hilo(o, h0p, h1p, l0p, l1p);
                const size_t off = base + r * HID + d4 * 4;
                *(uint2*)(x2hi + off) = make_uint2(h0p, h1p);
                *(uint2*)(x2lo + off) = make_uint2(l0p, l1p);
            }
        }
    }
}

// ---------------------------------------------------------------------------
// attn2: softmax (writes attn2 output) + aggregation -> combined (fp16 hi/lo)
// ---------------------------------------------------------------------------
__global__ void __launch_bounds__(256)
attn2_kernel(const float* __restrict__ h2, const float* __restrict__ adj,
             const float* __restrict__ a2, const float* __restrict__ context,
             __half* __restrict__ chi, __half* __restrict__ clo,
             float* __restrict__ out) {
    extern __shared__ float sm[];
    float* hs   = sm;
    float* av   = sm + 14336;
    float* sadj = sm + 14848;
    float* ssi  = sm + 14897;
    float* ssj  = sm + 14953;
    float* sal  = sm + 15009;
    const int tid = threadIdx.x;
    const int w = tid >> 5, lane = tid & 31;
    const int b0 = blockIdx.x * GB;
    const size_t base = (size_t)blockIdx.x * (GB * NND * HID);

    {
        const float4* src = (const float4*)(h2 + base);
        float4* dst = (float4*)hs;
        for (int i = tid; i < GB * NND * HID / 4; i += 256) dst[i] = src[i];
        if (tid < 128) ((float4*)av)[tid] = ((const float4*)a2)[tid];
        if (tid < 49) sadj[tid] = adj[tid];
    }
    __syncthreads();

    {
#pragma unroll
        for (int ri = 0; ri < 7; ++ri) {
            const int r = w * 7 + ri;
            const float* hr = hs + r * HID;
            float si = 0.f, sj = 0.f;
#pragma unroll
            for (int k = lane; k < HID; k += 32) {
                const float hv = hr[k];
                si = fmaf(hv, av[k], si);
                sj = fmaf(hv, av[HID + k], sj);
            }
#pragma unroll
            for (int off = 16; off > 0; off >>= 1) {
                si += __shfl_xor_sync(0xffffffffu, si, off);
                sj += __shfl_xor_sync(0xffffffffu, sj, off);
            }
            if (lane == 0) { ssi[r] = si; ssj[r] = sj; }
        }
    }
    __syncthreads();

    if (tid < GB * NND) {
        const int b = tid / 7, i = tid - b * 7;
        float e[7]; float mx = -3.0e38f;
#pragma unroll
        for (int j = 0; j < 7; ++j) {
            float v = ssi[b * 7 + i] + ssj[b * 7 + j];
            v = (v > 0.f) ? v : 0.2f * v;
            if (sadj[i * 7 + j] == 0.f) v = -3.0e38f;
            e[j] = v; mx = fmaxf(mx, v);
        }
        float s = 0.f;
#pragma unroll
        for (int j = 0; j < 7; ++j) {
            const float ex = (e[j] < -1.0e38f) ? 0.f : __expf(e[j] - mx);
            e[j] = ex; s += ex;
        }
        const float inv = 1.f / s;
        float* oa = out + (size_t)6 * BATCH + (size_t)(b0 + b) * 49 + i * 7;
#pragma unroll
        for (int j = 0; j < 7; ++j) {
            const float al = e[j] * inv;
            sal[tid * 7 + j] = al;
            oa[j] = al;
        }
    }
    __syncthreads();

    {
        const float* hb = hs + w * 7 * HID;
        const size_t cb = (size_t)(b0 + w) * COMB;
#pragma unroll
        for (int ri = 0; ri < 7; ++ri) {
            const float* alr = sal + (w * 7 + ri) * 7;
            float a0 = alr[0], a1v = alr[1], a2v = alr[2], a3 = alr[3],
                  a4 = alr[4], a5 = alr[5], a6 = alr[6];
#pragma unroll
            for (int d4 = lane; d4 < 64; d4 += 32) {
                const float4* p0 = (const float4*)(hb) + d4;
                float4 h0 = p0[0],  h1v = p0[64],  h2 = p0[128], h3 = p0[192],
                       h4 = p0[256], h5 = p0[320], h6 = p0[384];
                float4 o;
                o.x = a0*h0.x + a1v*h1v.x + a2v*h2.x + a3*h3.x + a4*h4.x + a5*h5.x + a6*h6.x;
                o.y = a0*h0.y + a1v*h1v.y + a2v*h2.y + a3*h3.y + a4*h4.y + a5*h5.y + a6*h6.y;
                o.z = a0*h0.z + a1v*h1v.z + a2v*h2.z + a3*h3.z + a4*h4.z + a5*h5.z + a6*h6.z;
                o.w = a0*h0.w + a1v*h1v.w + a2v*h2.w + a3*h3.w + a4*h4.w + a5*h5.w + a6*h6.w;
                o.x = fmaxf(o.x, 0.f); o.y = fmaxf(o.y, 0.f);
                o.z = fmaxf(o.z, 0.f); o.w = fmaxf(o.w, 0.f);
                uint32_t h0p, h1p, l0p, l1p;
                cvt_hilo(o, h0p, h1p, l0p, l1p);
                const size_t off = cb + ri * HID + d4 * 4;
                *(uint2*)(chi + off) = make_uint2(h0p, h1p);
                *(uint2*)(clo + off) = make_uint2(l0p, l1p);
            }
        }
    }
    for (int idx = tid; idx < GB * CTXD / 4; idx += 256) {
        const int b = idx >> 6, c4 = idx & 63;
        float4 v = ((const float4*)context)[(size_t)(b0 + b) * 64 + c4];
        uint32_t h0p, h1p, l0p, l1p;
        cvt_hilo(v, h0p, h1p, l0p, l1p);
        const size_t off = (size_t)(b0 + b) * COMB + NND * HID + c4 * 4;
        *(uint2*)(chi + off) = make_uint2(h0p, h1p);
        *(uint2*)(clo + off) = make_uint2(l0p, l1p);
    }
}

// ---------------------------------------------------------------------------
// final heads tail. out = [pred(B) | weights(B*5) | attn2(B*49)]
// ---------------------------------------------------------------------------
__global__ void __launch_bounds__(256)
final_kernel(const float* __restrict__ ht, const float* __restrict__ base_preds,
             const float* __restrict__ wh1_b,
             const float* __restrict__ wh2_w, const float* __restrict__ wh2_b,
             const float* __restrict__ wh3_w, const float* __restrict__ wh3_b,
             const float* __restrict__ rh1_b,
             const float* __restrict__ rh2_w, const float* __restrict__ rh2_b,
             float* __restrict__ out) {
    const int b = blockIdx.x * 256 + threadIdx.x;
    if (b >= BATCH) return;
    const float* h = ht + (size_t)b * 64;

    float t1[32];
#pragma unroll
    for (int k = 0; k < 32; ++k) t1[k] = fmaxf(h[k] + wh1_b[k], 0.f);
    float t2[16];
#pragma unroll
    for (int o = 0; o < 16; ++o) {
        float s = wh2_b[o];
#pragma unroll
        for (int k = 0; k < 32; ++k) s = fmaf(t1[k], wh2_w[o * 32 + k], s);
        t2[o] = fmaxf(s, 0.f);
    }
    float raw[5]; float mx = -3.0e38f;
#pragma unroll
    for (int o = 0; o < 5; ++o) {
        float s = wh3_b[o];
#pragma unroll
        for (int k = 0; k < 16; ++k) s = fmaf(t2[k], wh3_w[o * 16 + k], s);
        raw[o] = s; mx = fmaxf(mx, s);
    }
    float se = 0.f;
#pragma unroll
    for (int o = 0; o < 5; ++o) { raw[o] = __expf(raw[o] - mx); se += raw[o]; }
    const float inv = 1.f / se;
    float wp = 0.f;
#pragma unroll
    for (int o = 0; o < 5; ++o) {
        const float wt = raw[o] * inv;
        out[BATCH + (size_t)b * 5 + o] = wt;
        wp = fmaf(wt, base_preds[(size_t)b * 5 + o], wp);
    }
    float rr = rh2_b[0];
#pragma unroll
    for (int k = 0; k < 16; ++k)
        rr = fmaf(tanhf(h[32 + k] + rh1_b[k]), rh2_w[k], rr);
    out[b] = fmaxf(wp + rr * 0.05f, 0.05f);
}

// ---------------------------------------------------------------------------
extern "C" void kernel_launch(void* const* d_in, const int* in_sizes, int n_in,
                              void* d_out, int out_size) {
    const float* node_feats = (const float*)d_in[0];
    const float* adj        = (const float*)d_in[1];
    const float* context    = (const float*)d_in[2];
    const float* base_preds = (const float*)d_in[3];
    const float* W1    = (const float*)d_in[4];
    const float* a1    = (const float*)d_in[5];
    const float* W2    = (const float*)d_in[6];
    const float* a2    = (const float*)d_in[7];
    const float* wh1_w = (const float*)d_in[8];
    const float* wh1_b = (const float*)d_in[9];
    const float* wh2_w = (const float*)d_in[10];
    const float* wh2_b = (const float*)d_in[11];
    const float* wh3_w = (const float*)d_in[12];
    const float* wh3_b = (const float*)d_in[13];
    const float* rh1_w = (const float*)d_in[14];
    const float* rh1_b = (const float*)d_in[15];
    const float* rh2_w = (const float*)d_in[16];
    const float* rh2_b = (const float*)d_in[17];
    float* out = (float*)d_out;

    float *h1p, *h2p, *htp;
    __half *a1h, *a1l, *x2h, *x2l, *w1h, *w2h, *hwp, *cbh, *cbl;
    cudaGetSymbolAddress((void**)&h1p, g_h1);
    cudaGetSymbolAddress((void**)&h2p, g_h2);
    cudaGetSymbolAddress((void**)&htp, g_ht);
    cudaGetSymbolAddress((void**)&a1h, g_a1hi);
    cudaGetSymbolAddress((void**)&a1l, g_a1lo);
    cudaGetSymbolAddress((void**)&x2h, g_x2hi);
    cudaGetSymbolAddress((void**)&x2l, g_x2lo);
    cudaGetSymbolAddress((void**)&w1h, g_w1h);
    cudaGetSymbolAddress((void**)&w2h, g_w2h);
    cudaGetSymbolAddress((void**)&hwp, g_hw);
    cudaGetSymbolAddress((void**)&cbh, g_combhi);
    cudaGetSymbolAddress((void**)&cbl, g_comblo);

    const int smem1 = 15401 * 4;
    cudaFuncSetAttribute(gemm_f16, cudaFuncAttributeMaxDynamicSharedMemorySize, GX_SMEM);
    cudaFuncSetAttribute(gemm_heads, cudaFuncAttributeMaxDynamicSharedMemorySize, G3_SMEM);
    cudaFuncSetAttribute(attn1_kernel, cudaFuncAttributeMaxDynamicSharedMemorySize, smem1);
    cudaFuncSetAttribute(attn2_kernel, cudaFuncAttributeMaxDynamicSharedMemorySize, smem1);

    convw_kernel<<<(HID * FEATD + 255) / 256, 256>>>(W1, w1h, HID * FEATD);
    convw_kernel<<<(HID * HID + 255) / 256, 256>>>(W2, w2h, HID * HID);
    convhw_kernel<<<(64 * COMB + 255) / 256, 256>>>(wh1_w, rh1_w, hwp);
    convA_kernel<<<(MROWS * FEATD / 4 + 255) / 256, 256>>>(node_feats, a1h, a1l,
                                                           MROWS * FEATD / 4);

    // h1 = (a1hi+a1lo) @ W1^T   (tile 128x128, 2 CTAs/SM)
    gemm_f16<<<dim3(MROWS / 128, 2), 256, GX_SMEM>>>(a1h, a1l, w1h, h1p, FEATD);
    // x2 (fp16 hi/lo) = relu(alpha1 @ h1)
    attn1_kernel<<<BATCH / GB, 256, smem1>>>(h1p, adj, a1, x2h, x2l);
    // h2 = (x2hi+x2lo) @ W2^T
    gemm_f16<<<dim3(MROWS / 128, 2), 256, GX_SMEM>>>(x2h, x2l, w2h, h2p, HID);
    // attn2: softmax out + combined (fp16 hi/lo)
    attn2_kernel<<<BATCH / GB, 256, smem1>>>(h2p, adj, a2, context, cbh, cbl, out);
    // ht = combined @ HW^T  (N=64 heads GEMM)
    gemm_heads<<<BATCH / 128, 256, G3_SMEM>>>(cbh, cbl, hwp, htp);
    // tiny tail
    final_kernel<<<BATCH / 256, 256>>>(htp, base_preds, wh1_b, wh2_w, wh2_b,
                                       wh3_w, wh3_b, rh1_b, rh2_w, rh2_b, out);
}

// round 15
// speedup vs baseline: 3.9646x; 1.1797x over previous
#include <cuda_runtime.h>
#include <cuda_fp16.h>
#include <cstdint>
#include <cstddef>

#define BATCH 16384
#define NND   7
#define FEATD 512
#define HID   256
#define CTXD  256
#define COMB  2048
#define MROWS (BATCH * NND)        // 114688
#define GBA   4                    // batches per attn block

// main GEMM buffer (tile 128x128), XOR-swizzled 64B rows, 3-stage ring
#define XA_HI  0
#define XA_LO  8192
#define XB     16384
#define XSTAGE 24576
#define GX_SMEM (3 * XSTAGE)       // 73728 -> 2 CTAs/SM

// heads GEMM (tile 128x64), XOR-swizzled, double buffer
#define HA_HI  0
#define HA_LO  8192
#define HXB    16384
#define HSTAGE 20480
#define GH_SMEM (2 * HSTAGE)       // 40960 -> 2 CTAs/SM

// ---------------- scratch ---------------------------------------------------
__device__ float  g_h1[(size_t)MROWS * HID];
__device__ float  g_h2[(size_t)MROWS * HID];
__device__ __half g_a1hi[(size_t)MROWS * FEATD];
__device__ __half g_a1lo[(size_t)MROWS * FEATD];
__device__ __half g_x2hi[(size_t)MROWS * HID];
__device__ __half g_x2lo[(size_t)MROWS * HID];
__device__ __half g_combhi[(size_t)BATCH * COMB];
__device__ __half g_comblo[(size_t)BATCH * COMB];
__device__ float  g_ht[(size_t)BATCH * 64];
__device__ __half g_w1h[HID * FEATD];
__device__ __half g_w2h[HID * HID];
__device__ __half g_hw[64 * COMB];

// ---------------- helpers ---------------------------------------------------
__device__ __forceinline__ uint32_t smem_u32(const void* p) {
    uint32_t a;
    asm("{ .reg .u64 t; cvta.to.shared.u64 t, %1; cvt.u32.u64 %0, t; }" : "=r"(a) : "l"(p));
    return a;
}
__device__ __forceinline__ void ldsm4(uint32_t* r, uint32_t addr) {
    asm volatile("ldmatrix.sync.aligned.m8n8.x4.shared.b16 {%0,%1,%2,%3}, [%4];"
                 : "=r"(r[0]), "=r"(r[1]), "=r"(r[2]), "=r"(r[3]) : "r"(addr));
}
__device__ __forceinline__ void mma_f16(float* c, const uint32_t* a, const uint32_t* b) {
    asm volatile(
        "mma.sync.aligned.m16n8k16.row.col.f32.f16.f16.f32 "
        "{%0,%1,%2,%3}, {%4,%5,%6,%7}, {%8,%9}, {%0,%1,%2,%3};"
        : "+f"(c[0]), "+f"(c[1]), "+f"(c[2]), "+f"(c[3])
        : "r"(a[0]), "r"(a[1]), "r"(a[2]), "r"(a[3]), "r"(b[0]), "r"(b[1]));
}
__device__ __forceinline__ void cvt_hilo(float4 v, uint32_t& h0, uint32_t& h1,
                                         uint32_t& l0, uint32_t& l1) {
    __half2 ha = __floats2half2_rn(v.x, v.y);
    __half2 hb = __floats2half2_rn(v.z, v.w);
    float2 fa = __half22float2(ha);
    float2 fb = __half22float2(hb);
    __half2 la = __floats2half2_rn(v.x - fa.x, v.y - fa.y);
    __half2 lb = __floats2half2_rn(v.z - fb.x, v.w - fb.y);
    h0 = *(uint32_t*)&ha; h1 = *(uint32_t*)&hb;
    l0 = *(uint32_t*)&la; l1 = *(uint32_t*)&lb;
}
__device__ __forceinline__ void cpasync16(uint32_t saddr, const void* g) {
    asm volatile("cp.async.cg.shared.global [%0], [%1], 16;" :: "r"(saddr), "l"(g) : "memory");
}
__device__ __forceinline__ void cpasync_commit() {
    asm volatile("cp.async.commit_group;" ::: "memory");
}
__device__ __forceinline__ void cpasync_wait0() {
    asm volatile("cp.async.wait_group 0;" ::: "memory");
}
__device__ __forceinline__ void cpasync_wait1() {
    asm volatile("cp.async.wait_group 1;" ::: "memory");
}
// XOR swizzle for 64B rows: 16B chunk c at row r -> c ^ ((r>>1)&3)
__device__ __forceinline__ uint32_t xsw(int row, int ch) {
    return (uint32_t)(row * 64 + ((ch ^ ((row >> 1) & 3)) << 4));
}

// ---------------------------------------------------------------------------
// converters
// ---------------------------------------------------------------------------
__global__ void convw_kernel(const float* __restrict__ W, __half* __restrict__ H, int n) {
    int i = blockIdx.x * 256 + threadIdx.x;
    if (i < n) H[i] = __float2half_rn(W[i]);
}
__global__ void convhw_kernel(const float* __restrict__ wh1_w, const float* __restrict__ rh1_w,
                              __half* __restrict__ HW) {
    int i = blockIdx.x * 256 + threadIdx.x;
    if (i < 64 * COMB) {
        int row = i >> 11, k = i & (COMB - 1);
        float v = 0.f;
        if (row < 32) v = wh1_w[row * COMB + k];
        else if (row < 48) v = rh1_w[(row - 32) * COMB + k];
        HW[i] = __float2half_rn(v);
    }
}
__global__ void convA_kernel(const float* __restrict__ A, __half* __restrict__ Hi,
                             __half* __restrict__ Lo, int n4) {
    int i = blockIdx.x * 256 + threadIdx.x;
    if (i < n4) {
        float4 v = ((const float4*)A)[i];
        uint32_t h0, h1, l0, l1;
        cvt_hilo(v, h0, h1, l0, l1);
        ((uint2*)Hi)[i] = make_uint2(h0, h1);
        ((uint2*)Lo)[i] = make_uint2(l0, l1);
    }
}

// ---------------------------------------------------------------------------
// fp16 HMMA GEMM, tile 128x128, 2 CTAs/SM, 3-stage cp.async ring.
// C[m,n] = sum_k (Ahi+Alo)*B, 2-term. 8 warps (4m x 2n), warp tile 32x64.
// ---------------------------------------------------------------------------
__global__ void __launch_bounds__(256, 2)
gemm_f16(const __half* __restrict__ Ahi, const __half* __restrict__ Alo,
         const __half* __restrict__ Bh, float* __restrict__ C, int K) {
    extern __shared__ char smem[];
    const uint32_t sb = smem_u32(smem);
    const int tid  = threadIdx.x;
    const int lane = tid & 31;
    const int wid  = tid >> 5;
    const int wm   = wid & 3;
    const int wn   = wid >> 2;
    const int m0   = blockIdx.x * 128;
    const int n0   = blockIdx.y * 128;
    const int nk   = K >> 5;

    const int srow = tid >> 1;
    const int sch  = (tid & 1) * 2;
    const __half* AhiG = Ahi + (size_t)(m0 + srow) * K + sch * 8;
    const __half* AloG = Alo + (size_t)(m0 + srow) * K + sch * 8;
    const __half* BG   = Bh  + (size_t)(n0 + srow) * K + sch * 8;
    const uint32_t sAh0 = sb + XA_HI + xsw(srow, sch);
    const uint32_t sAh1 = sb + XA_HI + xsw(srow, sch + 1);
    const uint32_t sAl0 = sb + XA_LO + xsw(srow, sch);
    const uint32_t sAl1 = sb + XA_LO + xsw(srow, sch + 1);
    const uint32_t sB0  = sb + XB + xsw(srow, sch);
    const uint32_t sB1  = sb + XB + xsw(srow, sch + 1);

    const int arow0 = wm * 32 + (lane & 15);
    const int asel  = lane >> 4;
    const uint32_t abase0 = sb + XA_HI + arow0 * 64;
    const uint32_t abase1 = sb + XA_HI + (arow0 + 16) * 64;
    const int ars0 = (arow0 >> 1) & 3;
    const int ars1 = ((arow0 + 16) >> 1) & 3;
    const int brow0 = wn * 64 + (lane & 7) + ((lane >> 4) << 3);
    const int bsel  = (lane >> 3) & 1;
    uint32_t bbase[4]; int brs[4];
#pragma unroll
    for (int p = 0; p < 4; ++p) {
        bbase[p] = sb + XB + (brow0 + 16 * p) * 64;
        brs[p]   = ((brow0 + 16 * p) >> 1) & 3;
    }

    float acc[2][8][4];
#pragma unroll
    for (int i = 0; i < 2; ++i)
#pragma unroll
        for (int j = 0; j < 8; ++j)
#pragma unroll
            for (int q = 0; q < 4; ++q) acc[i][j][q] = 0.f;

    // prologue: issue stages 0 and 1
#pragma unroll
    for (int s = 0; s < 2; ++s) {
        const uint32_t nb = s * XSTAGE;
        const int go = s * 32;
        cpasync16(sAh0 + nb, AhiG + go);
        cpasync16(sAh1 + nb, AhiG + go + 8);
        cpasync16(sAl0 + nb, AloG + go);
        cpasync16(sAl1 + nb, AloG + go + 8);
        cpasync16(sB0 + nb, BG + go);
        cpasync16(sB1 + nb, BG + go + 8);
        cpasync_commit();
    }

    int buf = 0;
    for (int kt = 0; kt < nk; ++kt) {
        if (kt + 1 < nk) cpasync_wait1(); else cpasync_wait0();
        __syncthreads();

        const uint32_t bufo = buf * XSTAGE;
#pragma unroll
        for (int ks = 0; ks < 2; ++ks) {
            const int ca = ks * 2 + asel;
            const int cbsel = ks * 2 + bsel;
            uint32_t ah[2][4], al[2][4], bh[4][4];
            ldsm4(ah[0], bufo + abase0 + ((ca ^ ars0) << 4));
            ldsm4(ah[1], bufo + abase1 + ((ca ^ ars1) << 4));
            ldsm4(al[0], bufo + abase0 + (XA_LO - XA_HI) + ((ca ^ ars0) << 4));
            ldsm4(al[1], bufo + abase1 + (XA_LO - XA_HI) + ((ca ^ ars1) << 4));
#pragma unroll
            for (int p = 0; p < 4; ++p)
                ldsm4(bh[p], bufo + bbase[p] + ((cbsel ^ brs[p]) << 4));
#pragma unroll
            for (int p = 0; p < 4; ++p)
#pragma unroll
                for (int mi = 0; mi < 2; ++mi) {
                    mma_f16(acc[mi][2 * p],     ah[mi], bh[p]);
                    mma_f16(acc[mi][2 * p + 1], ah[mi], bh[p] + 2);
                }
#pragma unroll
            for (int p = 0; p < 4; ++p)
#pragma unroll
                for (int mi = 0; mi < 2; ++mi) {
                    mma_f16(acc[mi][2 * p],     al[mi], bh[p]);
                    mma_f16(acc[mi][2 * p + 1], al[mi], bh[p] + 2);
                }
        }

        if (kt + 2 < nk) {
            // buffer (kt+2)%3 == old stage kt-1; all warps synced above.
            const uint32_t nb = ((kt + 2) % 3) * XSTAGE;
            const int go = (kt + 2) * 32;
            cpasync16(sAh0 + nb, AhiG + go);
            cpasync16(sAh1 + nb, AhiG + go + 8);
            cpasync16(sAl0 + nb, AloG + go);
            cpasync16(sAl1 + nb, AloG + go + 8);
            cpasync16(sB0 + nb, BG + go);
            cpasync16(sB1 + nb, BG + go + 8);
            cpasync_commit();
        }
        buf = (buf + 1 == 3) ? 0 : buf + 1;
    }

    const int g  = lane >> 2;
    const int cq = (lane & 3) * 2;
#pragma unroll
    for (int mi = 0; mi < 2; ++mi) {
        const int row0 = m0 + wm * 32 + mi * 16 + g;
        float* C0 = C + (size_t)row0 * 256 + n0 + wn * 64;
        float* C1 = C0 + (size_t)8 * 256;
#pragma unroll
        for (int ni = 0; ni < 8; ++ni) {
            *(float2*)(C0 + ni * 8 + cq) = make_float2(acc[mi][ni][0], acc[mi][ni][1]);
            *(float2*)(C1 + ni * 8 + cq) = make_float2(acc[mi][ni][2], acc[mi][ni][3]);
        }
    }
}

// ---------------------------------------------------------------------------
// Heads GEMM (tile 128x64), XOR-swizzled, 2 CTAs/SM.
// ht[b,n] = sum_k (Chi+Clo)[b,k]*HW[n,k], K=2048. Warp tile 32x32.
// ---------------------------------------------------------------------------
__global__ void __launch_bounds__(256, 2)
gemm_heads(const __half* __restrict__ Ahi, const __half* __restrict__ Alo,
           const __half* __restrict__ Bh, float* __restrict__ C) {
    extern __shared__ char smem[];
    const uint32_t sb = smem_u32(smem);
    const int tid  = threadIdx.x;
    const int lane = tid & 31;
    const int wid  = tid >> 5;
    const int wm   = wid & 3;
    const int wn   = wid >> 2;
    const int m0   = blockIdx.x * 128;
    const int nk   = COMB >> 5;   // 64

    const int srow = tid >> 1;
    const int sch  = (tid & 1) * 2;
    const __half* AhiG = Ahi + (size_t)(m0 + srow) * COMB + sch * 8;
    const __half* AloG = Alo + (size_t)(m0 + srow) * COMB + sch * 8;
    const uint32_t sAh0 = sb + HA_HI + xsw(srow, sch);
    const uint32_t sAh1 = sb + HA_HI + xsw(srow, sch + 1);
    const uint32_t sAl0 = sb + HA_LO + xsw(srow, sch);
    const uint32_t sAl1 = sb + HA_LO + xsw(srow, sch + 1);
    const int brow = tid >> 2, bch = tid & 3;
    const __half* BG = Bh + (size_t)brow * COMB + bch * 8;
    const uint32_t sB = sb + HXB + xsw(brow, bch);

    const int arow0 = wm * 32 + (lane & 15);
    const int asel  = lane >> 4;
    const uint32_t abase0 = sb + HA_HI + arow0 * 64;
    const uint32_t abase1 = sb + HA_HI + (arow0 + 16) * 64;
    const int ars0 = (arow0 >> 1) & 3;
    const int ars1 = ((arow0 + 16) >> 1) & 3;
    const int brow0 = wn * 32 + (lane & 7) + ((lane >> 4) << 3);
    const int bsel  = (lane >> 3) & 1;
    uint32_t bbase[2]; int brs[2];
#pragma unroll
    for (int p = 0; p < 2; ++p) {
        bbase[p] = sb + HXB + (brow0 + 16 * p) * 64;
        brs[p]   = ((brow0 + 16 * p) >> 1) & 3;
    }

    float acc[2][4][4];
#pragma unroll
    for (int i = 0; i < 2; ++i)
#pragma unroll
        for (int j = 0; j < 4; ++j)
#pragma unroll
            for (int q = 0; q < 4; ++q) acc[i][j][q] = 0.f;

    {
        cpasync16(sAh0, AhiG);
        cpasync16(sAh1, AhiG + 8);
        cpasync16(sAl0, AloG);
        cpasync16(sAl1, AloG + 8);
        cpasync16(sB, BG);
        cpasync_commit();
        cpasync_wait0();
    }
    __syncthreads();

    for (int kt = 0; kt < nk; ++kt) {
        const uint32_t bufo = (kt & 1) * HSTAGE;
        const bool more = (kt + 1 < nk);
        if (more) {
            const uint32_t nb = ((kt + 1) & 1) * HSTAGE;
            const int go = (kt + 1) * 32;
            cpasync16(sAh0 + nb, AhiG + go);
            cpasync16(sAh1 + nb, AhiG + go + 8);
            cpasync16(sAl0 + nb, AloG + go);
            cpasync16(sAl1 + nb, AloG + go + 8);
            cpasync16(sB + nb, BG + go);
            cpasync_commit();
        }

#pragma unroll
        for (int ks = 0; ks < 2; ++ks) {
            const int ca = ks * 2 + asel;
            const int cbsel = ks * 2 + bsel;
            uint32_t ah[2][4], al[2][4], bh[2][4];
            ldsm4(ah[0], bufo + abase0 + ((ca ^ ars0) << 4));
            ldsm4(ah[1], bufo + abase1 + ((ca ^ ars1) << 4));
            ldsm4(al[0], bufo + abase0 + (HA_LO - HA_HI) + ((ca ^ ars0) << 4));
            ldsm4(al[1], bufo + abase1 + (HA_LO - HA_HI) + ((ca ^ ars1) << 4));
#pragma unroll
            for (int p = 0; p < 2; ++p)
                ldsm4(bh[p], bufo + bbase[p] + ((cbsel ^ brs[p]) << 4));
#pragma unroll
            for (int p = 0; p < 2; ++p)
#pragma unroll
                for (int mi = 0; mi < 2; ++mi) {
                    mma_f16(acc[mi][2 * p],     ah[mi], bh[p]);
                    mma_f16(acc[mi][2 * p + 1], ah[mi], bh[p] + 2);
                    mma_f16(acc[mi][2 * p],     al[mi], bh[p]);
                    mma_f16(acc[mi][2 * p + 1], al[mi], bh[p] + 2);
                }
        }

        if (more) {
            cpasync_wait0();
            __syncthreads();
        }
    }

    const int g  = lane >> 2;
    const int cq = (lane & 3) * 2;
#pragma unroll
    for (int mi = 0; mi < 2; ++mi) {
        const int row0 = m0 + wm * 32 + mi * 16 + g;
        float* C0 = C + (size_t)row0 * 64 + wn * 32;
        float* C1 = C0 + (size_t)8 * 64;
#pragma unroll
        for (int ni = 0; ni < 4; ++ni) {
            *(float2*)(C0 + ni * 8 + cq) = make_float2(acc[mi][ni][0], acc[mi][ni][1]);
            *(float2*)(C1 + ni * 8 + cq) = make_float2(acc[mi][ni][2], acc[mi][ni][3]);
        }
    }
}

// ---------------------------------------------------------------------------
// attn1 (GBA=4, 31KB smem -> 7 CTAs/SM): x2 = relu(alpha1 @ h1) as fp16 hi/lo
// ---------------------------------------------------------------------------
__global__ void __launch_bounds__(256)
attn1_kernel(const float* __restrict__ h1, const float* __restrict__ adj,
             const float* __restrict__ a1, __half* __restrict__ x2hi,
             __half* __restrict__ x2lo) {
    extern __shared__ float sm[];
    float* hs   = sm;           // 7168
    float* av   = sm + 7168;    // 512
    float* sadj = sm + 7680;    // 49
    float* ssi  = sm + 7729;    // 28
    float* ssj  = sm + 7757;    // 28
    float* sal  = sm + 7785;    // 196
    const int tid = threadIdx.x;
    const int w = tid >> 5, lane = tid & 31;
    const size_t base = (size_t)blockIdx.x * (GBA * NND * HID);

    {
        const float4* src = (const float4*)(h1 + base);
        float4* dst = (float4*)hs;
        for (int i = tid; i < GBA * NND * HID / 4; i += 256) dst[i] = src[i];
        if (tid < 128) ((float4*)av)[tid] = ((const float4*)a1)[tid];
        if (tid < 49) sadj[tid] = adj[tid];
    }
    __syncthreads();

    for (int r = w; r < GBA * NND; r += 8) {
        const float* hr = hs + r * HID;
        float si = 0.f, sj = 0.f;
#pragma unroll
        for (int k = lane; k < HID; k += 32) {
            const float hv = hr[k];
            si = fmaf(hv, av[k], si);
            sj = fmaf(hv, av[HID + k], sj);
        }
#pragma unroll
        for (int off = 16; off > 0; off >>= 1) {
            si += __shfl_xor_sync(0xffffffffu, si, off);
            sj += __shfl_xor_sync(0xffffffffu, sj, off);
        }
        if (lane == 0) { ssi[r] = si; ssj[r] = sj; }
    }
    __syncthreads();

    if (tid < GBA * NND) {
        const int b = tid / 7, i = tid - b * 7;
        float e[7]; float mx = -3.0e38f;
#pragma unroll
        for (int j = 0; j < 7; ++j) {
            float v = ssi[b * 7 + i] + ssj[b * 7 + j];
            v = (v > 0.f) ? v : 0.2f * v;
            if (sadj[i * 7 + j] == 0.f) v = -3.0e38f;
            e[j] = v; mx = fmaxf(mx, v);
        }
        float s = 0.f;
#pragma unroll
        for (int j = 0; j < 7; ++j) {
            const float ex = (e[j] < -1.0e38f) ? 0.f : __expf(e[j] - mx);
            e[j] = ex; s += ex;
        }
        const float inv = 1.f / s;
#pragma unroll
        for (int j = 0; j < 7; ++j) sal[tid * 7 + j] = e[j] * inv;
    }
    __syncthreads();

    for (int r = w; r < GBA * NND; r += 8) {
        const int b = r / 7;
        const float* hb = hs + b * 7 * HID;
        const float* alr = sal + r * 7;
        float a0 = alr[0], a1v = alr[1], a2v = alr[2], a3 = alr[3],
              a4 = alr[4], a5 = alr[5], a6 = alr[6];
#pragma unroll
        for (int d4 = lane; d4 < 64; d4 += 32) {
            const float4* p0 = (const float4*)(hb) + d4;
            float4 h0 = p0[0],  h1v = p0[64],  h2 = p0[128], h3 = p0[192],
                   h4 = p0[256], h5 = p0[320], h6 = p0[384];
            float4 o;
            o.x = a0*h0.x + a1v*h1v.x + a2v*h2.x + a3*h3.x + a4*h4.x + a5*h5.x + a6*h6.x;
            o.y = a0*h0.y + a1v*h1v.y + a2v*h2.y + a3*h3.y + a4*h4.y + a5*h5.y + a6*h6.y;
            o.z = a0*h0.z + a1v*h1v.z + a2v*h2.z + a3*h3.z + a4*h4.z + a5*h5.z + a6*h6.z;
            o.w = a0*h0.w + a1v*h1v.w + a2v*h2.w + a3*h3.w + a4*h4.w + a5*h5.w + a6*h6.w;
            o.x = fmaxf(o.x, 0.f); o.y = fmaxf(o.y, 0.f);
            o.z = fmaxf(o.z, 0.f); o.w = fmaxf(o.w, 0.f);
            uint32_t h0p, h1p, l0p, l1p;
            cvt_hilo(o, h0p, h1p, l0p, l1p);
            const size_t off = base + r * HID + d4 * 4;
            *(uint2*)(x2hi + off) = make_uint2(h0p, h1p);
            *(uint2*)(x2lo + off) = make_uint2(l0p, l1p);
        }
    }
}

// ---------------------------------------------------------------------------
// attn2 (GBA=4): softmax out + aggregation -> combined (fp16 hi/lo) + context
// ---------------------------------------------------------------------------
__global__ void __launch_bounds__(256)
attn2_kernel(const float* __restrict__ h2, const float* __restrict__ adj,
             const float* __restrict__ a2, const float* __restrict__ context,
             __half* __restrict__ chi, __half* __restrict__ clo,
             float* __restrict__ out) {
    extern __shared__ float sm[];
    float* hs   = sm;           // 7168
    float* av   = sm + 7168;    // 512
    float* sadj = sm + 7680;    // 49
    float* ssi  = sm + 7729;    // 28
    float* ssj  = sm + 7757;    // 28
    float* sal  = sm + 7785;    // 196
    const int tid = threadIdx.x;
    const int w = tid >> 5, lane = tid & 31;
    const int b0 = blockIdx.x * GBA;
    const size_t base = (size_t)blockIdx.x * (GBA * NND * HID);

    {
        const float4* src = (const float4*)(h2 + base);
        float4* dst = (float4*)hs;
        for (int i = tid; i < GBA * NND * HID / 4; i += 256) dst[i] = src[i];
        if (tid < 128) ((float4*)av)[tid] = ((const float4*)a2)[tid];
        if (tid < 49) sadj[tid] = adj[tid];
    }
    __syncthreads();

    for (int r = w; r < GBA * NND; r += 8) {
        const float* hr = hs + r * HID;
        float si = 0.f, sj = 0.f;
#pragma unroll
        for (int k = lane; k < HID; k += 32) {
            const float hv = hr[k];
            si = fmaf(hv, av[k], si);
            sj = fmaf(hv, av[HID + k], sj);
        }
#pragma unroll
        for (int off = 16; off > 0; off >>= 1) {
            si += __shfl_xor_sync(0xffffffffu, si, off);
            sj += __shfl_xor_sync(0xffffffffu, sj, off);
        }
        if (lane == 0) { ssi[r] = si; ssj[r] = sj; }
    }
    __syncthreads();

    if (tid < GBA * NND) {
        const int b = tid / 7, i = tid - b * 7;
        float e[7]; float mx = -3.0e38f;
#pragma unroll
        for (int j = 0; j < 7; ++j) {
            float v = ssi[b * 7 + i] + ssj[b * 7 + j];
            v = (v > 0.f) ? v : 0.2f * v;
            if (sadj[i * 7 + j] == 0.f) v = -3.0e38f;
            e[j] = v; mx = fmaxf(mx, v);
        }
        float s = 0.f;
#pragma unroll
        for (int j = 0; j < 7; ++j) {
            const float ex = (e[j] < -1.0e38f) ? 0.f : __expf(e[j] - mx);
            e[j] = ex; s += ex;
        }
        const float inv = 1.f / s;
        float* oa = out + (size_t)6 * BATCH + (size_t)(b0 + b) * 49 + i * 7;
#pragma unroll
        for (int j = 0; j < 7; ++j) {
            const float al = e[j] * inv;
            sal[tid * 7 + j] = al;
            oa[j] = al;
        }
    }
    __syncthreads();

    for (int r = w; r < GBA * NND; r += 8) {
        const int b = r / 7;
        const int rem = r - b * 7;
        const float* hb = hs + b * 7 * HID;
        const float* alr = sal + r * 7;
        float a0 = alr[0], a1v = alr[1], a2v = alr[2], a3 = alr[3],
              a4 = alr[4], a5 = alr[5], a6 = alr[6];
        const size_t cb = (size_t)(b0 + b) * COMB;
#pragma unroll
        for (int d4 = lane; d4 < 64; d4 += 32) {
            const float4* p0 = (const float4*)(hb) + d4;
            float4 h0 = p0[0],  h1v = p0[64],  h2 = p0[128], h3 = p0[192],
                   h4 = p0[256], h5 = p0[320], h6 = p0[384];
            float4 o;
            o.x = a0*h0.x + a1v*h1v.x + a2v*h2.x + a3*h3.x + a4*h4.x + a5*h5.x + a6*h6.x;
            o.y = a0*h0.y + a1v*h1v.y + a2v*h2.y + a3*h3.y + a4*h4.y + a5*h5.y + a6*h6.y;
            o.z = a0*h0.z + a1v*h1v.z + a2v*h2.z + a3*h3.z + a4*h4.z + a5*h5.z + a6*h6.z;
            o.w = a0*h0.w + a1v*h1v.w + a2v*h2.w + a3*h3.w + a4*h4.w + a5*h5.w + a6*h6.w;
            o.x = fmaxf(o.x, 0.f); o.y = fmaxf(o.y, 0.f);
            o.z = fmaxf(o.z, 0.f); o.w = fmaxf(o.w, 0.f);
            uint32_t h0p, h1p, l0p, l1p;
            cvt_hilo(o, h0p, h1p, l0p, l1p);
            const size_t off = cb + rem * HID + d4 * 4;
            *(uint2*)(chi + off) = make_uint2(h0p, h1p);
            *(uint2*)(clo + off) = make_uint2(l0p, l1p);
        }
    }
    for (int idx = tid; idx < GBA * CTXD / 4; idx += 256) {
        const int b = idx >> 6, c4 = idx & 63;
        float4 v = ((const float4*)context)[(size_t)(b0 + b) * 64 + c4];
        uint32_t h0p, h1p, l0p, l1p;
        cvt_hilo(v, h0p, h1p, l0p, l1p);
        const size_t off = (size_t)(b0 + b) * COMB + NND * HID + c4 * 4;
        *(uint2*)(chi + off) = make_uint2(h0p, h1p);
        *(uint2*)(clo + off) = make_uint2(l0p, l1p);
    }
}

// ---------------------------------------------------------------------------
// final heads tail. out = [pred(B) | weights(B*5) | attn2(B*49)]
// ---------------------------------------------------------------------------
__global__ void __launch_bounds__(256)
final_kernel(const float* __restrict__ ht, const float* __restrict__ base_preds,
             const float* __restrict__ wh1_b,
             const float* __restrict__ wh2_w, const float* __restrict__ wh2_b,
             const float* __restrict__ wh3_w, const float* __restrict__ wh3_b,
             const float* __restrict__ rh1_b,
             const float* __restrict__ rh2_w, const float* __restrict__ rh2_b,
             float* __restrict__ out) {
    const int b = blockIdx.x * 256 + threadIdx.x;
    if (b >= BATCH) return;
    const float* h = ht + (size_t)b * 64;

    float t1[32];
#pragma unroll
    for (int k = 0; k < 32; ++k) t1[k] = fmaxf(h[k] + wh1_b[k], 0.f);
    float t2[16];
#pragma unroll
    for (int o = 0; o < 16; ++o) {
        float s = wh2_b[o];
#pragma unroll
        for (int k = 0; k < 32; ++k) s = fmaf(t1[k], wh2_w[o * 32 + k], s);
        t2[o] = fmaxf(s, 0.f);
    }
    float raw[5]; float mx = -3.0e38f;
#pragma unroll
    for (int o = 0; o < 5; ++o) {
        float s = wh3_b[o];
#pragma unroll
        for (int k = 0; k < 16; ++k) s = fmaf(t2[k], wh3_w[o * 16 + k], s);
        raw[o] = s; mx = fmaxf(mx, s);
    }
    float se = 0.f;
#pragma unroll
    for (int o = 0; o < 5; ++o) { raw[o] = __expf(raw[o] - mx); se += raw[o]; }
    const float inv = 1.f / se;
    float wp = 0.f;
#pragma unroll
    for (int o = 0; o < 5; ++o) {
        const float wt = raw[o] * inv;
        out[BATCH + (size_t)b * 5 + o] = wt;
        wp = fmaf(wt, base_preds[(size_t)b * 5 + o], wp);
    }
    float rr = rh2_b[0];
#pragma unroll
    for (int k = 0; k < 16; ++k)
        rr = fmaf(tanhf(h[32 + k] + rh1_b[k]), rh2_w[k], rr);
    out[b] = fmaxf(wp + rr * 0.05f, 0.05f);
}

// ---------------------------------------------------------------------------
extern "C" void kernel_launch(void* const* d_in, const int* in_sizes, int n_in,
                              void* d_out, int out_size) {
    const float* node_feats = (const float*)d_in[0];
    const float* adj        = (const float*)d_in[1];
    const float* context    = (const float*)d_in[2];
    const float* base_preds = (const float*)d_in[3];
    const float* W1    = (const float*)d_in[4];
    const float* a1    = (const float*)d_in[5];
    const float* W2    = (const float*)d_in[6];
    const float* a2    = (const float*)d_in[7];
    const float* wh1_w = (const float*)d_in[8];
    const float* wh1_b = (const float*)d_in[9];
    const float* wh2_w = (const float*)d_in[10];
    const float* wh2_b = (const float*)d_in[11];
    const float* wh3_w = (const float*)d_in[12];
    const float* wh3_b = (const float*)d_in[13];
    const float* rh1_w = (const float*)d_in[14];
    const float* rh1_b = (const float*)d_in[15];
    const float* rh2_w = (const float*)d_in[16];
    const float* rh2_b = (const float*)d_in[17];
    float* out = (float*)d_out;

    float *h1p, *h2p, *htp;
    __half *a1h, *a1l, *x2h, *x2l, *w1h, *w2h, *hwp, *cbh, *cbl;
    cudaGetSymbolAddress((void**)&h1p, g_h1);
    cudaGetSymbolAddress((void**)&h2p, g_h2);
    cudaGetSymbolAddress((void**)&htp, g_ht);
    cudaGetSymbolAddress((void**)&a1h, g_a1hi);
    cudaGetSymbolAddress((void**)&a1l, g_a1lo);
    cudaGetSymbolAddress((void**)&x2h, g_x2hi);
    cudaGetSymbolAddress((void**)&x2l, g_x2lo);
    cudaGetSymbolAddress((void**)&w1h, g_w1h);
    cudaGetSymbolAddress((void**)&w2h, g_w2h);
    cudaGetSymbolAddress((void**)&hwp, g_hw);
    cudaGetSymbolAddress((void**)&cbh, g_combhi);
    cudaGetSymbolAddress((void**)&cbl, g_comblo);

    const int smemA = 7981 * 4;
    cudaFuncSetAttribute(gemm_f16, cudaFuncAttributeMaxDynamicSharedMemorySize, GX_SMEM);
    cudaFuncSetAttribute(gemm_heads, cudaFuncAttributeMaxDynamicSharedMemorySize, GH_SMEM);
    cudaFuncSetAttribute(attn1_kernel, cudaFuncAttributeMaxDynamicSharedMemorySize, smemA);
    cudaFuncSetAttribute(attn2_kernel, cudaFuncAttributeMaxDynamicSharedMemorySize, smemA);

    convw_kernel<<<(HID * FEATD + 255) / 256, 256>>>(W1, w1h, HID * FEATD);
    convw_kernel<<<(HID * HID + 255) / 256, 256>>>(W2, w2h, HID * HID);
    convhw_kernel<<<(64 * COMB + 255) / 256, 256>>>(wh1_w, rh1_w, hwp);
    convA_kernel<<<(MROWS * FEATD / 4 + 255) / 256, 256>>>(node_feats, a1h, a1l,
                                                           MROWS * FEATD / 4);

    // h1 = (a1hi+a1lo) @ W1^T   (3-stage ring, 2 CTAs/SM)
    gemm_f16<<<dim3(MROWS / 128, 2), 256, GX_SMEM>>>(a1h, a1l, w1h, h1p, FEATD);
    // x2 (fp16 hi/lo) = relu(alpha1 @ h1)
    attn1_kernel<<<BATCH / GBA, 256, smemA>>>(h1p, adj, a1, x2h, x2l);
    // h2 = (x2hi+x2lo) @ W2^T
    gemm_f16<<<dim3(MROWS / 128, 2), 256, GX_SMEM>>>(x2h, x2l, w2h, h2p, HID);
    // attn2: softmax out + combined (fp16 hi/lo)
    attn2_kernel<<<BATCH / GBA, 256, smemA>>>(h2p, adj, a2, context, cbh, cbl, out);
    // ht = combined @ HW^T  (N=64 heads GEMM, 2 CTAs/SM)
    gemm_heads<<<BATCH / 128, 256, GH_SMEM>>>(cbh, cbl, hwp, htp);
    // tiny tail
    final_kernel<<<BATCH / 256, 256>>>(htp, base_preds, wh1_b, wh2_w, wh2_b,
                                       wh3_w, wh3_b, rh1_b, rh2_w, rh2_b, out);
}

// round 16
// speedup vs baseline: 4.0107x; 1.0116x over previous
#include <cuda_runtime.h>
#include <cuda_fp16.h>
#include <cstdint>
#include <cstddef>

#define BATCH 16384
#define NND   7
#define FEATD 512
#define HID   256
#define CTXD  256
#define COMB  2048
#define MROWS (BATCH * NND)        // 114688
#define GBA   4                    // batches per attn block

// main GEMM buffer (tile 128x128), XOR-swizzled 64B rows, 3-stage ring
#define XA_HI  0
#define XA_LO  8192
#define XB     16384
#define XSTAGE 24576
#define GX_SMEM (3 * XSTAGE)       // 73728 -> 2 CTAs/SM

// heads GEMM (tile 128x64), XOR-swizzled, double buffer
#define HA_HI  0
#define HA_LO  8192
#define HXB    16384
#define HSTAGE 20480
#define GH_SMEM (2 * HSTAGE)       // 40960 -> 2 CTAs/SM

// ---------------- scratch ---------------------------------------------------
__device__ float  g_h1[(size_t)MROWS * HID];
__device__ float  g_h2[(size_t)MROWS * HID];
__device__ __half g_a1hi[(size_t)MROWS * FEATD];
__device__ __half g_a1lo[(size_t)MROWS * FEATD];
__device__ __half g_x2hi[(size_t)MROWS * HID];
__device__ __half g_x2lo[(size_t)MROWS * HID];
__device__ __half g_combhi[(size_t)BATCH * COMB];
__device__ __half g_comblo[(size_t)BATCH * COMB];
__device__ float  g_ht[(size_t)BATCH * 64];
__device__ __half g_w1h[HID * FEATD];
__device__ __half g_w2h[HID * HID];
__device__ __half g_hw[64 * COMB];

// ---------------- helpers ---------------------------------------------------
__device__ __forceinline__ uint32_t smem_u32(const void* p) {
    uint32_t a;
    asm("{ .reg .u64 t; cvta.to.shared.u64 t, %1; cvt.u32.u64 %0, t; }" : "=r"(a) : "l"(p));
    return a;
}
__device__ __forceinline__ void ldsm4(uint32_t* r, uint32_t addr) {
    asm volatile("ldmatrix.sync.aligned.m8n8.x4.shared.b16 {%0,%1,%2,%3}, [%4];"
                 : "=r"(r[0]), "=r"(r[1]), "=r"(r[2]), "=r"(r[3]) : "r"(addr));
}
__device__ __forceinline__ void mma_f16(float* c, const uint32_t* a, const uint32_t* b) {
    asm volatile(
        "mma.sync.aligned.m16n8k16.row.col.f32.f16.f16.f32 "
        "{%0,%1,%2,%3}, {%4,%5,%6,%7}, {%8,%9}, {%0,%1,%2,%3};"
        : "+f"(c[0]), "+f"(c[1]), "+f"(c[2]), "+f"(c[3])
        : "r"(a[0]), "r"(a[1]), "r"(a[2]), "r"(a[3]), "r"(b[0]), "r"(b[1]));
}
__device__ __forceinline__ void cvt_hilo(float4 v, uint32_t& h0, uint32_t& h1,
                                         uint32_t& l0, uint32_t& l1) {
    __half2 ha = __floats2half2_rn(v.x, v.y);
    __half2 hb = __floats2half2_rn(v.z, v.w);
    float2 fa = __half22float2(ha);
    float2 fb = __half22float2(hb);
    __half2 la = __floats2half2_rn(v.x - fa.x, v.y - fa.y);
    __half2 lb = __floats2half2_rn(v.z - fb.x, v.w - fb.y);
    h0 = *(uint32_t*)&ha; h1 = *(uint32_t*)&hb;
    l0 = *(uint32_t*)&la; l1 = *(uint32_t*)&lb;
}
__device__ __forceinline__ void cpasync16(uint32_t saddr, const void* g) {
    asm volatile("cp.async.cg.shared.global [%0], [%1], 16;" :: "r"(saddr), "l"(g) : "memory");
}
__device__ __forceinline__ void cpasync_commit() {
    asm volatile("cp.async.commit_group;" ::: "memory");
}
__device__ __forceinline__ void cpasync_wait0() {
    asm volatile("cp.async.wait_group 0;" ::: "memory");
}
__device__ __forceinline__ void cpasync_wait1() {
    asm volatile("cp.async.wait_group 1;" ::: "memory");
}
// XOR swizzle for 64B rows: 16B chunk c at row r -> c ^ ((r>>1)&3)
__device__ __forceinline__ uint32_t xsw(int row, int ch) {
    return (uint32_t)(row * 64 + ((ch ^ ((row >> 1) & 3)) << 4));
}

// ---------------------------------------------------------------------------
// converters
// ---------------------------------------------------------------------------
__global__ void convw_kernel(const float* __restrict__ W, __half* __restrict__ H, int n) {
    int i = blockIdx.x * 256 + threadIdx.x;
    if (i < n) H[i] = __float2half_rn(W[i]);
}
__global__ void convhw_kernel(const float* __restrict__ wh1_w, const float* __restrict__ rh1_w,
                              __half* __restrict__ HW) {
    int i = blockIdx.x * 256 + threadIdx.x;
    if (i < 64 * COMB) {
        int row = i >> 11, k = i & (COMB - 1);
        float v = 0.f;
        if (row < 32) v = wh1_w[row * COMB + k];
        else if (row < 48) v = rh1_w[(row - 32) * COMB + k];
        HW[i] = __float2half_rn(v);
    }
}
__global__ void convA_kernel(const float* __restrict__ A, __half* __restrict__ Hi,
                             __half* __restrict__ Lo, int n4) {
    int i = blockIdx.x * 256 + threadIdx.x;
    if (i < n4) {
        float4 v = ((const float4*)A)[i];
        uint32_t h0, h1, l0, l1;
        cvt_hilo(v, h0, h1, l0, l1);
        ((uint2*)Hi)[i] = make_uint2(h0, h1);
        ((uint2*)Lo)[i] = make_uint2(l0, l1);
    }
}

// ---------------------------------------------------------------------------
// fp16 HMMA GEMM, tile 128x128, 2 CTAs/SM, 3-stage cp.async ring.
// GRID IS (N/128, M/128): n-half varies fastest so the 2 CTAs sharing an
// A-tile are launch-adjacent -> second A read hits L2 (halves A DRAM traffic).
// ---------------------------------------------------------------------------
__global__ void __launch_bounds__(256, 2)
gemm_f16(const __half* __restrict__ Ahi, const __half* __restrict__ Alo,
         const __half* __restrict__ Bh, float* __restrict__ C, int K) {
    extern __shared__ char smem[];
    const uint32_t sb = smem_u32(smem);
    const int tid  = threadIdx.x;
    const int lane = tid & 31;
    const int wid  = tid >> 5;
    const int wm   = wid & 3;
    const int wn   = wid >> 2;
    const int m0   = blockIdx.y * 128;     // grid-transposed
    const int n0   = blockIdx.x * 128;
    const int nk   = K >> 5;

    const int srow = tid >> 1;
    const int sch  = (tid & 1) * 2;
    const __half* AhiG = Ahi + (size_t)(m0 + srow) * K + sch * 8;
    const __half* AloG = Alo + (size_t)(m0 + srow) * K + sch * 8;
    const __half* BG   = Bh  + (size_t)(n0 + srow) * K + sch * 8;
    const uint32_t sAh0 = sb + XA_HI + xsw(srow, sch);
    const uint32_t sAh1 = sb + XA_HI + xsw(srow, sch + 1);
    const uint32_t sAl0 = sb + XA_LO + xsw(srow, sch);
    const uint32_t sAl1 = sb + XA_LO + xsw(srow, sch + 1);
    const uint32_t sB0  = sb + XB + xsw(srow, sch);
    const uint32_t sB1  = sb + XB + xsw(srow, sch + 1);

    const int arow0 = wm * 32 + (lane & 15);
    const int asel  = lane >> 4;
    const uint32_t abase0 = sb + XA_HI + arow0 * 64;
    const uint32_t abase1 = sb + XA_HI + (arow0 + 16) * 64;
    const int ars0 = (arow0 >> 1) & 3;
    const int ars1 = ((arow0 + 16) >> 1) & 3;
    const int brow0 = wn * 64 + (lane & 7) + ((lane >> 4) << 3);
    const int bsel  = (lane >> 3) & 1;
    uint32_t bbase[4]; int brs[4];
#pragma unroll
    for (int p = 0; p < 4; ++p) {
        bbase[p] = sb + XB + (brow0 + 16 * p) * 64;
        brs[p]   = ((brow0 + 16 * p) >> 1) & 3;
    }

    float acc[2][8][4];
#pragma unroll
    for (int i = 0; i < 2; ++i)
#pragma unroll
        for (int j = 0; j < 8; ++j)
#pragma unroll
            for (int q = 0; q < 4; ++q) acc[i][j][q] = 0.f;

    // prologue: issue stages 0 and 1
#pragma unroll
    for (int s = 0; s < 2; ++s) {
        const uint32_t nb = s * XSTAGE;
        const int go = s * 32;
        cpasync16(sAh0 + nb, AhiG + go);
        cpasync16(sAh1 + nb, AhiG + go + 8);
        cpasync16(sAl0 + nb, AloG + go);
        cpasync16(sAl1 + nb, AloG + go + 8);
        cpasync16(sB0 + nb, BG + go);
        cpasync16(sB1 + nb, BG + go + 8);
        cpasync_commit();
    }

    int buf = 0;
    for (int kt = 0; kt < nk; ++kt) {
        if (kt + 1 < nk) cpasync_wait1(); else cpasync_wait0();
        __syncthreads();

        const uint32_t bufo = buf * XSTAGE;
#pragma unroll
        for (int ks = 0; ks < 2; ++ks) {
            const int ca = ks * 2 + asel;
            const int cbsel = ks * 2 + bsel;
            uint32_t ah[2][4], al[2][4], bh[4][4];
            ldsm4(ah[0], bufo + abase0 + ((ca ^ ars0) << 4));
            ldsm4(ah[1], bufo + abase1 + ((ca ^ ars1) << 4));
            ldsm4(al[0], bufo + abase0 + (XA_LO - XA_HI) + ((ca ^ ars0) << 4));
            ldsm4(al[1], bufo + abase1 + (XA_LO - XA_HI) + ((ca ^ ars1) << 4));
#pragma unroll
            for (int p = 0; p < 4; ++p)
                ldsm4(bh[p], bufo + bbase[p] + ((cbsel ^ brs[p]) << 4));
#pragma unroll
            for (int p = 0; p < 4; ++p)
#pragma unroll
                for (int mi = 0; mi < 2; ++mi) {
                    mma_f16(acc[mi][2 * p],     ah[mi], bh[p]);
                    mma_f16(acc[mi][2 * p + 1], ah[mi], bh[p] + 2);
                }
#pragma unroll
            for (int p = 0; p < 4; ++p)
#pragma unroll
                for (int mi = 0; mi < 2; ++mi) {
                    mma_f16(acc[mi][2 * p],     al[mi], bh[p]);
                    mma_f16(acc[mi][2 * p + 1], al[mi], bh[p] + 2);
                }
        }

        if (kt + 2 < nk) {
            const uint32_t nb = ((kt + 2) % 3) * XSTAGE;
            const int go = (kt + 2) * 32;
            cpasync16(sAh0 + nb, AhiG + go);
            cpasync16(sAh1 + nb, AhiG + go + 8);
            cpasync16(sAl0 + nb, AloG + go);
            cpasync16(sAl1 + nb, AloG + go + 8);
            cpasync16(sB0 + nb, BG + go);
            cpasync16(sB1 + nb, BG + go + 8);
            cpasync_commit();
        }
        buf = (buf + 1 == 3) ? 0 : buf + 1;
    }

    const int g  = lane >> 2;
    const int cq = (lane & 3) * 2;
#pragma unroll
    for (int mi = 0; mi < 2; ++mi) {
        const int row0 = m0 + wm * 32 + mi * 16 + g;
        float* C0 = C + (size_t)row0 * 256 + n0 + wn * 64;
        float* C1 = C0 + (size_t)8 * 256;
#pragma unroll
        for (int ni = 0; ni < 8; ++ni) {
            *(float2*)(C0 + ni * 8 + cq) = make_float2(acc[mi][ni][0], acc[mi][ni][1]);
            *(float2*)(C1 + ni * 8 + cq) = make_float2(acc[mi][ni][2], acc[mi][ni][3]);
        }
    }
}

// ---------------------------------------------------------------------------
// Heads GEMM (tile 128x64), XOR-swizzled, 2 CTAs/SM.
// ht[b,n] = sum_k (Chi+Clo)[b,k]*HW[n,k], K=2048. Warp tile 32x32.
// ---------------------------------------------------------------------------
__global__ void __launch_bounds__(256, 2)
gemm_heads(const __half* __restrict__ Ahi, const __half* __restrict__ Alo,
           const __half* __restrict__ Bh, float* __restrict__ C) {
    extern __shared__ char smem[];
    const uint32_t sb = smem_u32(smem);
    const int tid  = threadIdx.x;
    const int lane = tid & 31;
    const int wid  = tid >> 5;
    const int wm   = wid & 3;
    const int wn   = wid >> 2;
    const int m0   = blockIdx.x * 128;
    const int nk   = COMB >> 5;   // 64

    const int srow = tid >> 1;
    const int sch  = (tid & 1) * 2;
    const __half* AhiG = Ahi + (size_t)(m0 + srow) * COMB + sch * 8;
    const __half* AloG = Alo + (size_t)(m0 + srow) * COMB + sch * 8;
    const uint32_t sAh0 = sb + HA_HI + xsw(srow, sch);
    const uint32_t sAh1 = sb + HA_HI + xsw(srow, sch + 1);
    const uint32_t sAl0 = sb + HA_LO + xsw(srow, sch);
    const uint32_t sAl1 = sb + HA_LO + xsw(srow, sch + 1);
    const int brow = tid >> 2, bch = tid & 3;
    const __half* BG = Bh + (size_t)brow * COMB + bch * 8;
    const uint32_t sB = sb + HXB + xsw(brow, bch);

    const int arow0 = wm * 32 + (lane & 15);
    const int asel  = lane >> 4;
    const uint32_t abase0 = sb + HA_HI + arow0 * 64;
    const uint32_t abase1 = sb + HA_HI + (arow0 + 16) * 64;
    const int ars0 = (arow0 >> 1) & 3;
    const int ars1 = ((arow0 + 16) >> 1) & 3;
    const int brow0 = wn * 32 + (lane & 7) + ((lane >> 4) << 3);
    const int bsel  = (lane >> 3) & 1;
    uint32_t bbase[2]; int brs[2];
#pragma unroll
    for (int p = 0; p < 2; ++p) {
        bbase[p] = sb + HXB + (brow0 + 16 * p) * 64;
        brs[p]   = ((brow0 + 16 * p) >> 1) & 3;
    }

    float acc[2][4][4];
#pragma unroll
    for (int i = 0; i < 2; ++i)
#pragma unroll
        for (int j = 0; j < 4; ++j)
#pragma unroll
            for (int q = 0; q < 4; ++q) acc[i][j][q] = 0.f;

    {
        cpasync16(sAh0, AhiG);
        cpasync16(sAh1, AhiG + 8);
        cpasync16(sAl0, AloG);
        cpasync16(sAl1, AloG + 8);
        cpasync16(sB, BG);
        cpasync_commit();
        cpasync_wait0();
    }
    __syncthreads();

    for (int kt = 0; kt < nk; ++kt) {
        const uint32_t bufo = (kt & 1) * HSTAGE;
        const bool more = (kt + 1 < nk);
        if (more) {
            const uint32_t nb = ((kt + 1) & 1) * HSTAGE;
            const int go = (kt + 1) * 32;
            cpasync16(sAh0 + nb, AhiG + go);
            cpasync16(sAh1 + nb, AhiG + go + 8);
            cpasync16(sAl0 + nb, AloG + go);
            cpasync16(sAl1 + nb, AloG + go + 8);
            cpasync16(sB + nb, BG + go);
            cpasync_commit();
        }

#pragma unroll
        for (int ks = 0; ks < 2; ++ks) {
            const int ca = ks * 2 + asel;
            const int cbsel = ks * 2 + bsel;
            uint32_t ah[2][4], al[2][4], bh[2][4];
            ldsm4(ah[0], bufo + abase0 + ((ca ^ ars0) << 4));
            ldsm4(ah[1], bufo + abase1 + ((ca ^ ars1) << 4));
            ldsm4(al[0], bufo + abase0 + (HA_LO - HA_HI) + ((ca ^ ars0) << 4));
            ldsm4(al[1], bufo + abase1 + (HA_LO - HA_HI) + ((ca ^ ars1) << 4));
#pragma unroll
            for (int p = 0; p < 2; ++p)
                ldsm4(bh[p], bufo + bbase[p] + ((cbsel ^ brs[p]) << 4));
#pragma unroll
            for (int p = 0; p < 2; ++p)
#pragma unroll
                for (int mi = 0; mi < 2; ++mi) {
                    mma_f16(acc[mi][2 * p],     ah[mi], bh[p]);
                    mma_f16(acc[mi][2 * p + 1], ah[mi], bh[p] + 2);
                    mma_f16(acc[mi][2 * p],     al[mi], bh[p]);
                    mma_f16(acc[mi][2 * p + 1], al[mi], bh[p] + 2);
                }
        }

        if (more) {
            cpasync_wait0();
            __syncthreads();
        }
    }

    const int g  = lane >> 2;
    const int cq = (lane & 3) * 2;
#pragma unroll
    for (int mi = 0; mi < 2; ++mi) {
        const int row0 = m0 + wm * 32 + mi * 16 + g;
        float* C0 = C + (size_t)row0 * 64 + wn * 32;
        float* C1 = C0 + (size_t)8 * 64;
#pragma unroll
        for (int ni = 0; ni < 4; ++ni) {
            *(float2*)(C0 + ni * 8 + cq) = make_float2(acc[mi][ni][0], acc[mi][ni][1]);
            *(float2*)(C1 + ni * 8 + cq) = make_float2(acc[mi][ni][2], acc[mi][ni][3]);
        }
    }
}

// ---------------------------------------------------------------------------
// attn1 (GBA=4, 31KB smem): x2 = relu(alpha1 @ h1) as fp16 hi/lo
// ---------------------------------------------------------------------------
__global__ void __launch_bounds__(256)
attn1_kernel(const float* __restrict__ h1, const float* __restrict__ adj,
             const float* __restrict__ a1, __half* __restrict__ x2hi,
             __half* __restrict__ x2lo) {
    extern __shared__ float sm[];
    float* hs   = sm;           // 7168
    float* av   = sm + 7168;    // 512
    float* sadj = sm + 7680;    // 49
    float* ssi  = sm + 7729;    // 28
    float* ssj  = sm + 7757;    // 28
    float* sal  = sm + 7785;    // 196
    const int tid = threadIdx.x;
    const int w = tid >> 5, lane = tid & 31;
    const size_t base = (size_t)blockIdx.x * (GBA * NND * HID);

    {
        const float4* src = (const float4*)(h1 + base);
        float4* dst = (float4*)hs;
        for (int i = tid; i < GBA * NND * HID / 4; i += 256) dst[i] = src[i];
        if (tid < 128) ((float4*)av)[tid] = ((const float4*)a1)[tid];
        if (tid < 49) sadj[tid] = adj[tid];
    }
    __syncthreads();

    for (int r = w; r < GBA * NND; r += 8) {
        const float* hr = hs + r * HID;
        float si = 0.f, sj = 0.f;
#pragma unroll
        for (int k = lane; k < HID; k += 32) {
            const float hv = hr[k];
            si = fmaf(hv, av[k], si);
            sj = fmaf(hv, av[HID + k], sj);
        }
#pragma unroll
        for (int off = 16; off > 0; off >>= 1) {
            si += __shfl_xor_sync(0xffffffffu, si, off);
            sj += __shfl_xor_sync(0xffffffffu, sj, off);
        }
        if (lane == 0) { ssi[r] = si; ssj[r] = sj; }
    }
    __syncthreads();

    if (tid < GBA * NND) {
        const int b = tid / 7, i = tid - b * 7;
        float e[7]; float mx = -3.0e38f;
#pragma unroll
        for (int j = 0; j < 7; ++j) {
            float v = ssi[b * 7 + i] + ssj[b * 7 + j];
            v = (v > 0.f) ? v : 0.2f * v;
            if (sadj[i * 7 + j] == 0.f) v = -3.0e38f;
            e[j] = v; mx = fmaxf(mx, v);
        }
        float s = 0.f;
#pragma unroll
        for (int j = 0; j < 7; ++j) {
            const float ex = (e[j] < -1.0e38f) ? 0.f : __expf(e[j] - mx);
            e[j] = ex; s += ex;
        }
        const float inv = 1.f / s;
#pragma unroll
        for (int j = 0; j < 7; ++j) sal[tid * 7 + j] = e[j] * inv;
    }
    __syncthreads();

    for (int r = w; r < GBA * NND; r += 8) {
        const int b = r / 7;
        const float* hb = hs + b * 7 * HID;
        const float* alr = sal + r * 7;
        float a0 = alr[0], a1v = alr[1], a2v = alr[2], a3 = alr[3],
              a4 = alr[4], a5 = alr[5], a6 = alr[6];
#pragma unroll
        for (int d4 = lane; d4 < 64; d4 += 32) {
            const float4* p0 = (const float4*)(hb) + d4;
            float4 h0 = p0[0],  h1v = p0[64],  h2 = p0[128], h3 = p0[192],
                   h4 = p0[256], h5 = p0[320], h6 = p0[384];
            float4 o;
            o.x = a0*h0.x + a1v*h1v.x + a2v*h2.x + a3*h3.x + a4*h4.x + a5*h5.x + a6*h6.x;
            o.y = a0*h0.y + a1v*h1v.y + a2v*h2.y + a3*h3.y + a4*h4.y + a5*h5.y + a6*h6.y;
            o.z = a0*h0.z + a1v*h1v.z + a2v*h2.z + a3*h3.z + a4*h4.z + a5*h5.z + a6*h6.z;
            o.w = a0*h0.w + a1v*h1v.w + a2v*h2.w + a3*h3.w + a4*h4.w + a5*h5.w + a6*h6.w;
            o.x = fmaxf(o.x, 0.f); o.y = fmaxf(o.y, 0.f);
            o.z = fmaxf(o.z, 0.f); o.w = fmaxf(o.w, 0.f);
            uint32_t h0p, h1p, l0p, l1p;
            cvt_hilo(o, h0p, h1p, l0p, l1p);
            const size_t off = base + r * HID + d4 * 4;
            *(uint2*)(x2hi + off) = make_uint2(h0p, h1p);
            *(uint2*)(x2lo + off) = make_uint2(l0p, l1p);
        }
    }
}

// ---------------------------------------------------------------------------
// attn2 (GBA=4): softmax out + aggregation -> combined (fp16 hi/lo) + context
// ---------------------------------------------------------------------------
__global__ void __launch_bounds__(256)
attn2_kernel(const float* __restrict__ h2, const float* __restrict__ adj,
             const float* __restrict__ a2, const float* __restrict__ context,
             __half* __restrict__ chi, __half* __restrict__ clo,
             float* __restrict__ out) {
    extern __shared__ float sm[];
    float* hs   = sm;           // 7168
    float* av   = sm + 7168;    // 512
    float* sadj = sm + 7680;    // 49
    float* ssi  = sm + 7729;    // 28
    float* ssj  = sm + 7757;    // 28
    float* sal  = sm + 7785;    // 196
    const int tid = threadIdx.x;
    const int w = tid >> 5, lane = tid & 31;
    const int b0 = blockIdx.x * GBA;
    const size_t base = (size_t)blockIdx.x * (GBA * NND * HID);

    {
        const float4* src = (const float4*)(h2 + base);
        float4* dst = (float4*)hs;
        for (int i = tid; i < GBA * NND * HID / 4; i += 256) dst[i] = src[i];
        if (tid < 128) ((float4*)av)[tid] = ((const float4*)a2)[tid];
        if (tid < 49) sadj[tid] = adj[tid];
    }
    __syncthreads();

    for (int r = w; r < GBA * NND; r += 8) {
        const float* hr = hs + r * HID;
        float si = 0.f, sj = 0.f;
#pragma unroll
        for (int k = lane; k < HID; k += 32) {
            const float hv = hr[k];
            si = fmaf(hv, av[k], si);
            sj = fmaf(hv, av[HID + k], sj);
        }
#pragma unroll
        for (int off = 16; off > 0; off >>= 1) {
            si += __shfl_xor_sync(0xffffffffu, si, off);
            sj += __shfl_xor_sync(0xffffffffu, sj, off);
        }
        if (lane == 0) { ssi[r] = si; ssj[r] = sj; }
    }
    __syncthreads();

    if (tid < GBA * NND) {
        const int b = tid / 7, i = tid - b * 7;
        float e[7]; float mx = -3.0e38f;
#pragma unroll
        for (int j = 0; j < 7; ++j) {
            float v = ssi[b * 7 + i] + ssj[b * 7 + j];
            v = (v > 0.f) ? v : 0.2f * v;
            if (sadj[i * 7 + j] == 0.f) v = -3.0e38f;
            e[j] = v; mx = fmaxf(mx, v);
        }
        float s = 0.f;
#pragma unroll
        for (int j = 0; j < 7; ++j) {
            const float ex = (e[j] < -1.0e38f) ? 0.f : __expf(e[j] - mx);
            e[j] = ex; s += ex;
        }
        const float inv = 1.f / s;
        float* oa = out + (size_t)6 * BATCH + (size_t)(b0 + b) * 49 + i * 7;
#pragma unroll
        for (int j = 0; j < 7; ++j) {
            const float al = e[j] * inv;
            sal[tid * 7 + j] = al;
            oa[j] = al;
        }
    }
    __syncthreads();

    for (int r = w; r < GBA * NND; r += 8) {
        const int b = r / 7;
        const int rem = r - b * 7;
        const float* hb = hs + b * 7 * HID;
        const float* alr = sal + r * 7;
        float a0 = alr[0], a1v = alr[1], a2v = alr[2], a3 = alr[3],
              a4 = alr[4], a5 = alr[5], a6 = alr[6];
        const size_t cb = (size_t)(b0 + b) * COMB;
#pragma unroll
        for (int d4 = lane; d4 < 64; d4 += 32) {
            const float4* p0 = (const float4*)(hb) + d4;
            float4 h0 = p0[0],  h1v = p0[64],  h2 = p0[128], h3 = p0[192],
                   h4 = p0[256], h5 = p0[320], h6 = p0[384];
            float4 o;
            o.x = a0*h0.x + a1v*h1v.x + a2v*h2.x + a3*h3.x + a4*h4.x + a5*h5.x + a6*h6.x;
            o.y = a0*h0.y + a1v*h1v.y + a2v*h2.y + a3*h3.y + a4*h4.y + a5*h5.y + a6*h6.y;
            o.z = a0*h0.z + a1v*h1v.z + a2v*h2.z + a3*h3.z + a4*h4.z + a5*h5.z + a6*h6.z;
            o.w = a0*h0.w + a1v*h1v.w + a2v*h2.w + a3*h3.w + a4*h4.w + a5*h5.w + a6*h6.w;
            o.x = fmaxf(o.x, 0.f); o.y = fmaxf(o.y, 0.f);
            o.z = fmaxf(o.z, 0.f); o.w = fmaxf(o.w, 0.f);
            uint32_t h0p, h1p, l0p, l1p;
            cvt_hilo(o, h0p, h1p, l0p, l1p);
            const size_t off = cb + rem * HID + d4 * 4;
            *(uint2*)(chi + off) = make_uint2(h0p, h1p);
            *(uint2*)(clo + off) = make_uint2(l0p, l1p);
        }
    }
    for (int idx = tid; idx < GBA * CTXD / 4; idx += 256) {
        const int b = idx >> 6, c4 = idx & 63;
        float4 v = ((const float4*)context)[(size_t)(b0 + b) * 64 + c4];
        uint32_t h0p, h1p, l0p, l1p;
        cvt_hilo(v, h0p, h1p, l0p, l1p);
        const size_t off = (size_t)(b0 + b) * COMB + NND * HID + c4 * 4;
        *(uint2*)(chi + off) = make_uint2(h0p, h1p);
        *(uint2*)(clo + off) = make_uint2(l0p, l1p);
    }
}

// ---------------------------------------------------------------------------
// final heads tail. out = [pred(B) | weights(B*5) | attn2(B*49)]
// ---------------------------------------------------------------------------
__global__ void __launch_bounds__(256)
final_kernel(const float* __restrict__ ht, const float* __restrict__ base_preds,
             const float* __restrict__ wh1_b,
             const float* __restrict__ wh2_w, const float* __restrict__ wh2_b,
             const float* __restrict__ wh3_w, const float* __restrict__ wh3_b,
             const float* __restrict__ rh1_b,
             const float* __restrict__ rh2_w, const float* __restrict__ rh2_b,
             float* __restrict__ out) {
    const int b = blockIdx.x * 256 + threadIdx.x;
    if (b >= BATCH) return;
    const float* h = ht + (size_t)b * 64;

    float t1[32];
#pragma unroll
    for (int k = 0; k < 32; ++k) t1[k] = fmaxf(h[k] + wh1_b[k], 0.f);
    float t2[16];
#pragma unroll
    for (int o = 0; o < 16; ++o) {
        float s = wh2_b[o];
#pragma unroll
        for (int k = 0; k < 32; ++k) s = fmaf(t1[k], wh2_w[o * 32 + k], s);
        t2[o] = fmaxf(s, 0.f);
    }
    float raw[5]; float mx = -3.0e38f;
#pragma unroll
    for (int o = 0; o < 5; ++o) {
        float s = wh3_b[o];
#pragma unroll
        for (int k = 0; k < 16; ++k) s = fmaf(t2[k], wh3_w[o * 16 + k], s);
        raw[o] = s; mx = fmaxf(mx, s);
    }
    float se = 0.f;
#pragma unroll
    for (int o = 0; o < 5; ++o) { raw[o] = __expf(raw[o] - mx); se += raw[o]; }
    const float inv = 1.f / se;
    float wp = 0.f;
#pragma unroll
    for (int o = 0; o < 5; ++o) {
        const float wt = raw[o] * inv;
        out[BATCH + (size_t)b * 5 + o] = wt;
        wp = fmaf(wt, base_preds[(size_t)b * 5 + o], wp);
    }
    float rr = rh2_b[0];
#pragma unroll
    for (int k = 0; k < 16; ++k)
        rr = fmaf(tanhf(h[32 + k] + rh1_b[k]), rh2_w[k], rr);
    out[b] = fmaxf(wp + rr * 0.05f, 0.05f);
}

// ---------------------------------------------------------------------------
extern "C" void kernel_launch(void* const* d_in, const int* in_sizes, int n_in,
                              void* d_out, int out_size) {
    const float* node_feats = (const float*)d_in[0];
    const float* adj        = (const float*)d_in[1];
    const float* context    = (const float*)d_in[2];
    const float* base_preds = (const float*)d_in[3];
    const float* W1    = (const float*)d_in[4];
    const float* a1    = (const float*)d_in[5];
    const float* W2    = (const float*)d_in[6];
    const float* a2    = (const float*)d_in[7];
    const float* wh1_w = (const float*)d_in[8];
    const float* wh1_b = (const float*)d_in[9];
    const float* wh2_w = (const float*)d_in[10];
    const float* wh2_b = (const float*)d_in[11];
    const float* wh3_w = (const float*)d_in[12];
    const float* wh3_b = (const float*)d_in[13];
    const float* rh1_w = (const float*)d_in[14];
    const float* rh1_b = (const float*)d_in[15];
    const float* rh2_w = (const float*)d_in[16];
    const float* rh2_b = (const float*)d_in[17];
    float* out = (float*)d_out;

    float *h1p, *h2p, *htp;
    __half *a1h, *a1l, *x2h, *x2l, *w1h, *w2h, *hwp, *cbh, *cbl;
    cudaGetSymbolAddress((void**)&h1p, g_h1);
    cudaGetSymbolAddress((void**)&h2p, g_h2);
    cudaGetSymbolAddress((void**)&htp, g_ht);
    cudaGetSymbolAddress((void**)&a1h, g_a1hi);
    cudaGetSymbolAddress((void**)&a1l, g_a1lo);
    cudaGetSymbolAddress((void**)&x2h, g_x2hi);
    cudaGetSymbolAddress((void**)&x2l, g_x2lo);
    cudaGetSymbolAddress((void**)&w1h, g_w1h);
    cudaGetSymbolAddress((void**)&w2h, g_w2h);
    cudaGetSymbolAddress((void**)&hwp, g_hw);
    cudaGetSymbolAddress((void**)&cbh, g_combhi);
    cudaGetSymbolAddress((void**)&cbl, g_comblo);

    const int smemA = 7981 * 4;
    cudaFuncSetAttribute(gemm_f16, cudaFuncAttributeMaxDynamicSharedMemorySize, GX_SMEM);
    cudaFuncSetAttribute(gemm_heads, cudaFuncAttributeMaxDynamicSharedMemorySize, GH_SMEM);
    cudaFuncSetAttribute(attn1_kernel, cudaFuncAttributeMaxDynamicSharedMemorySize, smemA);
    cudaFuncSetAttribute(attn2_kernel, cudaFuncAttributeMaxDynamicSharedMemorySize, smemA);

    convw_kernel<<<(HID * FEATD + 255) / 256, 256>>>(W1, w1h, HID * FEATD);
    convw_kernel<<<(HID * HID + 255) / 256, 256>>>(W2, w2h, HID * HID);
    convhw_kernel<<<(64 * COMB + 255) / 256, 256>>>(wh1_w, rh1_w, hwp);
    convA_kernel<<<(MROWS * FEATD / 4 + 255) / 256, 256>>>(node_feats, a1h, a1l,
                                                           MROWS * FEATD / 4);

    // h1 = (a1hi+a1lo) @ W1^T   (grid transposed: n fastest -> L2 A-reuse)
    gemm_f16<<<dim3(2, MROWS / 128), 256, GX_SMEM>>>(a1h, a1l, w1h, h1p, FEATD);
    // x2 (fp16 hi/lo) = relu(alpha1 @ h1)
    attn1_kernel<<<BATCH / GBA, 256, smemA>>>(h1p, adj, a1, x2h, x2l);
    // h2 = (x2hi+x2lo) @ W2^T
    gemm_f16<<<dim3(2, MROWS / 128), 256, GX_SMEM>>>(x2h, x2l, w2h, h2p, HID);
    // attn2: softmax out + combined (fp16 hi/lo)
    attn2_kernel<<<BATCH / GBA, 256, smemA>>>(h2p, adj, a2, context, cbh, cbl, out);
    // ht = combined @ HW^T  (N=64 heads GEMM, 2 CTAs/SM)
    gemm_heads<<<BATCH / 128, 256, GH_SMEM>>>(cbh, cbl, hwp, htp);
    // tiny tail
    final_kernel<<<BATCH / 256, 256>>>(htp, base_preds, wh1_b, wh2_w, wh2_b,
                                       wh3_w, wh3_b, rh1_b, rh2_w, rh2_b, out);
}

// round 17
// speedup vs baseline: 5.0787x; 1.2663x over previous
#include <cuda_runtime.h>
#include <cuda_fp16.h>
#include <cstdint>
#include <cstddef>

#define BATCH 16384
#define NND   7
#define FEATD 512
#define HID   256
#define CTXD  256
#define COMB  2048
#define MROWS (BATCH * NND)        // 114688
#define GBA   4                    // batches per attn block

// main GEMM buffer (tile 128x128), XOR-swizzled 64B rows, 3-stage ring
#define XA     0
#define XB     8192
#define XSTAGE 16384
#define GX_SMEM (3 * XSTAGE)       // 49152 -> 2 CTAs/SM

// heads GEMM (tile 128x64), XOR-swizzled, double buffer
#define HA     0
#define HXB    8192
#define HSTAGE 12288
#define GH_SMEM (2 * HSTAGE)       // 24576 -> 3 CTAs/SM

// ---------------- scratch ---------------------------------------------------
__device__ float  g_h1[(size_t)MROWS * HID];
__device__ float  g_h2[(size_t)MROWS * HID];
__device__ __half g_a1h[(size_t)MROWS * FEATD];
__device__ __half g_x2h[(size_t)MROWS * HID];
__device__ __half g_combh[(size_t)BATCH * COMB];
__device__ float  g_ht[(size_t)BATCH * 64];
__device__ __half g_w1h[HID * FEATD];
__device__ __half g_w2h[HID * HID];
__device__ __half g_hw[64 * COMB];

// ---------------- helpers ---------------------------------------------------
__device__ __forceinline__ uint32_t smem_u32(const void* p) {
    uint32_t a;
    asm("{ .reg .u64 t; cvta.to.shared.u64 t, %1; cvt.u32.u64 %0, t; }" : "=r"(a) : "l"(p));
    return a;
}
__device__ __forceinline__ void ldsm4(uint32_t* r, uint32_t addr) {
    asm volatile("ldmatrix.sync.aligned.m8n8.x4.shared.b16 {%0,%1,%2,%3}, [%4];"
                 : "=r"(r[0]), "=r"(r[1]), "=r"(r[2]), "=r"(r[3]) : "r"(addr));
}
__device__ __forceinline__ void mma_f16(float* c, const uint32_t* a, const uint32_t* b) {
    asm volatile(
        "mma.sync.aligned.m16n8k16.row.col.f32.f16.f16.f32 "
        "{%0,%1,%2,%3}, {%4,%5,%6,%7}, {%8,%9}, {%0,%1,%2,%3};"
        : "+f"(c[0]), "+f"(c[1]), "+f"(c[2]), "+f"(c[3])
        : "r"(a[0]), "r"(a[1]), "r"(a[2]), "r"(a[3]), "r"(b[0]), "r"(b[1]));
}
__device__ __forceinline__ uint2 cvt_hi4(float4 v) {
    __half2 ha = __floats2half2_rn(v.x, v.y);
    __half2 hb = __floats2half2_rn(v.z, v.w);
    return make_uint2(*(uint32_t*)&ha, *(uint32_t*)&hb);
}
__device__ __forceinline__ void cpasync16(uint32_t saddr, const void* g) {
    asm volatile("cp.async.cg.shared.global [%0], [%1], 16;" :: "r"(saddr), "l"(g) : "memory");
}
__device__ __forceinline__ void cpasync_commit() {
    asm volatile("cp.async.commit_group;" ::: "memory");
}
__device__ __forceinline__ void cpasync_wait0() {
    asm volatile("cp.async.wait_group 0;" ::: "memory");
}
__device__ __forceinline__ void cpasync_wait1() {
    asm volatile("cp.async.wait_group 1;" ::: "memory");
}
// XOR swizzle for 64B rows: 16B chunk c at row r -> c ^ ((r>>1)&3)
__device__ __forceinline__ uint32_t xsw(int row, int ch) {
    return (uint32_t)(row * 64 + ((ch ^ ((row >> 1) & 3)) << 4));
}

// ---------------------------------------------------------------------------
// converters
// ---------------------------------------------------------------------------
__global__ void convw_kernel(const float* __restrict__ W, __half* __restrict__ H, int n) {
    int i = blockIdx.x * 256 + threadIdx.x;
    if (i < n) H[i] = __float2half_rn(W[i]);
}
__global__ void conv4_kernel(const float* __restrict__ A, __half* __restrict__ H, int n4) {
    int i = blockIdx.x * 256 + threadIdx.x;
    if (i < n4) ((uint2*)H)[i] = cvt_hi4(((const float4*)A)[i]);
}
__global__ void convhw_kernel(const float* __restrict__ wh1_w, const float* __restrict__ rh1_w,
                              __half* __restrict__ HW) {
    int i = blockIdx.x * 256 + threadIdx.x;
    if (i < 64 * COMB) {
        int row = i >> 11, k = i & (COMB - 1);
        float v = 0.f;
        if (row < 32) v = wh1_w[row * COMB + k];
        else if (row < 48) v = rh1_w[(row - 32) * COMB + k];
        HW[i] = __float2half_rn(v);
    }
}

// ---------------------------------------------------------------------------
// fp16 HMMA GEMM, tile 128x128, 2 CTAs/SM, 3-stage cp.async ring.
// C[m,n] = sum_k A[m,k]*B[n,k], pure fp16 inputs, fp32 accum.
// grid (N/128, M/128): n fastest -> L2 A-reuse. 8 warps (4m x 2n).
// ---------------------------------------------------------------------------
__global__ void __launch_bounds__(256, 2)
gemm_f16(const __half* __restrict__ Ah, const __half* __restrict__ Bh,
         float* __restrict__ C, int K) {
    extern __shared__ char smem[];
    const uint32_t sb = smem_u32(smem);
    const int tid  = threadIdx.x;
    const int lane = tid & 31;
    const int wid  = tid >> 5;
    const int wm   = wid & 3;
    const int wn   = wid >> 2;
    const int m0   = blockIdx.y * 128;
    const int n0   = blockIdx.x * 128;
    const int nk   = K >> 5;

    const int srow = tid >> 1;
    const int sch  = (tid & 1) * 2;
    const __half* AG = Ah + (size_t)(m0 + srow) * K + sch * 8;
    const __half* BG = Bh + (size_t)(n0 + srow) * K + sch * 8;
    const uint32_t sA0 = sb + XA + xsw(srow, sch);
    const uint32_t sA1 = sb + XA + xsw(srow, sch + 1);
    const uint32_t sB0 = sb + XB + xsw(srow, sch);
    const uint32_t sB1 = sb + XB + xsw(srow, sch + 1);

    const int arow0 = wm * 32 + (lane & 15);
    const int asel  = lane >> 4;
    const uint32_t abase0 = sb + XA + arow0 * 64;
    const uint32_t abase1 = sb + XA + (arow0 + 16) * 64;
    const int ars0 = (arow0 >> 1) & 3;
    const int ars1 = ((arow0 + 16) >> 1) & 3;
    const int brow0 = wn * 64 + (lane & 7) + ((lane >> 4) << 3);
    const int bsel  = (lane >> 3) & 1;
    uint32_t bbase[4]; int brs[4];
#pragma unroll
    for (int p = 0; p < 4; ++p) {
        bbase[p] = sb + XB + (brow0 + 16 * p) * 64;
        brs[p]   = ((brow0 + 16 * p) >> 1) & 3;
    }

    float acc[2][8][4];
#pragma unroll
    for (int i = 0; i < 2; ++i)
#pragma unroll
        for (int j = 0; j < 8; ++j)
#pragma unroll
            for (int q = 0; q < 4; ++q) acc[i][j][q] = 0.f;

    // prologue: issue stages 0 and 1
#pragma unroll
    for (int s = 0; s < 2; ++s) {
        const uint32_t nb = s * XSTAGE;
        const int go = s * 32;
        cpasync16(sA0 + nb, AG + go);
        cpasync16(sA1 + nb, AG + go + 8);
        cpasync16(sB0 + nb, BG + go);
        cpasync16(sB1 + nb, BG + go + 8);
        cpasync_commit();
    }

    int buf = 0;
    for (int kt = 0; kt < nk; ++kt) {
        if (kt + 1 < nk) cpasync_wait1(); else cpasync_wait0();
        __syncthreads();

        const uint32_t bufo = buf * XSTAGE;
#pragma unroll
        for (int ks = 0; ks < 2; ++ks) {
            const int ca = ks * 2 + asel;
            const int cbsel = ks * 2 + bsel;
            uint32_t ah[2][4], bh[4][4];
            ldsm4(ah[0], bufo + abase0 + ((ca ^ ars0) << 4));
            ldsm4(ah[1], bufo + abase1 + ((ca ^ ars1) << 4));
#pragma unroll
            for (int p = 0; p < 4; ++p)
                ldsm4(bh[p], bufo + bbase[p] + ((cbsel ^ brs[p]) << 4));
#pragma unroll
            for (int p = 0; p < 4; ++p)
#pragma unroll
                for (int mi = 0; mi < 2; ++mi) {
                    mma_f16(acc[mi][2 * p],     ah[mi], bh[p]);
                    mma_f16(acc[mi][2 * p + 1], ah[mi], bh[p] + 2);
                }
        }

        if (kt + 2 < nk) {
            const uint32_t nb = ((kt + 2) % 3) * XSTAGE;
            const int go = (kt + 2) * 32;
            cpasync16(sA0 + nb, AG + go);
            cpasync16(sA1 + nb, AG + go + 8);
            cpasync16(sB0 + nb, BG + go);
            cpasync16(sB1 + nb, BG + go + 8);
            cpasync_commit();
        }
        buf = (buf + 1 == 3) ? 0 : buf + 1;
    }

    const int g  = lane >> 2;
    const int cq = (lane & 3) * 2;
#pragma unroll
    for (int mi = 0; mi < 2; ++mi) {
        const int row0 = m0 + wm * 32 + mi * 16 + g;
        float* C0 = C + (size_t)row0 * 256 + n0 + wn * 64;
        float* C1 = C0 + (size_t)8 * 256;
#pragma unroll
        for (int ni = 0; ni < 8; ++ni) {
            *(float2*)(C0 + ni * 8 + cq) = make_float2(acc[mi][ni][0], acc[mi][ni][1]);
            *(float2*)(C1 + ni * 8 + cq) = make_float2(acc[mi][ni][2], acc[mi][ni][3]);
        }
    }
}

// ---------------------------------------------------------------------------
// Heads GEMM (tile 128x64), pure fp16, 3 CTAs/SM.
// ht[b,n] = sum_k C[b,k]*HW[n,k], K=2048. Warp tile 32x32.
// ---------------------------------------------------------------------------
__global__ void __launch_bounds__(256, 3)
gemm_heads(const __half* __restrict__ Ah, const __half* __restrict__ Bh,
           float* __restrict__ C) {
    extern __shared__ char smem[];
    const uint32_t sb = smem_u32(smem);
    const int tid  = threadIdx.x;
    const int lane = tid & 31;
    const int wid  = tid >> 5;
    const int wm   = wid & 3;
    const int wn   = wid >> 2;
    const int m0   = blockIdx.x * 128;
    const int nk   = COMB >> 5;   // 64

    const int srow = tid >> 1;
    const int sch  = (tid & 1) * 2;
    const __half* AG = Ah + (size_t)(m0 + srow) * COMB + sch * 8;
    const uint32_t sA0 = sb + HA + xsw(srow, sch);
    const uint32_t sA1 = sb + HA + xsw(srow, sch + 1);
    const int brow = tid >> 2, bch = tid & 3;
    const __half* BG = Bh + (size_t)brow * COMB + bch * 8;
    const uint32_t sB = sb + HXB + xsw(brow, bch);

    const int arow0 = wm * 32 + (lane & 15);
    const int asel  = lane >> 4;
    const uint32_t abase0 = sb + HA + arow0 * 64;
    const uint32_t abase1 = sb + HA + (arow0 + 16) * 64;
    const int ars0 = (arow0 >> 1) & 3;
    const int ars1 = ((arow0 + 16) >> 1) & 3;
    const int brow0 = wn * 32 + (lane & 7) + ((lane >> 4) << 3);
    const int bsel  = (lane >> 3) & 1;
    uint32_t bbase[2]; int brs[2];
#pragma unroll
    for (int p = 0; p < 2; ++p) {
        bbase[p] = sb + HXB + (brow0 + 16 * p) * 64;
        brs[p]   = ((brow0 + 16 * p) >> 1) & 3;
    }

    float acc[2][4][4];
#pragma unroll
    for (int i = 0; i < 2; ++i)
#pragma unroll
        for (int j = 0; j < 4; ++j)
#pragma unroll
            for (int q = 0; q < 4; ++q) acc[i][j][q] = 0.f;

    {
        cpasync16(sA0, AG);
        cpasync16(sA1, AG + 8);
        cpasync16(sB, BG);
        cpasync_commit();
        cpasync_wait0();
    }
    __syncthreads();

    for (int kt = 0; kt < nk; ++kt) {
        const uint32_t bufo = (kt & 1) * HSTAGE;
        const bool more = (kt + 1 < nk);
        if (more) {
            const uint32_t nb = ((kt + 1) & 1) * HSTAGE;
            const int go = (kt + 1) * 32;
            cpasync16(sA0 + nb, AG + go);
            cpasync16(sA1 + nb, AG + go + 8);
            cpasync16(sB + nb, BG + go);
            cpasync_commit();
        }

#pragma unroll
        for (int ks = 0; ks < 2; ++ks) {
            const int ca = ks * 2 + asel;
            const int cbsel = ks * 2 + bsel;
            uint32_t ah[2][4], bh[2][4];
            ldsm4(ah[0], bufo + abase0 + ((ca ^ ars0) << 4));
            ldsm4(ah[1], bufo + abase1 + ((ca ^ ars1) << 4));
#pragma unroll
            for (int p = 0; p < 2; ++p)
                ldsm4(bh[p], bufo + bbase[p] + ((cbsel ^ brs[p]) << 4));
#pragma unroll
            for (int p = 0; p < 2; ++p)
#pragma unroll
                for (int mi = 0; mi < 2; ++mi) {
                    mma_f16(acc[mi][2 * p],     ah[mi], bh[p]);
                    mma_f16(acc[mi][2 * p + 1], ah[mi], bh[p] + 2);
                }
        }

        if (more) {
            cpasync_wait0();
            __syncthreads();
        }
    }

    const int g  = lane >> 2;
    const int cq = (lane & 3) * 2;
#pragma unroll
    for (int mi = 0; mi < 2; ++mi) {
        const int row0 = m0 + wm * 32 + mi * 16 + g;
        float* C0 = C + (size_t)row0 * 64 + wn * 32;
        float* C1 = C0 + (size_t)8 * 64;
#pragma unroll
        for (int ni = 0; ni < 4; ++ni) {
            *(float2*)(C0 + ni * 8 + cq) = make_float2(acc[mi][ni][0], acc[mi][ni][1]);
            *(float2*)(C1 + ni * 8 + cq) = make_float2(acc[mi][ni][2], acc[mi][ni][3]);
        }
    }
}

// ---------------------------------------------------------------------------
// attn1 (GBA=4): x2 = relu(alpha1 @ h1) as single fp16
// ---------------------------------------------------------------------------
__global__ void __launch_bounds__(256)
attn1_kernel(const float* __restrict__ h1, const float* __restrict__ adj,
             const float* __restrict__ a1, __half* __restrict__ x2h) {
    extern __shared__ float sm[];
    float* hs   = sm;           // 7168
    float* av   = sm + 7168;    // 512
    float* sadj = sm + 7680;    // 49
    float* ssi  = sm + 7729;    // 28
    float* ssj  = sm + 7757;    // 28
    float* sal  = sm + 7785;    // 196
    const int tid = threadIdx.x;
    const int w = tid >> 5, lane = tid & 31;
    const size_t base = (size_t)blockIdx.x * (GBA * NND * HID);

    {
        const float4* src = (const float4*)(h1 + base);
        float4* dst = (float4*)hs;
        for (int i = tid; i < GBA * NND * HID / 4; i += 256) dst[i] = src[i];
        if (tid < 128) ((float4*)av)[tid] = ((const float4*)a1)[tid];
        if (tid < 49) sadj[tid] = adj[tid];
    }
    __syncthreads();

    for (int r = w; r < GBA * NND; r += 8) {
        const float* hr = hs + r * HID;
        float si = 0.f, sj = 0.f;
#pragma unroll
        for (int k = lane; k < HID; k += 32) {
            const float hv = hr[k];
            si = fmaf(hv, av[k], si);
            sj = fmaf(hv, av[HID + k], sj);
        }
#pragma unroll
        for (int off = 16; off > 0; off >>= 1) {
            si += __shfl_xor_sync(0xffffffffu, si, off);
            sj += __shfl_xor_sync(0xffffffffu, sj, off);
        }
        if (lane == 0) { ssi[r] = si; ssj[r] = sj; }
    }
    __syncthreads();

    if (tid < GBA * NND) {
        const int b = tid / 7, i = tid - b * 7;
        float e[7]; float mx = -3.0e38f;
#pragma unroll
        for (int j = 0; j < 7; ++j) {
            float v = ssi[b * 7 + i] + ssj[b * 7 + j];
            v = (v > 0.f) ? v : 0.2f * v;
            if (sadj[i * 7 + j] == 0.f) v = -3.0e38f;
            e[j] = v; mx = fmaxf(mx, v);
        }
        float s = 0.f;
#pragma unroll
        for (int j = 0; j < 7; ++j) {
            const float ex = (e[j] < -1.0e38f) ? 0.f : __expf(e[j] - mx);
            e[j] = ex; s += ex;
        }
        const float inv = 1.f / s;
#pragma unroll
        for (int j = 0; j < 7; ++j) sal[tid * 7 + j] = e[j] * inv;
    }
    __syncthreads();

    for (int r = w; r < GBA * NND; r += 8) {
        const int b = r / 7;
        const float* hb = hs + b * 7 * HID;
        const float* alr = sal + r * 7;
        float a0 = alr[0], a1v = alr[1], a2v = alr[2], a3 = alr[3],
              a4 = alr[4], a5 = alr[5], a6 = alr[6];
#pragma unroll
        for (int d4 = lane; d4 < 64; d4 += 32) {
            const float4* p0 = (const float4*)(hb) + d4;
            float4 h0 = p0[0],  h1v = p0[64],  h2 = p0[128], h3 = p0[192],
                   h4 = p0[256], h5 = p0[320], h6 = p0[384];
            float4 o;
            o.x = a0*h0.x + a1v*h1v.x + a2v*h2.x + a3*h3.x + a4*h4.x + a5*h5.x + a6*h6.x;
            o.y = a0*h0.y + a1v*h1v.y + a2v*h2.y + a3*h3.y + a4*h4.y + a5*h5.y + a6*h6.y;
            o.z = a0*h0.z + a1v*h1v.z + a2v*h2.z + a3*h3.z + a4*h4.z + a5*h5.z + a6*h6.z;
            o.w = a0*h0.w + a1v*h1v.w + a2v*h2.w + a3*h3.w + a4*h4.w + a5*h5.w + a6*h6.w;
            o.x = fmaxf(o.x, 0.f); o.y = fmaxf(o.y, 0.f);
            o.z = fmaxf(o.z, 0.f); o.w = fmaxf(o.w, 0.f);
            *(uint2*)(x2h + base + r * HID + d4 * 4) = cvt_hi4(o);
        }
    }
}

// ---------------------------------------------------------------------------
// attn2 (GBA=4): softmax out + aggregation -> combined (fp16) + context
// ---------------------------------------------------------------------------
__global__ void __launch_bounds__(256)
attn2_kernel(const float* __restrict__ h2, const float* __restrict__ adj,
             const float* __restrict__ a2, const float* __restrict__ context,
             __half* __restrict__ ch, float* __restrict__ out) {
    extern __shared__ float sm[];
    float* hs   = sm;           // 7168
    float* av   = sm + 7168;    // 512
    float* sadj = sm + 7680;    // 49
    float* ssi  = sm + 7729;    // 28
    float* ssj  = sm + 7757;    // 28
    float* sal  = sm + 7785;    // 196
    const int tid = threadIdx.x;
    const int w = tid >> 5, lane = tid & 31;
    const int b0 = blockIdx.x * GBA;
    const size_t base = (size_t)blockIdx.x * (GBA * NND * HID);

    {
        const float4* src = (const float4*)(h2 + base);
        float4* dst = (float4*)hs;
        for (int i = tid; i < GBA * NND * HID / 4; i += 256) dst[i] = src[i];
        if (tid < 128) ((float4*)av)[tid] = ((const float4*)a2)[tid];
        if (tid < 49) sadj[tid] = adj[tid];
    }
    __syncthreads();

    for (int r = w; r < GBA * NND; r += 8) {
        const float* hr = hs + r * HID;
        float si = 0.f, sj = 0.f;
#pragma unroll
        for (int k = lane; k < HID; k += 32) {
            const float hv = hr[k];
            si = fmaf(hv, av[k], si);
            sj = fmaf(hv, av[HID + k], sj);
        }
#pragma unroll
        for (int off = 16; off > 0; off >>= 1) {
            si += __shfl_xor_sync(0xffffffffu, si, off);
            sj += __shfl_xor_sync(0xffffffffu, sj, off);
        }
        if (lane == 0) { ssi[r] = si; ssj[r] = sj; }
    }
    __syncthreads();

    if (tid < GBA * NND) {
        const int b = tid / 7, i = tid - b * 7;
        float e[7]; float mx = -3.0e38f;
#pragma unroll
        for (int j = 0; j < 7; ++j) {
            float v = ssi[b * 7 + i] + ssj[b * 7 + j];
            v = (v > 0.f) ? v : 0.2f * v;
            if (sadj[i * 7 + j] == 0.f) v = -3.0e38f;
            e[j] = v; mx = fmaxf(mx, v);
        }
        float s = 0.f;
#pragma unroll
        for (int j = 0; j < 7; ++j) {
            const float ex = (e[j] < -1.0e38f) ? 0.f : __expf(e[j] - mx);
            e[j] = ex; s += ex;
        }
        const float inv = 1.f / s;
        float* oa = out + (size_t)6 * BATCH + (size_t)(b0 + b) * 49 + i * 7;
#pragma unroll
        for (int j = 0; j < 7; ++j) {
            const float al = e[j] * inv;
            sal[tid * 7 + j] = al;
            oa[j] = al;
        }
    }
    __syncthreads();

    for (int r = w; r < GBA * NND; r += 8) {
        const int b = r / 7;
        const int rem = r - b * 7;
        const float* hb = hs + b * 7 * HID;
        const float* alr = sal + r * 7;
        float a0 = alr[0], a1v = alr[1], a2v = alr[2], a3 = alr[3],
              a4 = alr[4], a5 = alr[5], a6 = alr[6];
        const size_t cb = (size_t)(b0 + b) * COMB;
#pragma unroll
        for (int d4 = lane; d4 < 64; d4 += 32) {
            const float4* p0 = (const float4*)(hb) + d4;
            float4 h0 = p0[0],  h1v = p0[64],  h2 = p0[128], h3 = p0[192],
                   h4 = p0[256], h5 = p0[320], h6 = p0[384];
            float4 o;
            o.x = a0*h0.x + a1v*h1v.x + a2v*h2.x + a3*h3.x + a4*h4.x + a5*h5.x + a6*h6.x;
            o.y = a0*h0.y + a1v*h1v.y + a2v*h2.y + a3*h3.y + a4*h4.y + a5*h5.y + a6*h6.y;
            o.z = a0*h0.z + a1v*h1v.z + a2v*h2.z + a3*h3.z + a4*h4.z + a5*h5.z + a6*h6.z;
            o.w = a0*h0.w + a1v*h1v.w + a2v*h2.w + a3*h3.w + a4*h4.w + a5*h5.w + a6*h6.w;
            o.x = fmaxf(o.x, 0.f); o.y = fmaxf(o.y, 0.f);
            o.z = fmaxf(o.z, 0.f); o.w = fmaxf(o.w, 0.f);
            *(uint2*)(ch + cb + rem * HID + d4 * 4) = cvt_hi4(o);
        }
    }
    for (int idx = tid; idx < GBA * CTXD / 4; idx += 256) {
        const int b = idx >> 6, c4 = idx & 63;
        float4 v = ((const float4*)context)[(size_t)(b0 + b) * 64 + c4];
        *(uint2*)(ch + (size_t)(b0 + b) * COMB + NND * HID + c4 * 4) = cvt_hi4(v);
    }
}

// ---------------------------------------------------------------------------
// final heads tail. out = [pred(B) | weights(B*5) | attn2(B*49)]
// ---------------------------------------------------------------------------
__global__ void __launch_bounds__(256)
final_kernel(const float* __restrict__ ht, const float* __restrict__ base_preds,
             const float* __restrict__ wh1_b,
             const float* __restrict__ wh2_w, const float* __restrict__ wh2_b,
             const float* __restrict__ wh3_w, const float* __restrict__ wh3_b,
             const float* __restrict__ rh1_b,
             const float* __restrict__ rh2_w, const float* __restrict__ rh2_b,
             float* __restrict__ out) {
    const int b = blockIdx.x * 256 + threadIdx.x;
    if (b >= BATCH) return;
    const float* h = ht + (size_t)b * 64;

    float t1[32];
#pragma unroll
    for (int k = 0; k < 32; ++k) t1[k] = fmaxf(h[k] + wh1_b[k], 0.f);
    float t2[16];
#pragma unroll
    for (int o = 0; o < 16; ++o) {
        float s = wh2_b[o];
#pragma unroll
        for (int k = 0; k < 32; ++k) s = fmaf(t1[k], wh2_w[o * 32 + k], s);
        t2[o] = fmaxf(s, 0.f);
    }
    float raw[5]; float mx = -3.0e38f;
#pragma unroll
    for (int o = 0; o < 5; ++o) {
        float s = wh3_b[o];
#pragma unroll
        for (int k = 0; k < 16; ++k) s = fmaf(t2[k], wh3_w[o * 16 + k], s);
        raw[o] = s; mx = fmaxf(mx, s);
    }
    float se = 0.f;
#pragma unroll
    for (int o = 0; o < 5; ++o) { raw[o] = __expf(raw[o] - mx); se += raw[o]; }
    const float inv = 1.f / se;
    float wp = 0.f;
#pragma unroll
    for (int o = 0; o < 5; ++o) {
        const float wt = raw[o] * inv;
        out[BATCH + (size_t)b * 5 + o] = wt;
        wp = fmaf(wt, base_preds[(size_t)b * 5 + o], wp);
    }
    float rr = rh2_b[0];
#pragma unroll
    for (int k = 0; k < 16; ++k)
        rr = fmaf(tanhf(h[32 + k] + rh1_b[k]), rh2_w[k], rr);
    out[b] = fmaxf(wp + rr * 0.05f, 0.05f);
}

// ---------------------------------------------------------------------------
extern "C" void kernel_launch(void* const* d_in, const int* in_sizes, int n_in,
                              void* d_out, int out_size) {
    const float* node_feats = (const float*)d_in[0];
    const float* adj        = (const float*)d_in[1];
    const float* context    = (const float*)d_in[2];
    const float* base_preds = (const float*)d_in[3];
    const float* W1    = (const float*)d_in[4];
    const float* a1    = (const float*)d_in[5];
    const float* W2    = (const float*)d_in[6];
    const float* a2    = (const float*)d_in[7];
    const float* wh1_w = (const float*)d_in[8];
    const float* wh1_b = (const float*)d_in[9];
    const float* wh2_w = (const float*)d_in[10];
    const float* wh2_b = (const float*)d_in[11];
    const float* wh3_w = (const float*)d_in[12];
    const float* wh3_b = (const float*)d_in[13];
    const float* rh1_w = (const float*)d_in[14];
    const float* rh1_b = (const float*)d_in[15];
    const float* rh2_w = (const float*)d_in[16];
    const float* rh2_b = (const float*)d_in[17];
    float* out = (float*)d_out;

    float *h1p, *h2p, *htp;
    __half *a1h, *x2h, *w1h, *w2h, *hwp, *cbh;
    cudaGetSymbolAddress((void**)&h1p, g_h1);
    cudaGetSymbolAddress((void**)&h2p, g_h2);
    cudaGetSymbolAddress((void**)&htp, g_ht);
    cudaGetSymbolAddress((void**)&a1h, g_a1h);
    cudaGetSymbolAddress((void**)&x2h, g_x2h);
    cudaGetSymbolAddress((void**)&w1h, g_w1h);
    cudaGetSymbolAddress((void**)&w2h, g_w2h);
    cudaGetSymbolAddress((void**)&hwp, g_hw);
    cudaGetSymbolAddress((void**)&cbh, g_combh);

    const int smemA = 7981 * 4;
    cudaFuncSetAttribute(gemm_f16, cudaFuncAttributeMaxDynamicSharedMemorySize, GX_SMEM);
    cudaFuncSetAttribute(gemm_heads, cudaFuncAttributeMaxDynamicSharedMemorySize, GH_SMEM);
    cudaFuncSetAttribute(attn1_kernel, cudaFuncAttributeMaxDynamicSharedMemorySize, smemA);
    cudaFuncSetAttribute(attn2_kernel, cudaFuncAttributeMaxDynamicSharedMemorySize, smemA);

    convw_kernel<<<(HID * FEATD + 255) / 256, 256>>>(W1, w1h, HID * FEATD);
    convw_kernel<<<(HID * HID + 255) / 256, 256>>>(W2, w2h, HID * HID);
    convhw_kernel<<<(64 * COMB + 255) / 256, 256>>>(wh1_w, rh1_w, hwp);
    conv4_kernel<<<(MROWS * FEATD / 4 + 255) / 256, 256>>>(node_feats, a1h,
                                                           MROWS * FEATD / 4);

    // h1 = a1h @ W1^T   (pure fp16)
    gemm_f16<<<dim3(2, MROWS / 128), 256, GX_SMEM>>>(a1h, w1h, h1p, FEATD);
    // x2 (fp16) = relu(alpha1 @ h1)
    attn1_kernel<<<BATCH / GBA, 256, smemA>>>(h1p, adj, a1, x2h);
    // h2 = x2 @ W2^T
    gemm_f16<<<dim3(2, MROWS / 128), 256, GX_SMEM>>>(x2h, w2h, h2p, HID);
    // attn2: softmax out + combined (fp16)
    attn2_kernel<<<BATCH / GBA, 256, smemA>>>(h2p, adj, a2, context, cbh, out);
    // ht = combined @ HW^T  (N=64 heads GEMM)
    gemm_heads<<<BATCH / 128, 256, GH_SMEM>>>(cbh, hwp, htp);
    // tiny tail
    final_kernel<<<BATCH / 256, 256>>>(htp, base_preds, wh1_b, wh2_w, wh2_b,
                                       wh3_w, wh3_b, rh1_b, rh2_w, rh2_b, out);
}